// round 1
// baseline (speedup 1.0000x reference)
#include <cuda_runtime.h>
#include <math.h>

#define NN 100000
#define EE 500000
#define DD 128
#define LL 8
#define GG 64
#define AA 100

// ---------------- scratch (static device allocations; no cudaMalloc) -------
__device__ float g_feat0[(size_t)NN * DD];
__device__ float g_feat1[(size_t)NN * DD];
__device__ float g_e0[(size_t)EE * DD];
__device__ float g_e1[(size_t)EE * DD];
__device__ float g_qkv[(size_t)NN * 3 * DD];
__device__ float g_ekv[(size_t)EE * 2 * DD];
__device__ float g_sc[(size_t)EE * 4];
__device__ float g_m[NN * 4];
__device__ float g_den[NN * 4];
__device__ float g_agg[(size_t)NN * DD];
__device__ float g_ga[GG * 256];
__device__ float g_cn[GG];
__device__ float g_ce[GG];

// ---------------- small helpers -------------------------------------------
__device__ __forceinline__ void atomicMaxF(float* addr, float v) {
    if (v >= 0.f) atomicMax((int*)addr, __float_as_int(v));
    else          atomicMin((unsigned int*)addr, __float_as_uint(v));
}

__global__ void k_fill(float* p, int n, float v) {
    int i = blockIdx.x * blockDim.x + threadIdx.x;
    if (i < n) p[i] = v;
}

// feat[n][:] = emb_table[x[n]][:]
__global__ void k_node_embed(const int* __restrict__ x,
                             const float* __restrict__ emb,
                             float* __restrict__ feat) {
    unsigned t = blockIdx.x * blockDim.x + threadIdx.x;
    if (t >= (unsigned)NN * 32u) return;
    int n = t >> 5, q = t & 31;
    float4 v = *reinterpret_cast<const float4*>(emb + (size_t)x[n] * 128 + q * 4);
    *reinterpret_cast<float4*>(feat + (size_t)n * 128 + q * 4) = v;
}

// e[e][:] = flow_emb[flow] + pos_emb[pos] + blk_emb[crossing]
__global__ void k_edge_embed(const int* __restrict__ flow, const int* __restrict__ pos,
                             const int* __restrict__ blk,
                             const int* __restrict__ src, const int* __restrict__ dst,
                             const float* __restrict__ femb, const float* __restrict__ pemb,
                             const float* __restrict__ bemb, float* __restrict__ e) {
    unsigned t = blockIdx.x * blockDim.x + threadIdx.x;
    if (t >= (unsigned)EE * 32u) return;
    int ed = t >> 5, q = t & 31;
    int cr = (blk[src[ed]] != blk[dst[ed]]) ? 1 : 0;
    float4 a = *reinterpret_cast<const float4*>(femb + (size_t)flow[ed] * 128 + q * 4);
    float4 b = *reinterpret_cast<const float4*>(pemb + (size_t)pos[ed] * 128 + q * 4);
    float4 c = *reinterpret_cast<const float4*>(bemb + (size_t)cr * 128 + q * 4);
    float4 r;
    r.x = a.x + b.x + c.x; r.y = a.y + b.y + c.y;
    r.z = a.z + b.z + c.z; r.w = a.w + b.w + c.w;
    *reinterpret_cast<float4*>(e + (size_t)ed * 128 + q * 4) = r;
}

// ---------------- fp32 tiled SGEMM: C[M,128] = A[M,128] @ B[128,128] -------
// optional residual (stride 128) + relu epilogue, strided C (ldc)
__global__ __launch_bounds__(256, 2) void sgemm128(
    const float* __restrict__ A, const float* __restrict__ B,
    float* __restrict__ C, const float* __restrict__ R,
    int M, int ldc, int relu)
{
    __shared__ float As[16][128];
    __shared__ float Bs[16][128];
    const int tid = threadIdx.x;
    const int m0 = blockIdx.x * 128;
    const int tx = tid & 15, ty = tid >> 4;
    const int ar = tid >> 2, ac = (tid & 3) << 2;
    const int br = tid >> 5, bc = (tid & 31) << 2;
    float acc[8][8];
#pragma unroll
    for (int i = 0; i < 8; i++)
#pragma unroll
        for (int j = 0; j < 8; j++) acc[i][j] = 0.f;

    for (int kt = 0; kt < 128; kt += 16) {
#pragma unroll
        for (int p = 0; p < 2; p++) {
            int lr = ar + p * 64;
            int row = m0 + lr;
            float4 v = make_float4(0.f, 0.f, 0.f, 0.f);
            if (row < M)
                v = *reinterpret_cast<const float4*>(A + (size_t)row * 128 + kt + ac);
            As[ac + 0][lr] = v.x; As[ac + 1][lr] = v.y;
            As[ac + 2][lr] = v.z; As[ac + 3][lr] = v.w;
        }
#pragma unroll
        for (int p = 0; p < 2; p++) {
            int kr = br + p * 8;
            *reinterpret_cast<float4*>(&Bs[kr][bc]) =
                *reinterpret_cast<const float4*>(B + (size_t)(kt + kr) * 128 + bc);
        }
        __syncthreads();
#pragma unroll
        for (int k = 0; k < 16; k++) {
            float a[8], b[8];
            *reinterpret_cast<float4*>(&a[0]) = *reinterpret_cast<float4*>(&As[k][ty * 8]);
            *reinterpret_cast<float4*>(&a[4]) = *reinterpret_cast<float4*>(&As[k][ty * 8 + 4]);
            *reinterpret_cast<float4*>(&b[0]) = *reinterpret_cast<float4*>(&Bs[k][tx * 8]);
            *reinterpret_cast<float4*>(&b[4]) = *reinterpret_cast<float4*>(&Bs[k][tx * 8 + 4]);
#pragma unroll
            for (int i = 0; i < 8; i++)
#pragma unroll
                for (int j = 0; j < 8; j++) acc[i][j] = fmaf(a[i], b[j], acc[i][j]);
        }
        __syncthreads();
    }
#pragma unroll
    for (int i = 0; i < 8; i++) {
        int row = m0 + ty * 8 + i;
        if (row >= M) continue;
#pragma unroll
        for (int j = 0; j < 8; j += 4) {
            int col = tx * 8 + j;
            float4 r = make_float4(acc[i][j], acc[i][j + 1], acc[i][j + 2], acc[i][j + 3]);
            if (R) {
                float4 rv = *reinterpret_cast<const float4*>(R + (size_t)row * 128 + col);
                r.x += rv.x; r.y += rv.y; r.z += rv.z; r.w += rv.w;
            }
            if (relu) {
                r.x = fmaxf(r.x, 0.f); r.y = fmaxf(r.y, 0.f);
                r.z = fmaxf(r.z, 0.f); r.w = fmaxf(r.w, 0.f);
            }
            *reinterpret_cast<float4*>(C + (size_t)row * ldc + col) = r;
        }
    }
}

// ---------------- edge update GEMM: enew = relu(eold + cat @ Weu) ----------
// cat[r] = [feat[src[r]], feat[dst[r]], eold[r]]  (K = 384), gather fused
__global__ __launch_bounds__(256, 2) void sgemm_edge(
    const float* __restrict__ feat, const float* __restrict__ eold,
    const float* __restrict__ B, float* __restrict__ enew,
    const int* __restrict__ src, const int* __restrict__ dst, int M)
{
    __shared__ float As[16][128];
    __shared__ float Bs[16][128];
    __shared__ int ssrc[128], sdst[128];
    const int tid = threadIdx.x;
    const int m0 = blockIdx.x * 128;
    if (tid < 128) {
        int row = m0 + tid;
        ssrc[tid] = (row < M) ? src[row] : 0;
        sdst[tid] = (row < M) ? dst[row] : 0;
    }
    __syncthreads();
    const int tx = tid & 15, ty = tid >> 4;
    const int ar = tid >> 2, ac = (tid & 3) << 2;
    const int br = tid >> 5, bc = (tid & 31) << 2;
    float acc[8][8];
#pragma unroll
    for (int i = 0; i < 8; i++)
#pragma unroll
        for (int j = 0; j < 8; j++) acc[i][j] = 0.f;

    for (int kt = 0; kt < 384; kt += 16) {
#pragma unroll
        for (int p = 0; p < 2; p++) {
            int lr = ar + p * 64;
            int row = m0 + lr;
            int kc = kt + ac;
            float4 v = make_float4(0.f, 0.f, 0.f, 0.f);
            if (row < M) {
                const float* P; int off;
                if (kc < 128)      { P = feat + (size_t)ssrc[lr] * 128; off = kc; }
                else if (kc < 256) { P = feat + (size_t)sdst[lr] * 128; off = kc - 128; }
                else               { P = eold + (size_t)row * 128;      off = kc - 256; }
                v = *reinterpret_cast<const float4*>(P + off);
            }
            As[ac + 0][lr] = v.x; As[ac + 1][lr] = v.y;
            As[ac + 2][lr] = v.z; As[ac + 3][lr] = v.w;
        }
#pragma unroll
        for (int p = 0; p < 2; p++) {
            int kr = br + p * 8;
            *reinterpret_cast<float4*>(&Bs[kr][bc]) =
                *reinterpret_cast<const float4*>(B + (size_t)(kt + kr) * 128 + bc);
        }
        __syncthreads();
#pragma unroll
        for (int k = 0; k < 16; k++) {
            float a[8], b[8];
            *reinterpret_cast<float4*>(&a[0]) = *reinterpret_cast<float4*>(&As[k][ty * 8]);
            *reinterpret_cast<float4*>(&a[4]) = *reinterpret_cast<float4*>(&As[k][ty * 8 + 4]);
            *reinterpret_cast<float4*>(&b[0]) = *reinterpret_cast<float4*>(&Bs[k][tx * 8]);
            *reinterpret_cast<float4*>(&b[4]) = *reinterpret_cast<float4*>(&Bs[k][tx * 8 + 4]);
#pragma unroll
            for (int i = 0; i < 8; i++)
#pragma unroll
                for (int j = 0; j < 8; j++) acc[i][j] = fmaf(a[i], b[j], acc[i][j]);
        }
        __syncthreads();
    }
#pragma unroll
    for (int i = 0; i < 8; i++) {
        int row = m0 + ty * 8 + i;
        if (row >= M) continue;
#pragma unroll
        for (int j = 0; j < 8; j += 4) {
            int col = tx * 8 + j;
            float4 r = make_float4(acc[i][j], acc[i][j + 1], acc[i][j + 2], acc[i][j + 3]);
            float4 rv = *reinterpret_cast<const float4*>(eold + (size_t)row * 128 + col);
            r.x = fmaxf(r.x + rv.x, 0.f); r.y = fmaxf(r.y + rv.y, 0.f);
            r.z = fmaxf(r.z + rv.z, 0.f); r.w = fmaxf(r.w + rv.w, 0.f);
            *reinterpret_cast<float4*>(enew + (size_t)row * 128 + col) = r;
        }
    }
}

// ---------------- attention edge kernels -----------------------------------
// scores[e,h] = scale * dot(q[dst], k[src] + ek[e]) ; segment max into m
__global__ void k_scores(const float* __restrict__ qkv, const float* __restrict__ ekv,
                         const int* __restrict__ src, const int* __restrict__ dst,
                         float* __restrict__ sc, float* __restrict__ m)
{
    unsigned t = blockIdx.x * blockDim.x + threadIdx.x;
    int w = t >> 5;
    int lane = threadIdx.x & 31;
    if (w >= EE) return;
    int s = src[w], d = dst[w];
    float4 q4 = *reinterpret_cast<const float4*>(qkv + (size_t)d * 384 + lane * 4);
    float4 k4 = *reinterpret_cast<const float4*>(qkv + (size_t)s * 384 + 128 + lane * 4);
    float4 e4 = *reinterpret_cast<const float4*>(ekv + (size_t)w * 256 + lane * 4);
    float p = q4.x * (k4.x + e4.x) + q4.y * (k4.y + e4.y) +
              q4.z * (k4.z + e4.z) + q4.w * (k4.w + e4.w);
    p += __shfl_xor_sync(0xffffffffu, p, 4);
    p += __shfl_xor_sync(0xffffffffu, p, 2);
    p += __shfl_xor_sync(0xffffffffu, p, 1);
    if ((lane & 7) == 0) {
        int h = lane >> 3;
        float v = p * 0.17677669529663687f;  // 1/sqrt(32)
        sc[(size_t)w * 4 + h] = v;
        atomicMaxF(&m[d * 4 + h], v);
    }
}

// ex = exp(score - m[dst]) ; den[dst] += ex  (sc overwritten with ex)
__global__ void k_expden(const int* __restrict__ dst, float* __restrict__ sc,
                         const float* __restrict__ m, float* __restrict__ den)
{
    unsigned i = blockIdx.x * blockDim.x + threadIdx.x;
    if (i >= (unsigned)EE * 4u) return;
    int e = i >> 2, h = i & 3;
    int d = dst[e];
    float ex = __expf(sc[i] - m[d * 4 + h]);
    sc[i] = ex;
    atomicAdd(&den[d * 4 + h], ex);
}

// agg[dst] += alpha * (v[src] + ev[e])
__global__ void k_agg(const float* __restrict__ qkv, const float* __restrict__ ekv,
                      const int* __restrict__ src, const int* __restrict__ dst,
                      const float* __restrict__ sc, const float* __restrict__ den,
                      float* __restrict__ agg)
{
    unsigned t = blockIdx.x * blockDim.x + threadIdx.x;
    int w = t >> 5;
    int lane = threadIdx.x & 31;
    if (w >= EE) return;
    int s = src[w], d = dst[w];
    int h = lane >> 3;
    float alpha = sc[(size_t)w * 4 + h] / (den[d * 4 + h] + 1e-16f);
    float4 v4 = *reinterpret_cast<const float4*>(qkv + (size_t)s * 384 + 256 + lane * 4);
    float4 e4 = *reinterpret_cast<const float4*>(ekv + (size_t)w * 256 + 128 + lane * 4);
    float* p = agg + (size_t)d * 128 + lane * 4;
    atomicAdd(p + 0, alpha * (v4.x + e4.x));
    atomicAdd(p + 1, alpha * (v4.y + e4.y));
    atomicAdd(p + 2, alpha * (v4.z + e4.z));
    atomicAdd(p + 3, alpha * (v4.w + e4.w));
}

// ---------------- graph pooling --------------------------------------------
__global__ void k_gnode(const float* __restrict__ feat, const int* __restrict__ ntype,
                        const int* __restrict__ batch, float* __restrict__ ga,
                        float* __restrict__ cn)
{
    unsigned t = blockIdx.x * blockDim.x + threadIdx.x;
    if (t >= (unsigned)NN * 32u) return;
    int n = t >> 5, q = t & 31;
    if (ntype[n] != 0) return;
    int b = batch[n];
    float4 f = *reinterpret_cast<const float4*>(feat + (size_t)n * 128 + q * 4);
    float* p = ga + (size_t)b * 256 + q * 4;
    atomicAdd(p + 0, f.x); atomicAdd(p + 1, f.y);
    atomicAdd(p + 2, f.z); atomicAdd(p + 3, f.w);
    if (q == 0) atomicAdd(&cn[b], 1.f);
}

__global__ void k_gedge(const float* __restrict__ e, const int* __restrict__ src,
                        const int* __restrict__ batch, float* __restrict__ ga,
                        float* __restrict__ ce)
{
    unsigned t = blockIdx.x * blockDim.x + threadIdx.x;
    if (t >= (unsigned)EE * 32u) return;
    int ed = t >> 5, q = t & 31;
    int b = batch[src[ed]];
    float4 f = *reinterpret_cast<const float4*>(e + (size_t)ed * 128 + q * 4);
    float* p = ga + (size_t)b * 256 + 128 + q * 4;
    atomicAdd(p + 0, f.x); atomicAdd(p + 1, f.y);
    atomicAdd(p + 2, f.z); atomicAdd(p + 3, f.w);
    if (q == 0) atomicAdd(&ce[b], 1.f);
}

// ---------------- Q head: mean -> relu(ga@QW1+b1) -> @QW2+b2 -> log_softmax
__global__ void k_head(const float* __restrict__ ga, const float* __restrict__ cn,
                       const float* __restrict__ ce,
                       const float* __restrict__ QW1, const float* __restrict__ Qb1,
                       const float* __restrict__ QW2, const float* __restrict__ Qb2,
                       float* __restrict__ out)
{
    int g = blockIdx.x;
    int t = threadIdx.x;  // 128
    __shared__ float s_in[256];
    __shared__ float s_h[128];
    __shared__ float s_l[128];
    __shared__ float s_max, s_lse;
    float nc = fmaxf(cn[g], 1.0f);
    float ec = fmaxf(ce[g], 1.0f);
    s_in[t]       = ga[(size_t)g * 256 + t] / nc;
    s_in[t + 128] = ga[(size_t)g * 256 + 128 + t] / ec;
    __syncthreads();
    float acc = Qb1[t];
    for (int k = 0; k < 256; k++) acc = fmaf(s_in[k], QW1[(size_t)k * 128 + t], acc);
    s_h[t] = fmaxf(acc, 0.f);
    __syncthreads();
    float lg = 0.f;
    if (t < AA) {
        lg = Qb2[t];
        for (int k = 0; k < 128; k++) lg = fmaf(s_h[k], QW2[(size_t)k * AA + t], lg);
        s_l[t] = lg;
    }
    __syncthreads();
    if (t == 0) {
        float mx = -3.4e38f;
        for (int i = 0; i < AA; i++) mx = fmaxf(mx, s_l[i]);
        float s = 0.f;
        for (int i = 0; i < AA; i++) s += expf(s_l[i] - mx);
        s_max = mx;
        s_lse = logf(s);
    }
    __syncthreads();
    if (t < AA) out[(size_t)g * AA + t] = lg - s_max - s_lse;
}

// ---------------- launch ----------------------------------------------------
extern "C" void kernel_launch(void* const* d_in, const int* in_sizes, int n_in,
                              void* d_out, int out_size)
{
    const int* x     = (const int*)d_in[0];
    const int* ntype = (const int*)d_in[1];
    const int* batch = (const int*)d_in[2];
    const int* ei    = (const int*)d_in[3];
    const int* flow  = (const int*)d_in[4];
    const int* pos   = (const int*)d_in[5];
    const int* blk   = (const int*)d_in[6];
    // num_graphs may or may not occupy a slot; detect via emb_table size (8192*128)
    int base = (in_sizes[7] == 8192 * 128) ? 7 : 8;
    const float* emb  = (const float*)d_in[base + 0];
    const float* femb = (const float*)d_in[base + 1];
    const float* pemb = (const float*)d_in[base + 2];
    const float* bemb = (const float*)d_in[base + 3];
    const float* Wq   = (const float*)d_in[base + 4];
    const float* Wk   = (const float*)d_in[base + 5];
    const float* Wv   = (const float*)d_in[base + 6];
    const float* Wek  = (const float*)d_in[base + 7];
    const float* Wev  = (const float*)d_in[base + 8];
    const float* Wo   = (const float*)d_in[base + 9];
    const float* Weu  = (const float*)d_in[base + 10];
    const float* QW1  = (const float*)d_in[base + 11];
    const float* Qb1  = (const float*)d_in[base + 12];
    const float* QW2  = (const float*)d_in[base + 13];
    const float* Qb2  = (const float*)d_in[base + 14];
    const int* src = ei;
    const int* dst = ei + EE;
    float* out = (float*)d_out;

    float *feat0, *feat1, *e0, *e1, *qkv, *ekv, *sc, *m, *den, *agg, *ga, *cn, *ce;
    cudaGetSymbolAddress((void**)&feat0, g_feat0);
    cudaGetSymbolAddress((void**)&feat1, g_feat1);
    cudaGetSymbolAddress((void**)&e0, g_e0);
    cudaGetSymbolAddress((void**)&e1, g_e1);
    cudaGetSymbolAddress((void**)&qkv, g_qkv);
    cudaGetSymbolAddress((void**)&ekv, g_ekv);
    cudaGetSymbolAddress((void**)&sc, g_sc);
    cudaGetSymbolAddress((void**)&m, g_m);
    cudaGetSymbolAddress((void**)&den, g_den);
    cudaGetSymbolAddress((void**)&agg, g_agg);
    cudaGetSymbolAddress((void**)&ga, g_ga);
    cudaGetSymbolAddress((void**)&cn, g_cn);
    cudaGetSymbolAddress((void**)&ce, g_ce);

    const int TPB = 256;
    const int gN32 = (NN * 32 + TPB - 1) / TPB;
    const int gE32 = (EE * 32 + TPB - 1) / TPB;
    const int GN = (NN + 127) / 128;
    const int GE = (EE + 127) / 128;

    k_node_embed<<<gN32, TPB>>>(x, emb, feat0);
    k_edge_embed<<<gE32, TPB>>>(flow, pos, blk, src, dst, femb, pemb, bemb, e0);

    float* fc = feat0; float* fn = feat1;
    float* ec = e0;    float* en = e1;

    for (int l = 0; l < LL; l++) {
        const float* wq  = Wq  + (size_t)l * 128 * 128;
        const float* wk  = Wk  + (size_t)l * 128 * 128;
        const float* wv  = Wv  + (size_t)l * 128 * 128;
        const float* wek = Wek + (size_t)l * 128 * 128;
        const float* wev = Wev + (size_t)l * 128 * 128;
        const float* wo  = Wo  + (size_t)l * 128 * 128;
        const float* weu = Weu + (size_t)l * 384 * 128;

        sgemm128<<<GN, TPB>>>(fc, wq, qkv + 0,   nullptr, NN, 384, 0);
        sgemm128<<<GN, TPB>>>(fc, wk, qkv + 128, nullptr, NN, 384, 0);
        sgemm128<<<GN, TPB>>>(fc, wv, qkv + 256, nullptr, NN, 384, 0);
        sgemm128<<<GE, TPB>>>(ec, wek, ekv + 0,   nullptr, EE, 256, 0);
        sgemm128<<<GE, TPB>>>(ec, wev, ekv + 128, nullptr, EE, 256, 0);

        k_fill<<<(NN * 4 + TPB - 1) / TPB, TPB>>>(m, NN * 4, -3.4e38f);
        cudaMemsetAsync(den, 0, (size_t)NN * 4 * sizeof(float));
        cudaMemsetAsync(agg, 0, (size_t)NN * 128 * sizeof(float));

        k_scores<<<gE32, TPB>>>(qkv, ekv, src, dst, sc, m);
        k_expden<<<(EE * 4 + TPB - 1) / TPB, TPB>>>(dst, sc, m, den);
        k_agg<<<gE32, TPB>>>(qkv, ekv, src, dst, sc, den, agg);

        sgemm128<<<GN, TPB>>>(agg, wo, fn, fc, NN, 128, 1);
        sgemm_edge<<<GE, TPB>>>(fc, ec, weu, en, src, dst, EE);

        float* tf = fc; fc = fn; fn = tf;
        float* te = ec; ec = en; en = te;
    }

    cudaMemsetAsync(ga, 0, (size_t)GG * 256 * sizeof(float));
    cudaMemsetAsync(cn, 0, GG * sizeof(float));
    cudaMemsetAsync(ce, 0, GG * sizeof(float));
    k_gnode<<<gN32, TPB>>>(fc, ntype, batch, ga, cn);
    k_gedge<<<gE32, TPB>>>(ec, src, batch, ga, ce);
    k_head<<<GG, 128>>>(ga, cn, ce, QW1, Qb1, QW2, Qb2, out);
}

// round 2
// speedup vs baseline: 1.0658x; 1.0658x over previous
#include <cuda_runtime.h>
#include <math.h>

#define NN 100000
#define EE 500000
#define DD 128
#define LL 8
#define GG 64
#define AA 100

// ---------------- scratch (static device arrays; no cudaMalloc) -------------
__device__ float g_feat0[(size_t)NN * DD];
__device__ float g_feat1[(size_t)NN * DD];
__device__ float g_e0[(size_t)EE * DD];
__device__ float g_e1[(size_t)EE * DD];
__device__ float g_qkv[(size_t)NN * 3 * DD];
__device__ float g_ekv[(size_t)EE * 2 * DD];
__device__ float g_sc[(size_t)EE * 4];
__device__ float g_m[NN * 4];
__device__ float g_den[NN * 4];
__device__ float g_agg[(size_t)NN * DD];
__device__ float g_P[(size_t)NN * DD];
__device__ float g_Q[(size_t)NN * DD];
__device__ float g_ga[GG * 256];
__device__ float g_cn[GG];
__device__ float g_ce[GG];
__device__ int   g_code[EE];
__device__ float g_elut[1024 * DD];
__device__ float g_ekvlut[1024 * 2 * DD];

// ---------------- helpers ---------------------------------------------------
__device__ __forceinline__ void atomicMaxF(float* addr, float v) {
    if (v >= 0.f) atomicMax((int*)addr, __float_as_int(v));
    else          atomicMin((unsigned int*)addr, __float_as_uint(v));
}

__device__ __forceinline__ void cp_async16(void* smem, const void* gmem) {
    unsigned s = (unsigned)__cvta_generic_to_shared(smem);
    asm volatile("cp.async.cg.shared.global [%0], [%1], 16;\n" :: "r"(s), "l"(gmem));
}
__device__ __forceinline__ void cp_commit() {
    asm volatile("cp.async.commit_group;\n");
}
__device__ __forceinline__ void cp_wait_all() {
    asm volatile("cp.async.wait_group 0;\n");
}

__global__ void k_fill(float* p, int n, float v) {
    int i = blockIdx.x * blockDim.x + threadIdx.x;
    if (i < n) p[i] = v;
}

// feat[n][:] = emb_table[x[n]][:]
__global__ void k_node_embed(const int* __restrict__ x,
                             const float* __restrict__ emb,
                             float* __restrict__ feat) {
    unsigned t = blockIdx.x * blockDim.x + threadIdx.x;
    if (t >= (unsigned)NN * 32u) return;
    int n = t >> 5, q = t & 31;
    float4 v = *reinterpret_cast<const float4*>(emb + (size_t)x[n] * 128 + q * 4);
    *reinterpret_cast<float4*>(feat + (size_t)n * 128 + q * 4) = v;
}

// elut[c][:] = flow_emb[c>>7] + pos_emb[(c>>1)&63] + blk_emb[c&1]
__global__ void k_lut_e(const float* __restrict__ femb, const float* __restrict__ pemb,
                        const float* __restrict__ bemb, float* __restrict__ elut) {
    int c = blockIdx.x, t = threadIdx.x;  // 1024 blocks, 128 threads
    elut[c * 128 + t] = femb[(c >> 7) * 128 + t] + pemb[((c >> 1) & 63) * 128 + t] +
                        bemb[(c & 1) * 128 + t];
}

__global__ void k_code(const int* __restrict__ flow, const int* __restrict__ pos,
                       const int* __restrict__ blk,
                       const int* __restrict__ src, const int* __restrict__ dst,
                       int* __restrict__ code) {
    int e = blockIdx.x * blockDim.x + threadIdx.x;
    if (e >= EE) return;
    int cr = (blk[src[e]] != blk[dst[e]]) ? 1 : 0;
    code[e] = (flow[e] << 7) | (pos[e] << 1) | cr;
}

__global__ void k_expand_e(const int* __restrict__ code, const float* __restrict__ elut,
                           float* __restrict__ e) {
    unsigned t = blockIdx.x * blockDim.x + threadIdx.x;
    if (t >= (unsigned)EE * 32u) return;
    int ed = t >> 5, q = t & 31;
    float4 v = *reinterpret_cast<const float4*>(elut + (size_t)code[ed] * 128 + q * 4);
    *reinterpret_cast<float4*>(e + (size_t)ed * 128 + q * 4) = v;
}

__global__ void k_expand_ekv(const int* __restrict__ code, const float* __restrict__ lut,
                             float* __restrict__ ekv) {
    unsigned t = blockIdx.x * blockDim.x + threadIdx.x;
    if (t >= (unsigned)EE * 64u) return;
    int ed = t >> 6, q = t & 63;
    float4 v = *reinterpret_cast<const float4*>(lut + (size_t)code[ed] * 256 + q * 4);
    *reinterpret_cast<float4*>(ekv + (size_t)ed * 256 + q * 4) = v;
}

// ---------------- pipelined fp32 GEMM: C[M,128] = A[M,128] @ B[128,128] -----
// MODE 0: plain (strided C via ldc+colofs)
// MODE 1: C = relu(R + A@B)
// MODE 2: C = relu(R + A@B + P[src] + Q[dst])   (edge update, decomposed)
template<int MODE>
__global__ __launch_bounds__(256, 2) void gemm_t(
    const float* __restrict__ A, const float* __restrict__ B,
    float* __restrict__ C, const float* __restrict__ R,
    const float* __restrict__ P, const float* __restrict__ Q,
    const int* __restrict__ src, const int* __restrict__ dst,
    int M, int ldc, int colofs)
{
    __shared__ float As[2][16][128];
    __shared__ float Bs[2][16][128];
    const int tid = threadIdx.x;
    const int m0 = blockIdx.x * 128;
    const int tx = tid & 15, ty = tid >> 4;
    const int ar = tid >> 2, ac = (tid & 3) << 2;   // A: row ar(+64), k within tile
    const int br = tid >> 5, bc = (tid & 31) << 2;  // B: k-row br(+8), col bc

    // clamped row indices (OOB rows read garbage but are never written)
    int row0 = m0 + ar;       if (row0 >= M) row0 = M - 1;
    int row1 = m0 + ar + 64;  if (row1 >= M) row1 = M - 1;
    const float* a0p = A + (size_t)row0 * 128 + ac;
    const float* a1p = A + (size_t)row1 * 128 + ac;

    float acc[8][8];
#pragma unroll
    for (int i = 0; i < 8; i++)
#pragma unroll
        for (int j = 0; j < 8; j++) acc[i][j] = 0.f;

    // prologue: tile 0
    float4 ra0 = *reinterpret_cast<const float4*>(a0p);
    float4 ra1 = *reinterpret_cast<const float4*>(a1p);
    {
        As[0][ac + 0][ar] = ra0.x; As[0][ac + 1][ar] = ra0.y;
        As[0][ac + 2][ar] = ra0.z; As[0][ac + 3][ar] = ra0.w;
        As[0][ac + 0][ar + 64] = ra1.x; As[0][ac + 1][ar + 64] = ra1.y;
        As[0][ac + 2][ar + 64] = ra1.z; As[0][ac + 3][ar + 64] = ra1.w;
#pragma unroll
        for (int p = 0; p < 2; p++)
            cp_async16(&Bs[0][br + p * 8][bc], B + (size_t)(br + p * 8) * 128 + bc);
        cp_commit();
    }
    cp_wait_all();
    __syncthreads();

#pragma unroll
    for (int kt = 0; kt < 8; kt++) {
        const int cur = kt & 1, nxt = cur ^ 1;
        if (kt < 7) {
            ra0 = *reinterpret_cast<const float4*>(a0p + (kt + 1) * 16);
            ra1 = *reinterpret_cast<const float4*>(a1p + (kt + 1) * 16);
#pragma unroll
            for (int p = 0; p < 2; p++)
                cp_async16(&Bs[nxt][br + p * 8][bc],
                           B + (size_t)((kt + 1) * 16 + br + p * 8) * 128 + bc);
            cp_commit();
        }
#pragma unroll
        for (int k = 0; k < 16; k++) {
            float a[8], b[8];
            *reinterpret_cast<float4*>(&a[0]) = *reinterpret_cast<const float4*>(&As[cur][k][ty * 8]);
            *reinterpret_cast<float4*>(&a[4]) = *reinterpret_cast<const float4*>(&As[cur][k][ty * 8 + 4]);
            *reinterpret_cast<float4*>(&b[0]) = *reinterpret_cast<const float4*>(&Bs[cur][k][tx * 8]);
            *reinterpret_cast<float4*>(&b[4]) = *reinterpret_cast<const float4*>(&Bs[cur][k][tx * 8 + 4]);
#pragma unroll
            for (int i = 0; i < 8; i++)
#pragma unroll
                for (int j = 0; j < 8; j++) acc[i][j] = fmaf(a[i], b[j], acc[i][j]);
        }
        if (kt < 7) {
            As[nxt][ac + 0][ar] = ra0.x; As[nxt][ac + 1][ar] = ra0.y;
            As[nxt][ac + 2][ar] = ra0.z; As[nxt][ac + 3][ar] = ra0.w;
            As[nxt][ac + 0][ar + 64] = ra1.x; As[nxt][ac + 1][ar + 64] = ra1.y;
            As[nxt][ac + 2][ar + 64] = ra1.z; As[nxt][ac + 3][ar + 64] = ra1.w;
            cp_wait_all();
            __syncthreads();
        }
    }

#pragma unroll
    for (int i = 0; i < 8; i++) {
        int row = m0 + ty * 8 + i;
        if (row >= M) continue;
        int s = 0, d = 0;
        if (MODE == 2) { s = src[row]; d = dst[row]; }
#pragma unroll
        for (int j = 0; j < 8; j += 4) {
            int col = tx * 8 + j;
            float4 r = make_float4(acc[i][j], acc[i][j + 1], acc[i][j + 2], acc[i][j + 3]);
            if (MODE >= 1) {
                float4 rv = *reinterpret_cast<const float4*>(R + (size_t)row * 128 + col);
                r.x += rv.x; r.y += rv.y; r.z += rv.z; r.w += rv.w;
            }
            if (MODE == 2) {
                float4 pv = *reinterpret_cast<const float4*>(P + (size_t)s * 128 + col);
                float4 qv = *reinterpret_cast<const float4*>(Q + (size_t)d * 128 + col);
                r.x += pv.x + qv.x; r.y += pv.y + qv.y;
                r.z += pv.z + qv.z; r.w += pv.w + qv.w;
            }
            if (MODE >= 1) {
                r.x = fmaxf(r.x, 0.f); r.y = fmaxf(r.y, 0.f);
                r.z = fmaxf(r.z, 0.f); r.w = fmaxf(r.w, 0.f);
            }
            *reinterpret_cast<float4*>(C + (size_t)row * ldc + colofs + col) = r;
        }
    }
}

// ---------------- attention edge kernels ------------------------------------
__global__ void k_scores(const float* __restrict__ qkv, const float* __restrict__ ekv,
                         const int* __restrict__ src, const int* __restrict__ dst,
                         float* __restrict__ sc, float* __restrict__ m)
{
    unsigned t = blockIdx.x * blockDim.x + threadIdx.x;
    int w = t >> 5;
    int lane = threadIdx.x & 31;
    if (w >= EE) return;
    int s = src[w], d = dst[w];
    float4 q4 = *reinterpret_cast<const float4*>(qkv + (size_t)d * 384 + lane * 4);
    float4 k4 = *reinterpret_cast<const float4*>(qkv + (size_t)s * 384 + 128 + lane * 4);
    float4 e4 = *reinterpret_cast<const float4*>(ekv + (size_t)w * 256 + lane * 4);
    float p = q4.x * (k4.x + e4.x) + q4.y * (k4.y + e4.y) +
              q4.z * (k4.z + e4.z) + q4.w * (k4.w + e4.w);
    p += __shfl_xor_sync(0xffffffffu, p, 4);
    p += __shfl_xor_sync(0xffffffffu, p, 2);
    p += __shfl_xor_sync(0xffffffffu, p, 1);
    if ((lane & 7) == 0) {
        int h = lane >> 3;
        float v = p * 0.17677669529663687f;  // 1/sqrt(32)
        sc[(size_t)w * 4 + h] = v;
        atomicMaxF(&m[d * 4 + h], v);
    }
}

__global__ void k_expden(const int* __restrict__ dst, float* __restrict__ sc,
                         const float* __restrict__ m, float* __restrict__ den)
{
    unsigned i = blockIdx.x * blockDim.x + threadIdx.x;
    if (i >= (unsigned)EE * 4u) return;
    int e = i >> 2, h = i & 3;
    int d = dst[e];
    float ex = __expf(sc[i] - m[d * 4 + h]);
    sc[i] = ex;
    atomicAdd(&den[d * 4 + h], ex);
}

__global__ void k_agg(const float* __restrict__ qkv, const float* __restrict__ ekv,
                      const int* __restrict__ src, const int* __restrict__ dst,
                      const float* __restrict__ sc, const float* __restrict__ den,
                      float* __restrict__ agg)
{
    unsigned t = blockIdx.x * blockDim.x + threadIdx.x;
    int w = t >> 5;
    int lane = threadIdx.x & 31;
    if (w >= EE) return;
    int s = src[w], d = dst[w];
    int h = lane >> 3;
    float alpha = sc[(size_t)w * 4 + h] / (den[d * 4 + h] + 1e-16f);
    float4 v4 = *reinterpret_cast<const float4*>(qkv + (size_t)s * 384 + 256 + lane * 4);
    float4 e4 = *reinterpret_cast<const float4*>(ekv + (size_t)w * 256 + 128 + lane * 4);
    float* p = agg + (size_t)d * 128 + lane * 4;
    atomicAdd(p + 0, alpha * (v4.x + e4.x));
    atomicAdd(p + 1, alpha * (v4.y + e4.y));
    atomicAdd(p + 2, alpha * (v4.z + e4.z));
    atomicAdd(p + 3, alpha * (v4.w + e4.w));
}

// ---------------- graph pooling ----------------------------------------------
__global__ void k_gnode(const float* __restrict__ feat, const int* __restrict__ ntype,
                        const int* __restrict__ batch, float* __restrict__ ga,
                        float* __restrict__ cn)
{
    unsigned t = blockIdx.x * blockDim.x + threadIdx.x;
    if (t >= (unsigned)NN * 32u) return;
    int n = t >> 5, q = t & 31;
    if (ntype[n] != 0) return;
    int b = batch[n];
    float4 f = *reinterpret_cast<const float4*>(feat + (size_t)n * 128 + q * 4);
    float* p = ga + (size_t)b * 256 + q * 4;
    atomicAdd(p + 0, f.x); atomicAdd(p + 1, f.y);
    atomicAdd(p + 2, f.z); atomicAdd(p + 3, f.w);
    if (q == 0) atomicAdd(&cn[b], 1.f);
}

__global__ void k_gedge(const float* __restrict__ e, const int* __restrict__ src,
                        const int* __restrict__ batch, float* __restrict__ ga,
                        float* __restrict__ ce)
{
    unsigned t = blockIdx.x * blockDim.x + threadIdx.x;
    if (t >= (unsigned)EE * 32u) return;
    int ed = t >> 5, q = t & 31;
    int b = batch[src[ed]];
    float4 f = *reinterpret_cast<const float4*>(e + (size_t)ed * 128 + q * 4);
    float* p = ga + (size_t)b * 256 + 128 + q * 4;
    atomicAdd(p + 0, f.x); atomicAdd(p + 1, f.y);
    atomicAdd(p + 2, f.z); atomicAdd(p + 3, f.w);
    if (q == 0) atomicAdd(&ce[b], 1.f);
}

// ---------------- Q head ------------------------------------------------------
__global__ void k_head(const float* __restrict__ ga, const float* __restrict__ cn,
                       const float* __restrict__ ce,
                       const float* __restrict__ QW1, const float* __restrict__ Qb1,
                       const float* __restrict__ QW2, const float* __restrict__ Qb2,
                       float* __restrict__ out)
{
    int g = blockIdx.x;
    int t = threadIdx.x;  // 128
    __shared__ float s_in[256];
    __shared__ float s_h[128];
    __shared__ float s_l[128];
    __shared__ float s_max, s_lse;
    float nc = fmaxf(cn[g], 1.0f);
    float ec = fmaxf(ce[g], 1.0f);
    s_in[t]       = ga[(size_t)g * 256 + t] / nc;
    s_in[t + 128] = ga[(size_t)g * 256 + 128 + t] / ec;
    __syncthreads();
    float acc = Qb1[t];
    for (int k = 0; k < 256; k++) acc = fmaf(s_in[k], QW1[(size_t)k * 128 + t], acc);
    s_h[t] = fmaxf(acc, 0.f);
    __syncthreads();
    float lg = 0.f;
    if (t < AA) {
        lg = Qb2[t];
        for (int k = 0; k < 128; k++) lg = fmaf(s_h[k], QW2[(size_t)k * AA + t], lg);
        s_l[t] = lg;
    }
    __syncthreads();
    if (t == 0) {
        float mx = -3.4e38f;
        for (int i = 0; i < AA; i++) mx = fmaxf(mx, s_l[i]);
        float s = 0.f;
        for (int i = 0; i < AA; i++) s += expf(s_l[i] - mx);
        s_max = mx;
        s_lse = logf(s);
    }
    __syncthreads();
    if (t < AA) out[(size_t)g * AA + t] = lg - s_max - s_lse;
}

// ---------------- launch ------------------------------------------------------
extern "C" void kernel_launch(void* const* d_in, const int* in_sizes, int n_in,
                              void* d_out, int out_size)
{
    const int* x     = (const int*)d_in[0];
    const int* ntype = (const int*)d_in[1];
    const int* batch = (const int*)d_in[2];
    const int* ei    = (const int*)d_in[3];
    const int* flow  = (const int*)d_in[4];
    const int* pos   = (const int*)d_in[5];
    const int* blk   = (const int*)d_in[6];
    int base = (in_sizes[7] == 8192 * 128) ? 7 : 8;
    const float* emb  = (const float*)d_in[base + 0];
    const float* femb = (const float*)d_in[base + 1];
    const float* pemb = (const float*)d_in[base + 2];
    const float* bemb = (const float*)d_in[base + 3];
    const float* Wq   = (const float*)d_in[base + 4];
    const float* Wk   = (const float*)d_in[base + 5];
    const float* Wv   = (const float*)d_in[base + 6];
    const float* Wek  = (const float*)d_in[base + 7];
    const float* Wev  = (const float*)d_in[base + 8];
    const float* Wo   = (const float*)d_in[base + 9];
    const float* Weu  = (const float*)d_in[base + 10];
    const float* QW1  = (const float*)d_in[base + 11];
    const float* Qb1  = (const float*)d_in[base + 12];
    const float* QW2  = (const float*)d_in[base + 13];
    const float* Qb2  = (const float*)d_in[base + 14];
    const int* src = ei;
    const int* dst = ei + EE;
    float* out = (float*)d_out;

    float *feat0, *feat1, *e0, *e1, *qkv, *ekv, *sc, *m, *den, *agg, *P, *Q;
    float *ga, *cn, *ce, *elut, *ekvlut;
    int* code;
    cudaGetSymbolAddress((void**)&feat0, g_feat0);
    cudaGetSymbolAddress((void**)&feat1, g_feat1);
    cudaGetSymbolAddress((void**)&e0, g_e0);
    cudaGetSymbolAddress((void**)&e1, g_e1);
    cudaGetSymbolAddress((void**)&qkv, g_qkv);
    cudaGetSymbolAddress((void**)&ekv, g_ekv);
    cudaGetSymbolAddress((void**)&sc, g_sc);
    cudaGetSymbolAddress((void**)&m, g_m);
    cudaGetSymbolAddress((void**)&den, g_den);
    cudaGetSymbolAddress((void**)&agg, g_agg);
    cudaGetSymbolAddress((void**)&P, g_P);
    cudaGetSymbolAddress((void**)&Q, g_Q);
    cudaGetSymbolAddress((void**)&ga, g_ga);
    cudaGetSymbolAddress((void**)&cn, g_cn);
    cudaGetSymbolAddress((void**)&ce, g_ce);
    cudaGetSymbolAddress((void**)&code, g_code);
    cudaGetSymbolAddress((void**)&elut, g_elut);
    cudaGetSymbolAddress((void**)&ekvlut, g_ekvlut);

    const int TPB = 256;
    const int gN32 = (NN * 32 + TPB - 1) / TPB;
    const int gE32 = (EE * 32 + TPB - 1) / TPB;
    const int gE64 = (EE * 64 + TPB - 1) / TPB;
    const int GN = (NN + 127) / 128;
    const int GE = (EE + 127) / 128;

    // prologue: node embeddings + layer-0 edge LUT path
    k_node_embed<<<gN32, TPB>>>(x, emb, feat0);
    k_lut_e<<<1024, 128>>>(femb, pemb, bemb, elut);
    k_code<<<(EE + TPB - 1) / TPB, TPB>>>(flow, pos, blk, src, dst, code);
    k_expand_e<<<gE32, TPB>>>(code, elut, e0);
    gemm_t<0><<<8, TPB>>>(elut, Wek, ekvlut, nullptr, nullptr, nullptr, nullptr, nullptr,
                          1024, 256, 0);
    gemm_t<0><<<8, TPB>>>(elut, Wev, ekvlut, nullptr, nullptr, nullptr, nullptr, nullptr,
                          1024, 256, 128);
    k_expand_ekv<<<gE64, TPB>>>(code, ekvlut, ekv);

    float* fc = feat0; float* fn = feat1;
    float* ec = e0;    float* en = e1;

    for (int l = 0; l < LL; l++) {
        const float* wq  = Wq  + (size_t)l * 128 * 128;
        const float* wk  = Wk  + (size_t)l * 128 * 128;
        const float* wv  = Wv  + (size_t)l * 128 * 128;
        const float* wek = Wek + (size_t)l * 128 * 128;
        const float* wev = Wev + (size_t)l * 128 * 128;
        const float* wo  = Wo  + (size_t)l * 128 * 128;
        const float* weuS = Weu + (size_t)l * 384 * 128;
        const float* weuD = weuS + 128 * 128;
        const float* weuE = weuS + 256 * 128;

        gemm_t<0><<<GN, TPB>>>(fc, wq, qkv, nullptr, nullptr, nullptr, nullptr, nullptr,
                               NN, 384, 0);
        gemm_t<0><<<GN, TPB>>>(fc, wk, qkv, nullptr, nullptr, nullptr, nullptr, nullptr,
                               NN, 384, 128);
        gemm_t<0><<<GN, TPB>>>(fc, wv, qkv, nullptr, nullptr, nullptr, nullptr, nullptr,
                               NN, 384, 256);
        if (l > 0) {
            gemm_t<0><<<GE, TPB>>>(ec, wek, ekv, nullptr, nullptr, nullptr, nullptr, nullptr,
                                   EE, 256, 0);
            gemm_t<0><<<GE, TPB>>>(ec, wev, ekv, nullptr, nullptr, nullptr, nullptr, nullptr,
                                   EE, 256, 128);
        }
        // P = fc @ Weu[0:128], Q = fc @ Weu[128:256]  (edge-update decomposition)
        gemm_t<0><<<GN, TPB>>>(fc, weuS, P, nullptr, nullptr, nullptr, nullptr, nullptr,
                               NN, 128, 0);
        gemm_t<0><<<GN, TPB>>>(fc, weuD, Q, nullptr, nullptr, nullptr, nullptr, nullptr,
                               NN, 128, 0);

        k_fill<<<(NN * 4 + TPB - 1) / TPB, TPB>>>(m, NN * 4, -3.4e38f);
        cudaMemsetAsync(den, 0, (size_t)NN * 4 * sizeof(float));
        cudaMemsetAsync(agg, 0, (size_t)NN * 128 * sizeof(float));

        k_scores<<<gE32, TPB>>>(qkv, ekv, src, dst, sc, m);
        k_expden<<<(EE * 4 + TPB - 1) / TPB, TPB>>>(dst, sc, m, den);
        k_agg<<<gE32, TPB>>>(qkv, ekv, src, dst, sc, den, agg);

        gemm_t<1><<<GN, TPB>>>(agg, wo, fn, fc, nullptr, nullptr, nullptr, nullptr,
                               NN, 128, 0);
        gemm_t<2><<<GE, TPB>>>(ec, weuE, en, ec, P, Q, src, dst, EE, 128, 0);

        float* tf = fc; fc = fn; fn = tf;
        float* te = ec; ec = en; en = te;
    }

    cudaMemsetAsync(ga, 0, (size_t)GG * 256 * sizeof(float));
    cudaMemsetAsync(cn, 0, GG * sizeof(float));
    cudaMemsetAsync(ce, 0, GG * sizeof(float));
    k_gnode<<<gN32, TPB>>>(fc, ntype, batch, ga, cn);
    k_gedge<<<gE32, TPB>>>(ec, src, batch, ga, ce);
    k_head<<<GG, 128>>>(ga, cn, ce, QW1, Qb1, QW2, Qb2, out);
}

// round 3
// speedup vs baseline: 1.0742x; 1.0079x over previous
#include <cuda_runtime.h>
#include <math.h>

#define NN 100000
#define EE 500000
#define DD 128
#define LL 8
#define GG 64
#define AA 100

// ---------------- scratch (static device arrays; no cudaMalloc) -------------
__device__ float g_feat0[(size_t)NN * DD];
__device__ float g_feat1[(size_t)NN * DD];
__device__ float g_e0[(size_t)EE * DD];
__device__ float g_e1[(size_t)EE * DD];
__device__ float g_qkv[(size_t)NN * 3 * DD];
__device__ float g_ekv[(size_t)EE * 2 * DD];
__device__ float g_sc[(size_t)EE * 4];
__device__ float g_m[NN * 4];
__device__ float g_den[NN * 4];
__device__ float g_agg[(size_t)NN * DD];
__device__ float g_P[(size_t)NN * DD];
__device__ float g_Q[(size_t)NN * DD];
__device__ float g_ga[GG * 256];
__device__ float g_cn[GG];
__device__ float g_ce[GG];
__device__ int   g_code[EE];
__device__ float g_elut[1024 * DD];
__device__ float g_ekvlut[1024 * 2 * DD];

// ---------------- helpers ---------------------------------------------------
__device__ __forceinline__ void atomicMaxF(float* addr, float v) {
    if (v >= 0.f) atomicMax((int*)addr, __float_as_int(v));
    else          atomicMin((unsigned int*)addr, __float_as_uint(v));
}

__device__ __forceinline__ void cp_async16(void* smem, const void* gmem) {
    unsigned s = (unsigned)__cvta_generic_to_shared(smem);
    asm volatile("cp.async.cg.shared.global [%0], [%1], 16;\n" :: "r"(s), "l"(gmem));
}
__device__ __forceinline__ void cp_commit() {
    asm volatile("cp.async.commit_group;\n");
}
__device__ __forceinline__ void cp_wait_all() {
    asm volatile("cp.async.wait_group 0;\n");
}

__global__ void k_fill(float* p, int n, float v) {
    int i = blockIdx.x * blockDim.x + threadIdx.x;
    if (i < n) p[i] = v;
}

// feat[n][:] = emb_table[x[n]][:]
__global__ void k_node_embed(const int* __restrict__ x,
                             const float* __restrict__ emb,
                             float* __restrict__ feat) {
    unsigned t = blockIdx.x * blockDim.x + threadIdx.x;
    if (t >= (unsigned)NN * 32u) return;
    int n = t >> 5, q = t & 31;
    float4 v = *reinterpret_cast<const float4*>(emb + (size_t)x[n] * 128 + q * 4);
    *reinterpret_cast<float4*>(feat + (size_t)n * 128 + q * 4) = v;
}

// elut[c][:] = flow_emb[c>>7] + pos_emb[(c>>1)&63] + blk_emb[c&1]
__global__ void k_lut_e(const float* __restrict__ femb, const float* __restrict__ pemb,
                        const float* __restrict__ bemb, float* __restrict__ elut) {
    int c = blockIdx.x, t = threadIdx.x;  // 1024 blocks, 128 threads
    elut[c * 128 + t] = femb[(c >> 7) * 128 + t] + pemb[((c >> 1) & 63) * 128 + t] +
                        bemb[(c & 1) * 128 + t];
}

__global__ void k_code(const int* __restrict__ flow, const int* __restrict__ pos,
                       const int* __restrict__ blk,
                       const int* __restrict__ src, const int* __restrict__ dst,
                       int* __restrict__ code) {
    int e = blockIdx.x * blockDim.x + threadIdx.x;
    if (e >= EE) return;
    int cr = (blk[src[e]] != blk[dst[e]]) ? 1 : 0;
    code[e] = (flow[e] << 7) | (pos[e] << 1) | cr;
}

__global__ void k_expand_e(const int* __restrict__ code, const float* __restrict__ elut,
                           float* __restrict__ e) {
    unsigned t = blockIdx.x * blockDim.x + threadIdx.x;
    if (t >= (unsigned)EE * 32u) return;
    int ed = t >> 5, q = t & 31;
    float4 v = *reinterpret_cast<const float4*>(elut + (size_t)code[ed] * 128 + q * 4);
    *reinterpret_cast<float4*>(e + (size_t)ed * 128 + q * 4) = v;
}

__global__ void k_expand_ekv(const int* __restrict__ code, const float* __restrict__ lut,
                             float* __restrict__ ekv) {
    unsigned t = blockIdx.x * blockDim.x + threadIdx.x;
    if (t >= (unsigned)EE * 64u) return;
    int ed = t >> 6, q = t & 63;
    float4 v = *reinterpret_cast<const float4*>(lut + (size_t)code[ed] * 256 + q * 4);
    *reinterpret_cast<float4*>(ekv + (size_t)ed * 256 + q * 4) = v;
}

// ---------------- pipelined fp32 GEMM: C[M,128] = A[M,128] @ B[128,128] -----
// MODE 0: plain (strided C via ldc+colofs)
// MODE 1: C = relu(R + A@B)
// MODE 2: C = relu(R + A@B + P[src] + Q[dst])   (edge update, decomposed)
template<int MODE>
__global__ __launch_bounds__(256, 2) void gemm_t(
    const float* __restrict__ A, const float* __restrict__ B,
    float* __restrict__ C, const float* __restrict__ R,
    const float* __restrict__ P, const float* __restrict__ Q,
    const int* __restrict__ src, const int* __restrict__ dst,
    int M, int ldc, int colofs)
{
    __shared__ float As[2][16][128];
    __shared__ float Bs[2][16][128];
    const int tid = threadIdx.x;
    const int m0 = blockIdx.x * 128;
    const int tx = tid & 15, ty = tid >> 4;
    const int ar = tid >> 2, ac = (tid & 3) << 2;   // A: row ar(+64), k within tile
    const int br = tid >> 5, bc = (tid & 31) << 2;  // B: k-row br(+8), col bc

    // clamped row indices (OOB rows read garbage but are never written)
    int row0 = m0 + ar;       if (row0 >= M) row0 = M - 1;
    int row1 = m0 + ar + 64;  if (row1 >= M) row1 = M - 1;
    const float* a0p = A + (size_t)row0 * 128 + ac;
    const float* a1p = A + (size_t)row1 * 128 + ac;

    float acc[8][8];
#pragma unroll
    for (int i = 0; i < 8; i++)
#pragma unroll
        for (int j = 0; j < 8; j++) acc[i][j] = 0.f;

    // prologue: tile 0
    float4 ra0 = *reinterpret_cast<const float4*>(a0p);
    float4 ra1 = *reinterpret_cast<const float4*>(a1p);
    {
        As[0][ac + 0][ar] = ra0.x; As[0][ac + 1][ar] = ra0.y;
        As[0][ac + 2][ar] = ra0.z; As[0][ac + 3][ar] = ra0.w;
        As[0][ac + 0][ar + 64] = ra1.x; As[0][ac + 1][ar + 64] = ra1.y;
        As[0][ac + 2][ar + 64] = ra1.z; As[0][ac + 3][ar + 64] = ra1.w;
#pragma unroll
        for (int p = 0; p < 2; p++)
            cp_async16(&Bs[0][br + p * 8][bc], B + (size_t)(br + p * 8) * 128 + bc);
        cp_commit();
    }
    cp_wait_all();
    __syncthreads();

#pragma unroll
    for (int kt = 0; kt < 8; kt++) {
        const int cur = kt & 1, nxt = cur ^ 1;
        if (kt < 7) {
            ra0 = *reinterpret_cast<const float4*>(a0p + (kt + 1) * 16);
            ra1 = *reinterpret_cast<const float4*>(a1p + (kt + 1) * 16);
#pragma unroll
            for (int p = 0; p < 2; p++)
                cp_async16(&Bs[nxt][br + p * 8][bc],
                           B + (size_t)((kt + 1) * 16 + br + p * 8) * 128 + bc);
            cp_commit();
        }
#pragma unroll
        for (int k = 0; k < 16; k++) {
            float a[8], b[8];
            *reinterpret_cast<float4*>(&a[0]) = *reinterpret_cast<const float4*>(&As[cur][k][ty * 8]);
            *reinterpret_cast<float4*>(&a[4]) = *reinterpret_cast<const float4*>(&As[cur][k][ty * 8 + 4]);
            *reinterpret_cast<float4*>(&b[0]) = *reinterpret_cast<const float4*>(&Bs[cur][k][tx * 8]);
            *reinterpret_cast<float4*>(&b[4]) = *reinterpret_cast<const float4*>(&Bs[cur][k][tx * 8 + 4]);
#pragma unroll
            for (int i = 0; i < 8; i++)
#pragma unroll
                for (int j = 0; j < 8; j++) acc[i][j] = fmaf(a[i], b[j], acc[i][j]);
        }
        if (kt < 7) {
            As[nxt][ac + 0][ar] = ra0.x; As[nxt][ac + 1][ar] = ra0.y;
            As[nxt][ac + 2][ar] = ra0.z; As[nxt][ac + 3][ar] = ra0.w;
            As[nxt][ac + 0][ar + 64] = ra1.x; As[nxt][ac + 1][ar + 64] = ra1.y;
            As[nxt][ac + 2][ar + 64] = ra1.z; As[nxt][ac + 3][ar + 64] = ra1.w;
            cp_wait_all();
            __syncthreads();
        }
    }

#pragma unroll
    for (int i = 0; i < 8; i++) {
        int row = m0 + ty * 8 + i;
        if (row >= M) continue;
        int s = 0, d = 0;
        if (MODE == 2) { s = src[row]; d = dst[row]; }
#pragma unroll
        for (int j = 0; j < 8; j += 4) {
            int col = tx * 8 + j;
            float4 r = make_float4(acc[i][j], acc[i][j + 1], acc[i][j + 2], acc[i][j + 3]);
            if (MODE >= 1) {
                float4 rv = *reinterpret_cast<const float4*>(R + (size_t)row * 128 + col);
                r.x += rv.x; r.y += rv.y; r.z += rv.z; r.w += rv.w;
            }
            if (MODE == 2) {
                float4 pv = *reinterpret_cast<const float4*>(P + (size_t)s * 128 + col);
                float4 qv = *reinterpret_cast<const float4*>(Q + (size_t)d * 128 + col);
                r.x += pv.x + qv.x; r.y += pv.y + qv.y;
                r.z += pv.z + qv.z; r.w += pv.w + qv.w;
            }
            if (MODE >= 1) {
                r.x = fmaxf(r.x, 0.f); r.y = fmaxf(r.y, 0.f);
                r.z = fmaxf(r.z, 0.f); r.w = fmaxf(r.w, 0.f);
            }
            *reinterpret_cast<float4*>(C + (size_t)row * ldc + colofs + col) = r;
        }
    }
}

// ---------------- attention edge kernels ------------------------------------
__global__ void k_scores(const float* __restrict__ qkv, const float* __restrict__ ekv,
                         const int* __restrict__ src, const int* __restrict__ dst,
                         float* __restrict__ sc, float* __restrict__ m)
{
    unsigned t = blockIdx.x * blockDim.x + threadIdx.x;
    int w = t >> 5;
    int lane = threadIdx.x & 31;
    if (w >= EE) return;
    int s = src[w], d = dst[w];
    float4 q4 = *reinterpret_cast<const float4*>(qkv + (size_t)d * 384 + lane * 4);
    float4 k4 = *reinterpret_cast<const float4*>(qkv + (size_t)s * 384 + 128 + lane * 4);
    float4 e4 = *reinterpret_cast<const float4*>(ekv + (size_t)w * 256 + lane * 4);
    float p = q4.x * (k4.x + e4.x) + q4.y * (k4.y + e4.y) +
              q4.z * (k4.z + e4.z) + q4.w * (k4.w + e4.w);
    p += __shfl_xor_sync(0xffffffffu, p, 4);
    p += __shfl_xor_sync(0xffffffffu, p, 2);
    p += __shfl_xor_sync(0xffffffffu, p, 1);
    if ((lane & 7) == 0) {
        int h = lane >> 3;
        float v = p * 0.17677669529663687f;  // 1/sqrt(32)
        sc[(size_t)w * 4 + h] = v;
        atomicMaxF(&m[d * 4 + h], v);
    }
}

__global__ void k_expden(const int* __restrict__ dst, float* __restrict__ sc,
                         const float* __restrict__ m, float* __restrict__ den)
{
    unsigned i = blockIdx.x * blockDim.x + threadIdx.x;
    if (i >= (unsigned)EE * 4u) return;
    int e = i >> 2, h = i & 3;
    int d = dst[e];
    float ex = __expf(sc[i] - m[d * 4 + h]);
    sc[i] = ex;
    atomicAdd(&den[d * 4 + h], ex);
}

__global__ void k_agg(const float* __restrict__ qkv, const float* __restrict__ ekv,
                      const int* __restrict__ src, const int* __restrict__ dst,
                      const float* __restrict__ sc, const float* __restrict__ den,
                      float* __restrict__ agg)
{
    unsigned t = blockIdx.x * blockDim.x + threadIdx.x;
    int w = t >> 5;
    int lane = threadIdx.x & 31;
    if (w >= EE) return;
    int s = src[w], d = dst[w];
    int h = lane >> 3;
    float alpha = sc[(size_t)w * 4 + h] / (den[d * 4 + h] + 1e-16f);
    float4 v4 = *reinterpret_cast<const float4*>(qkv + (size_t)s * 384 + 256 + lane * 4);
    float4 e4 = *reinterpret_cast<const float4*>(ekv + (size_t)w * 256 + 128 + lane * 4);
    float* p = agg + (size_t)d * 128 + lane * 4;
    atomicAdd(p + 0, alpha * (v4.x + e4.x));
    atomicAdd(p + 1, alpha * (v4.y + e4.y));
    atomicAdd(p + 2, alpha * (v4.z + e4.z));
    atomicAdd(p + 3, alpha * (v4.w + e4.w));
}

// ---------------- graph pooling ----------------------------------------------
__global__ void k_gnode(const float* __restrict__ feat, const int* __restrict__ ntype,
                        const int* __restrict__ batch, float* __restrict__ ga,
                        float* __restrict__ cn)
{
    unsigned t = blockIdx.x * blockDim.x + threadIdx.x;
    if (t >= (unsigned)NN * 32u) return;
    int n = t >> 5, q = t & 31;
    if (ntype[n] != 0) return;
    int b = batch[n];
    float4 f = *reinterpret_cast<const float4*>(feat + (size_t)n * 128 + q * 4);
    float* p = ga + (size_t)b * 256 + q * 4;
    atomicAdd(p + 0, f.x); atomicAdd(p + 1, f.y);
    atomicAdd(p + 2, f.z); atomicAdd(p + 3, f.w);
    if (q == 0) atomicAdd(&cn[b], 1.f);
}

__global__ void k_gedge(const float* __restrict__ e, const int* __restrict__ src,
                        const int* __restrict__ batch, float* __restrict__ ga,
                        float* __restrict__ ce)
{
    unsigned t = blockIdx.x * blockDim.x + threadIdx.x;
    if (t >= (unsigned)EE * 32u) return;
    int ed = t >> 5, q = t & 31;
    int b = batch[src[ed]];
    float4 f = *reinterpret_cast<const float4*>(e + (size_t)ed * 128 + q * 4);
    float* p = ga + (size_t)b * 256 + 128 + q * 4;
    atomicAdd(p + 0, f.x); atomicAdd(p + 1, f.y);
    atomicAdd(p + 2, f.z); atomicAdd(p + 3, f.w);
    if (q == 0) atomicAdd(&ce[b], 1.f);
}

// ---------------- Q head ------------------------------------------------------
__global__ void k_head(const float* __restrict__ ga, const float* __restrict__ cn,
                       const float* __restrict__ ce,
                       const float* __restrict__ QW1, const float* __restrict__ Qb1,
                       const float* __restrict__ QW2, const float* __restrict__ Qb2,
                       float* __restrict__ out)
{
    int g = blockIdx.x;
    int t = threadIdx.x;  // 128
    __shared__ float s_in[256];
    __shared__ float s_h[128];
    __shared__ float s_l[128];
    __shared__ float s_max, s_lse;
    float nc = fmaxf(cn[g], 1.0f);
    float ec = fmaxf(ce[g], 1.0f);
    s_in[t]       = ga[(size_t)g * 256 + t] / nc;
    s_in[t + 128] = ga[(size_t)g * 256 + 128 + t] / ec;
    __syncthreads();
    float acc = Qb1[t];
    for (int k = 0; k < 256; k++) acc = fmaf(s_in[k], QW1[(size_t)k * 128 + t], acc);
    s_h[t] = fmaxf(acc, 0.f);
    __syncthreads();
    float lg = 0.f;
    if (t < AA) {
        lg = Qb2[t];
        for (int k = 0; k < 128; k++) lg = fmaf(s_h[k], QW2[(size_t)k * AA + t], lg);
        s_l[t] = lg;
    }
    __syncthreads();
    if (t == 0) {
        float mx = -3.4e38f;
        for (int i = 0; i < AA; i++) mx = fmaxf(mx, s_l[i]);
        float s = 0.f;
        for (int i = 0; i < AA; i++) s += expf(s_l[i] - mx);
        s_max = mx;
        s_lse = logf(s);
    }
    __syncthreads();
    if (t < AA) out[(size_t)g * AA + t] = lg - s_max - s_lse;
}

// ---------------- launch ------------------------------------------------------
extern "C" void kernel_launch(void* const* d_in, const int* in_sizes, int n_in,
                              void* d_out, int out_size)
{
    const int* x     = (const int*)d_in[0];
    const int* ntype = (const int*)d_in[1];
    const int* batch = (const int*)d_in[2];
    const int* ei    = (const int*)d_in[3];
    const int* flow  = (const int*)d_in[4];
    const int* pos   = (const int*)d_in[5];
    const int* blk   = (const int*)d_in[6];
    int base = (in_sizes[7] == 8192 * 128) ? 7 : 8;
    const float* emb  = (const float*)d_in[base + 0];
    const float* femb = (const float*)d_in[base + 1];
    const float* pemb = (const float*)d_in[base + 2];
    const float* bemb = (const float*)d_in[base + 3];
    const float* Wq   = (const float*)d_in[base + 4];
    const float* Wk   = (const float*)d_in[base + 5];
    const float* Wv   = (const float*)d_in[base + 6];
    const float* Wek  = (const float*)d_in[base + 7];
    const float* Wev  = (const float*)d_in[base + 8];
    const float* Wo   = (const float*)d_in[base + 9];
    const float* Weu  = (const float*)d_in[base + 10];
    const float* QW1  = (const float*)d_in[base + 11];
    const float* Qb1  = (const float*)d_in[base + 12];
    const float* QW2  = (const float*)d_in[base + 13];
    const float* Qb2  = (const float*)d_in[base + 14];
    const int* src = ei;
    const int* dst = ei + EE;
    float* out = (float*)d_out;

    float *feat0, *feat1, *e0, *e1, *qkv, *ekv, *sc, *m, *den, *agg, *P, *Q;
    float *ga, *cn, *ce, *elut, *ekvlut;
    int* code;
    cudaGetSymbolAddress((void**)&feat0, g_feat0);
    cudaGetSymbolAddress((void**)&feat1, g_feat1);
    cudaGetSymbolAddress((void**)&e0, g_e0);
    cudaGetSymbolAddress((void**)&e1, g_e1);
    cudaGetSymbolAddress((void**)&qkv, g_qkv);
    cudaGetSymbolAddress((void**)&ekv, g_ekv);
    cudaGetSymbolAddress((void**)&sc, g_sc);
    cudaGetSymbolAddress((void**)&m, g_m);
    cudaGetSymbolAddress((void**)&den, g_den);
    cudaGetSymbolAddress((void**)&agg, g_agg);
    cudaGetSymbolAddress((void**)&P, g_P);
    cudaGetSymbolAddress((void**)&Q, g_Q);
    cudaGetSymbolAddress((void**)&ga, g_ga);
    cudaGetSymbolAddress((void**)&cn, g_cn);
    cudaGetSymbolAddress((void**)&ce, g_ce);
    cudaGetSymbolAddress((void**)&code, g_code);
    cudaGetSymbolAddress((void**)&elut, g_elut);
    cudaGetSymbolAddress((void**)&ekvlut, g_ekvlut);

    const int TPB = 256;
    const int gN32 = (NN * 32 + TPB - 1) / TPB;
    const int gE32 = (EE * 32 + TPB - 1) / TPB;
    const int gE64 = (EE * 64 + TPB - 1) / TPB;
    const int GN = (NN + 127) / 128;
    const int GE = (EE + 127) / 128;

    // prologue: node embeddings + layer-0 edge LUT path
    k_node_embed<<<gN32, TPB>>>(x, emb, feat0);
    k_lut_e<<<1024, 128>>>(femb, pemb, bemb, elut);
    k_code<<<(EE + TPB - 1) / TPB, TPB>>>(flow, pos, blk, src, dst, code);
    k_expand_e<<<gE32, TPB>>>(code, elut, e0);
    gemm_t<0><<<8, TPB>>>(elut, Wek, ekvlut, nullptr, nullptr, nullptr, nullptr, nullptr,
                          1024, 256, 0);
    gemm_t<0><<<8, TPB>>>(elut, Wev, ekvlut, nullptr, nullptr, nullptr, nullptr, nullptr,
                          1024, 256, 128);
    k_expand_ekv<<<gE64, TPB>>>(code, ekvlut, ekv);

    float* fc = feat0; float* fn = feat1;
    float* ec = e0;    float* en = e1;

    for (int l = 0; l < LL; l++) {
        const float* wq  = Wq  + (size_t)l * 128 * 128;
        const float* wk  = Wk  + (size_t)l * 128 * 128;
        const float* wv  = Wv  + (size_t)l * 128 * 128;
        const float* wek = Wek + (size_t)l * 128 * 128;
        const float* wev = Wev + (size_t)l * 128 * 128;
        const float* wo  = Wo  + (size_t)l * 128 * 128;
        const float* weuS = Weu + (size_t)l * 384 * 128;
        const float* weuD = weuS + 128 * 128;
        const float* weuE = weuS + 256 * 128;

        gemm_t<0><<<GN, TPB>>>(fc, wq, qkv, nullptr, nullptr, nullptr, nullptr, nullptr,
                               NN, 384, 0);
        gemm_t<0><<<GN, TPB>>>(fc, wk, qkv, nullptr, nullptr, nullptr, nullptr, nullptr,
                               NN, 384, 128);
        gemm_t<0><<<GN, TPB>>>(fc, wv, qkv, nullptr, nullptr, nullptr, nullptr, nullptr,
                               NN, 384, 256);
        if (l > 0) {
            gemm_t<0><<<GE, TPB>>>(ec, wek, ekv, nullptr, nullptr, nullptr, nullptr, nullptr,
                                   EE, 256, 0);
            gemm_t<0><<<GE, TPB>>>(ec, wev, ekv, nullptr, nullptr, nullptr, nullptr, nullptr,
                                   EE, 256, 128);
        }
        // P = fc @ Weu[0:128], Q = fc @ Weu[128:256]  (edge-update decomposition)
        gemm_t<0><<<GN, TPB>>>(fc, weuS, P, nullptr, nullptr, nullptr, nullptr, nullptr,
                               NN, 128, 0);
        gemm_t<0><<<GN, TPB>>>(fc, weuD, Q, nullptr, nullptr, nullptr, nullptr, nullptr,
                               NN, 128, 0);

        k_fill<<<(NN * 4 + TPB - 1) / TPB, TPB>>>(m, NN * 4, -3.4e38f);
        cudaMemsetAsync(den, 0, (size_t)NN * 4 * sizeof(float));
        cudaMemsetAsync(agg, 0, (size_t)NN * 128 * sizeof(float));

        k_scores<<<gE32, TPB>>>(qkv, ekv, src, dst, sc, m);
        k_expden<<<(EE * 4 + TPB - 1) / TPB, TPB>>>(dst, sc, m, den);
        k_agg<<<gE32, TPB>>>(qkv, ekv, src, dst, sc, den, agg);

        gemm_t<1><<<GN, TPB>>>(agg, wo, fn, fc, nullptr, nullptr, nullptr, nullptr,
                               NN, 128, 0);
        gemm_t<2><<<GE, TPB>>>(ec, weuE, en, ec, P, Q, src, dst, EE, 128, 0);

        float* tf = fc; fc = fn; fn = tf;
        float* te = ec; ec = en; en = te;
    }

    cudaMemsetAsync(ga, 0, (size_t)GG * 256 * sizeof(float));
    cudaMemsetAsync(cn, 0, GG * sizeof(float));
    cudaMemsetAsync(ce, 0, GG * sizeof(float));
    k_gnode<<<gN32, TPB>>>(fc, ntype, batch, ga, cn);
    k_gedge<<<gE32, TPB>>>(ec, src, batch, ga, ce);
    k_head<<<GG, 128>>>(ga, cn, ce, QW1, Qb1, QW2, Qb2, out);
}

// round 6
// speedup vs baseline: 1.2593x; 1.1723x over previous
#include <cuda_runtime.h>
#include <cuda_bf16.h>
#include <math.h>
#include <stdint.h>

#define NN 100000
#define EE 500000
#define DD 128
#define LL 8
#define GG 64
#define AA 100

// ---------------- scratch (static device arrays; no cudaMalloc) -------------
__device__ float g_feat0[(size_t)NN * DD];
__device__ float g_feat1[(size_t)NN * DD];
__device__ float g_e0[(size_t)EE * DD];
__device__ float g_e1[(size_t)EE * DD];
__device__ float g_qkv[(size_t)NN * 3 * DD];
__device__ float g_ekv[(size_t)EE * 2 * DD];
__device__ float g_sc[(size_t)EE * 4];
__device__ float g_m[NN * 4];
__device__ float g_den[NN * 4];
__device__ float g_agg[(size_t)NN * DD];
__device__ float g_PQ[(size_t)NN * 256];
__device__ float g_ga[GG * 256];
__device__ float g_cn[GG];
__device__ float g_ce[GG];
__device__ int   g_code[EE];
__device__ float g_elut[1024 * DD];
__device__ float g_ekvlut[1024 * 2 * DD];
// packed weights: 8 layers x 9 mats x (16384 hi + 16384 lo) bf16, [k][n] row-major
__device__ __nv_bfloat16 g_pack[(size_t)LL * 9 * 32768];

// ---------------- PTX helpers (baseline features only: sm_80-era) -----------
__device__ __forceinline__ uint32_t smem_u32(const void* p) {
    return (uint32_t)__cvta_generic_to_shared(p);
}
__device__ __forceinline__ void cp_async16(uint32_t smem, const void* gmem) {
    asm volatile("cp.async.cg.shared.global [%0], [%1], 16;\n" :: "r"(smem), "l"(gmem));
}
__device__ __forceinline__ void cp_commit() { asm volatile("cp.async.commit_group;\n"); }
__device__ __forceinline__ void cp_wait_all() { asm volatile("cp.async.wait_group 0;\n"); }

__device__ __forceinline__ void ldmx4(uint32_t* r, uint32_t addr) {
    asm volatile("ldmatrix.sync.aligned.m8n8.x4.shared.b16 {%0,%1,%2,%3}, [%4];"
                 : "=r"(r[0]), "=r"(r[1]), "=r"(r[2]), "=r"(r[3]) : "r"(addr));
}
__device__ __forceinline__ void ldmx2t(uint32_t* r, uint32_t addr) {
    asm volatile("ldmatrix.sync.aligned.m8n8.x2.trans.shared.b16 {%0,%1}, [%2];"
                 : "=r"(r[0]), "=r"(r[1]) : "r"(addr));
}
__device__ __forceinline__ void mma_bf16(float* c, const uint32_t* a, const uint32_t* b) {
    asm volatile("mma.sync.aligned.m16n8k16.row.col.f32.bf16.bf16.f32 "
                 "{%0,%1,%2,%3}, {%4,%5,%6,%7}, {%8,%9}, {%0,%1,%2,%3};"
                 : "+f"(c[0]), "+f"(c[1]), "+f"(c[2]), "+f"(c[3])
                 : "r"(a[0]), "r"(a[1]), "r"(a[2]), "r"(a[3]), "r"(b[0]), "r"(b[1]));
}

// ---------------- weight pack: split hi/lo bf16, keep [k][n] layout ---------
__global__ void k_packall(const float* __restrict__ Wq, const float* __restrict__ Wk,
                          const float* __restrict__ Wv, const float* __restrict__ Wek,
                          const float* __restrict__ Wev, const float* __restrict__ Wo,
                          const float* __restrict__ Weu, __nv_bfloat16* __restrict__ pack)
{
    int b = blockIdx.x;        // 72 = 8 layers * 9 mats
    int l = b / 9, mt = b % 9;
    const float* W;
    switch (mt) {
        case 0: W = Wq  + (size_t)l * 16384; break;
        case 1: W = Wk  + (size_t)l * 16384; break;
        case 2: W = Wv  + (size_t)l * 16384; break;
        case 3: W = Weu + (size_t)l * 49152; break;           // WeuS
        case 4: W = Weu + (size_t)l * 49152 + 16384; break;   // WeuD
        case 5: W = Wek + (size_t)l * 16384; break;
        case 6: W = Wev + (size_t)l * 16384; break;
        case 7: W = Wo  + (size_t)l * 16384; break;
        default: W = Weu + (size_t)l * 49152 + 32768; break;  // WeuE
    }
    __nv_bfloat16* dst = pack + (size_t)b * 32768;
    for (int idx = threadIdx.x; idx < 16384; idx += blockDim.x) {
        float a = W[idx];
        __nv_bfloat16 h = __float2bfloat16(a);
        __nv_bfloat16 lo = __float2bfloat16(a - __bfloat162float(h));
        dst[idx] = h;
        dst[16384 + idx] = lo;
    }
}

// ---------------- tensor-core GEMM via mma.sync (bf16x3 split) --------------
// C[M, co:co+128] = A[M,128] @ Wmat (fp32 in/out, ~fp32 accuracy)
// MODE 0: plain.  MODE 1: C = relu(R + C).  MODE 2: C = relu(R + C + P[src] + Q[dst])
// smem: Ah | Al | Bh | Bl, each 128 rows x 272B (136 bf16, padded)
template<int MODE>
__global__ void __launch_bounds__(256, 1) mma_gemm(
    const float* __restrict__ A, const __nv_bfloat16* __restrict__ Bp,
    float* __restrict__ C, int ldc, int co,
    const float* __restrict__ R, const float* __restrict__ PQ,
    const int* __restrict__ src, const int* __restrict__ dst, int M)
{
    extern __shared__ char smem[];
    const uint32_t sb = smem_u32(smem);
    const int tid = threadIdx.x;
    const int lane = tid & 31, wid = tid >> 5;
    const int wm = wid & 3, wn = wid >> 2;     // 4x2 warp grid
    const int m0 = blockIdx.x * 128;
    const int PS = 272;                        // padded row stride (bytes)
    const uint32_t OFF_AH = 0, OFF_AL = 34816, OFF_BH = 69632, OFF_BL = 104448;

    // B: pre-packed hi/lo, async copy into padded rows
    for (int idx = tid; idx < 4096; idx += 256) {
        int hl = idx >> 11, rem = idx & 2047, r = rem >> 4, c = rem & 15;
        cp_async16(sb + OFF_BH + hl * 34816 + r * PS + c * 16,
                   (const char*)Bp + hl * 32768 + r * 256 + c * 16);
    }
    cp_commit();

    // A: load fp32, split bf16 hi/lo, store padded
    for (int idx = tid; idx < 4096; idx += 256) {
        int r = idx >> 5, f4 = idx & 31;
        int rg = m0 + r; if (rg >= M) rg = M - 1;
        float4 v = *reinterpret_cast<const float4*>(A + (size_t)rg * 128 + f4 * 4);
        __nv_bfloat16 hx = __float2bfloat16(v.x), hy = __float2bfloat16(v.y);
        __nv_bfloat16 hz = __float2bfloat16(v.z), hw = __float2bfloat16(v.w);
        __nv_bfloat16 lx = __float2bfloat16(v.x - __bfloat162float(hx));
        __nv_bfloat16 ly = __float2bfloat16(v.y - __bfloat162float(hy));
        __nv_bfloat16 lz = __float2bfloat16(v.z - __bfloat162float(hz));
        __nv_bfloat16 lw = __float2bfloat16(v.w - __bfloat162float(hw));
        __nv_bfloat162 h01 = __halves2bfloat162(hx, hy), h23 = __halves2bfloat162(hz, hw);
        __nv_bfloat162 l01 = __halves2bfloat162(lx, ly), l23 = __halves2bfloat162(lz, lw);
        int off = r * PS + f4 * 8;
        *reinterpret_cast<uint2*>(smem + OFF_AH + off) =
            make_uint2(*(uint32_t*)&h01, *(uint32_t*)&h23);
        *reinterpret_cast<uint2*>(smem + OFF_AL + off) =
            make_uint2(*(uint32_t*)&l01, *(uint32_t*)&l23);
    }
    cp_wait_all();
    __syncthreads();

    float acc[2][8][4];
#pragma unroll
    for (int i = 0; i < 2; i++)
#pragma unroll
        for (int j = 0; j < 8; j++)
#pragma unroll
            for (int q = 0; q < 4; q++) acc[i][j][q] = 0.f;

    // 3 split terms: (Ah,Bh), (Ah,Bl), (Al,Bh)
#pragma unroll
    for (int term = 0; term < 3; term++) {
        const uint32_t Ab = sb + (term == 2 ? OFF_AL : OFF_AH);
        const uint32_t Bb = sb + (term == 1 ? OFF_BL : OFF_BH);
        // ldmatrix A: lane L -> row (m_tile + L%16), col chunk (L/16)*8 elems
        const uint32_t aBase = Ab + (wm * 32 + (lane & 15)) * PS + (lane >> 4) * 16;
        // ldmatrix B (.trans): lane L(0..15) -> row (k_tile + L), col n_tile
        const uint32_t bBase = Bb + (lane & 15) * PS + wn * 128;
#pragma unroll
        for (int ks = 0; ks < 8; ks++) {
            uint32_t a0[4], a1[4], bf[8][2];
            ldmx4(a0, aBase + ks * 32);
            ldmx4(a1, aBase + 16 * PS + ks * 32);
#pragma unroll
            for (int nt = 0; nt < 8; nt++)
                ldmx2t(bf[nt], bBase + ks * 16 * PS + nt * 16);
#pragma unroll
            for (int nt = 0; nt < 8; nt++) {
                mma_bf16(acc[0][nt], a0, bf[nt]);
                mma_bf16(acc[1][nt], a1, bf[nt]);
            }
        }
    }

    // epilogue: c0,c1 -> row lane/4, cols (lane%4)*2; c2,c3 -> row lane/4+8
#pragma unroll
    for (int mt = 0; mt < 2; mt++) {
#pragma unroll
        for (int h = 0; h < 2; h++) {
            int row = m0 + wm * 32 + mt * 16 + (lane >> 2) + h * 8;
            if (row >= M) continue;
            int s = 0, d = 0;
            if (MODE == 2) { s = src[row]; d = dst[row]; }
#pragma unroll
            for (int nt = 0; nt < 8; nt++) {
                int col = wn * 64 + nt * 8 + (lane & 3) * 2;
                float vx = acc[mt][nt][h * 2], vy = acc[mt][nt][h * 2 + 1];
                if (MODE >= 1) {
                    float2 rv = *reinterpret_cast<const float2*>(R + (size_t)row * 128 + col);
                    vx += rv.x; vy += rv.y;
                }
                if (MODE == 2) {
                    float2 pv = *reinterpret_cast<const float2*>(PQ + (size_t)s * 256 + col);
                    float2 qv = *reinterpret_cast<const float2*>(PQ + (size_t)d * 256 + 128 + col);
                    vx += pv.x + qv.x; vy += pv.y + qv.y;
                }
                if (MODE >= 1) { vx = fmaxf(vx, 0.f); vy = fmaxf(vy, 0.f); }
                *reinterpret_cast<float2*>(C + (size_t)row * ldc + co + col) =
                    make_float2(vx, vy);
            }
        }
    }
}

// ---------------- misc elementwise kernels ----------------------------------
__device__ __forceinline__ void atomicMaxF(float* addr, float v) {
    if (v >= 0.f) atomicMax((int*)addr, __float_as_int(v));
    else          atomicMin((unsigned int*)addr, __float_as_uint(v));
}

__global__ void k_fill(float* p, int n, float v) {
    int i = blockIdx.x * blockDim.x + threadIdx.x;
    if (i < n) p[i] = v;
}

__global__ void k_node_embed(const int* __restrict__ x, const float* __restrict__ emb,
                             float* __restrict__ feat) {
    unsigned t = blockIdx.x * blockDim.x + threadIdx.x;
    if (t >= (unsigned)NN * 32u) return;
    int n = t >> 5, q = t & 31;
    float4 v = *reinterpret_cast<const float4*>(emb + (size_t)x[n] * 128 + q * 4);
    *reinterpret_cast<float4*>(feat + (size_t)n * 128 + q * 4) = v;
}

__global__ void k_lut_e(const float* __restrict__ femb, const float* __restrict__ pemb,
                        const float* __restrict__ bemb, float* __restrict__ elut) {
    int c = blockIdx.x, t = threadIdx.x;
    elut[c * 128 + t] = femb[(c >> 7) * 128 + t] + pemb[((c >> 1) & 63) * 128 + t] +
                        bemb[(c & 1) * 128 + t];
}

__global__ void k_code(const int* __restrict__ flow, const int* __restrict__ pos,
                       const int* __restrict__ blk, const int* __restrict__ src,
                       const int* __restrict__ dst, int* __restrict__ code) {
    int e = blockIdx.x * blockDim.x + threadIdx.x;
    if (e >= EE) return;
    int cr = (blk[src[e]] != blk[dst[e]]) ? 1 : 0;
    code[e] = (flow[e] << 7) | (pos[e] << 1) | cr;
}

__global__ void k_expand_e(const int* __restrict__ code, const float* __restrict__ elut,
                           float* __restrict__ e) {
    unsigned t = blockIdx.x * blockDim.x + threadIdx.x;
    if (t >= (unsigned)EE * 32u) return;
    int ed = t >> 5, q = t & 31;
    float4 v = *reinterpret_cast<const float4*>(elut + (size_t)code[ed] * 128 + q * 4);
    *reinterpret_cast<float4*>(e + (size_t)ed * 128 + q * 4) = v;
}

__global__ void k_expand_ekv(const int* __restrict__ code, const float* __restrict__ lut,
                             float* __restrict__ ekv) {
    unsigned t = blockIdx.x * blockDim.x + threadIdx.x;
    if (t >= (unsigned)EE * 64u) return;
    int ed = t >> 6, q = t & 63;
    float4 v = *reinterpret_cast<const float4*>(lut + (size_t)code[ed] * 256 + q * 4);
    *reinterpret_cast<float4*>(ekv + (size_t)ed * 256 + q * 4) = v;
}

__global__ void k_scores(const float* __restrict__ qkv, const float* __restrict__ ekv,
                         const int* __restrict__ src, const int* __restrict__ dst,
                         float* __restrict__ sc, float* __restrict__ m)
{
    unsigned t = blockIdx.x * blockDim.x + threadIdx.x;
    int w = t >> 5;
    int lane = threadIdx.x & 31;
    if (w >= EE) return;
    int s = src[w], d = dst[w];
    float4 q4 = *reinterpret_cast<const float4*>(qkv + (size_t)d * 384 + lane * 4);
    float4 k4 = *reinterpret_cast<const float4*>(qkv + (size_t)s * 384 + 128 + lane * 4);
    float4 e4 = *reinterpret_cast<const float4*>(ekv + (size_t)w * 256 + lane * 4);
    float p = q4.x * (k4.x + e4.x) + q4.y * (k4.y + e4.y) +
              q4.z * (k4.z + e4.z) + q4.w * (k4.w + e4.w);
    p += __shfl_xor_sync(0xffffffffu, p, 4);
    p += __shfl_xor_sync(0xffffffffu, p, 2);
    p += __shfl_xor_sync(0xffffffffu, p, 1);
    if ((lane & 7) == 0) {
        int h = lane >> 3;
        float v = p * 0.17677669529663687f;
        sc[(size_t)w * 4 + h] = v;
        atomicMaxF(&m[d * 4 + h], v);
    }
}

__global__ void k_expden(const int* __restrict__ dst, float* __restrict__ sc,
                         const float* __restrict__ m, float* __restrict__ den)
{
    unsigned i = blockIdx.x * blockDim.x + threadIdx.x;
    if (i >= (unsigned)EE * 4u) return;
    int e = i >> 2, h = i & 3;
    int d = dst[e];
    float ex = __expf(sc[i] - m[d * 4 + h]);
    sc[i] = ex;
    atomicAdd(&den[d * 4 + h], ex);
}

__global__ void k_agg(const float* __restrict__ qkv, const float* __restrict__ ekv,
                      const int* __restrict__ src, const int* __restrict__ dst,
                      const float* __restrict__ sc, const float* __restrict__ den,
                      float* __restrict__ agg)
{
    unsigned t = blockIdx.x * blockDim.x + threadIdx.x;
    int w = t >> 5;
    int lane = threadIdx.x & 31;
    if (w >= EE) return;
    int s = src[w], d = dst[w];
    int h = lane >> 3;
    float alpha = sc[(size_t)w * 4 + h] / (den[d * 4 + h] + 1e-16f);
    float4 v4 = *reinterpret_cast<const float4*>(qkv + (size_t)s * 384 + 256 + lane * 4);
    float4 e4 = *reinterpret_cast<const float4*>(ekv + (size_t)w * 256 + 128 + lane * 4);
    float* p = agg + (size_t)d * 128 + lane * 4;
    atomicAdd(p + 0, alpha * (v4.x + e4.x));
    atomicAdd(p + 1, alpha * (v4.y + e4.y));
    atomicAdd(p + 2, alpha * (v4.z + e4.z));
    atomicAdd(p + 3, alpha * (v4.w + e4.w));
}

__global__ void k_gnode(const float* __restrict__ feat, const int* __restrict__ ntype,
                        const int* __restrict__ batch, float* __restrict__ ga,
                        float* __restrict__ cn)
{
    unsigned t = blockIdx.x * blockDim.x + threadIdx.x;
    if (t >= (unsigned)NN * 32u) return;
    int n = t >> 5, q = t & 31;
    if (ntype[n] != 0) return;
    int b = batch[n];
    float4 f = *reinterpret_cast<const float4*>(feat + (size_t)n * 128 + q * 4);
    float* p = ga + (size_t)b * 256 + q * 4;
    atomicAdd(p + 0, f.x); atomicAdd(p + 1, f.y);
    atomicAdd(p + 2, f.z); atomicAdd(p + 3, f.w);
    if (q == 0) atomicAdd(&cn[b], 1.f);
}

__global__ void k_gedge(const float* __restrict__ e, const int* __restrict__ src,
                        const int* __restrict__ batch, float* __restrict__ ga,
                        float* __restrict__ ce)
{
    unsigned t = blockIdx.x * blockDim.x + threadIdx.x;
    if (t >= (unsigned)EE * 32u) return;
    int ed = t >> 5, q = t & 31;
    int b = batch[src[ed]];
    float4 f = *reinterpret_cast<const float4*>(e + (size_t)ed * 128 + q * 4);
    float* p = ga + (size_t)b * 256 + 128 + q * 4;
    atomicAdd(p + 0, f.x); atomicAdd(p + 1, f.y);
    atomicAdd(p + 2, f.z); atomicAdd(p + 3, f.w);
    if (q == 0) atomicAdd(&ce[b], 1.f);
}

__global__ void k_head(const float* __restrict__ ga, const float* __restrict__ cn,
                       const float* __restrict__ ce,
                       const float* __restrict__ QW1, const float* __restrict__ Qb1,
                       const float* __restrict__ QW2, const float* __restrict__ Qb2,
                       float* __restrict__ out)
{
    int g = blockIdx.x;
    int t = threadIdx.x;  // 128
    __shared__ float s_in[256];
    __shared__ float s_h[128];
    __shared__ float s_l[128];
    __shared__ float s_max, s_lse;
    float nc = fmaxf(cn[g], 1.0f);
    float ec = fmaxf(ce[g], 1.0f);
    s_in[t]       = ga[(size_t)g * 256 + t] / nc;
    s_in[t + 128] = ga[(size_t)g * 256 + 128 + t] / ec;
    __syncthreads();
    float acc = Qb1[t];
    for (int k = 0; k < 256; k++) acc = fmaf(s_in[k], QW1[(size_t)k * 128 + t], acc);
    s_h[t] = fmaxf(acc, 0.f);
    __syncthreads();
    float lg = 0.f;
    if (t < AA) {
        lg = Qb2[t];
        for (int k = 0; k < 128; k++) lg = fmaf(s_h[k], QW2[(size_t)k * AA + t], lg);
        s_l[t] = lg;
    }
    __syncthreads();
    if (t == 0) {
        float mx = -3.4e38f;
        for (int i = 0; i < AA; i++) mx = fmaxf(mx, s_l[i]);
        float s = 0.f;
        for (int i = 0; i < AA; i++) s += expf(s_l[i] - mx);
        s_max = mx;
        s_lse = logf(s);
    }
    __syncthreads();
    if (t < AA) out[(size_t)g * AA + t] = lg - s_max - s_lse;
}

// ---------------- launch ------------------------------------------------------
extern "C" void kernel_launch(void* const* d_in, const int* in_sizes, int n_in,
                              void* d_out, int out_size)
{
    const int* x     = (const int*)d_in[0];
    const int* ntype = (const int*)d_in[1];
    const int* batch = (const int*)d_in[2];
    const int* ei    = (const int*)d_in[3];
    const int* flow  = (const int*)d_in[4];
    const int* pos   = (const int*)d_in[5];
    const int* blk   = (const int*)d_in[6];
    int base = (in_sizes[7] == 8192 * 128) ? 7 : 8;
    const float* emb  = (const float*)d_in[base + 0];
    const float* femb = (const float*)d_in[base + 1];
    const float* pemb = (const float*)d_in[base + 2];
    const float* bemb = (const float*)d_in[base + 3];
    const float* Wq   = (const float*)d_in[base + 4];
    const float* Wk   = (const float*)d_in[base + 5];
    const float* Wv   = (const float*)d_in[base + 6];
    const float* Wek  = (const float*)d_in[base + 7];
    const float* Wev  = (const float*)d_in[base + 8];
    const float* Wo   = (const float*)d_in[base + 9];
    const float* Weu  = (const float*)d_in[base + 10];
    const float* QW1  = (const float*)d_in[base + 11];
    const float* Qb1  = (const float*)d_in[base + 12];
    const float* QW2  = (const float*)d_in[base + 13];
    const float* Qb2  = (const float*)d_in[base + 14];
    const int* src = ei;
    const int* dst = ei + EE;
    float* out = (float*)d_out;

    float *feat0, *feat1, *e0, *e1, *qkv, *ekv, *sc, *m, *den, *agg, *PQ;
    float *ga, *cn, *ce, *elut, *ekvlut;
    int* code;
    __nv_bfloat16* pack;
    cudaGetSymbolAddress((void**)&feat0, g_feat0);
    cudaGetSymbolAddress((void**)&feat1, g_feat1);
    cudaGetSymbolAddress((void**)&e0, g_e0);
    cudaGetSymbolAddress((void**)&e1, g_e1);
    cudaGetSymbolAddress((void**)&qkv, g_qkv);
    cudaGetSymbolAddress((void**)&ekv, g_ekv);
    cudaGetSymbolAddress((void**)&sc, g_sc);
    cudaGetSymbolAddress((void**)&m, g_m);
    cudaGetSymbolAddress((void**)&den, g_den);
    cudaGetSymbolAddress((void**)&agg, g_agg);
    cudaGetSymbolAddress((void**)&PQ, g_PQ);
    cudaGetSymbolAddress((void**)&ga, g_ga);
    cudaGetSymbolAddress((void**)&cn, g_cn);
    cudaGetSymbolAddress((void**)&ce, g_ce);
    cudaGetSymbolAddress((void**)&code, g_code);
    cudaGetSymbolAddress((void**)&elut, g_elut);
    cudaGetSymbolAddress((void**)&ekvlut, g_ekvlut);
    cudaGetSymbolAddress((void**)&pack, g_pack);

    const int SMT = 139264;   // 4 x 34816
    cudaFuncSetAttribute(mma_gemm<0>, cudaFuncAttributeMaxDynamicSharedMemorySize, SMT);
    cudaFuncSetAttribute(mma_gemm<1>, cudaFuncAttributeMaxDynamicSharedMemorySize, SMT);
    cudaFuncSetAttribute(mma_gemm<2>, cudaFuncAttributeMaxDynamicSharedMemorySize, SMT);

    const int TPB = 256;
    const int gN32 = (NN * 32 + TPB - 1) / TPB;
    const int gE32 = (EE * 32 + TPB - 1) / TPB;
    const int gE64 = (EE * 64 + TPB - 1) / TPB;
    const int GN = (NN + 127) / 128;
    const int GE = (EE + 127) / 128;

    // prologue
    k_packall<<<72, 256>>>(Wq, Wk, Wv, Wek, Wev, Wo, Weu, pack);
    k_node_embed<<<gN32, TPB>>>(x, emb, feat0);
    k_lut_e<<<1024, 128>>>(femb, pemb, bemb, elut);
    k_code<<<(EE + TPB - 1) / TPB, TPB>>>(flow, pos, blk, src, dst, code);
    k_expand_e<<<gE32, TPB>>>(code, elut, e0);
    // layer-0 ek/ev via LUT
    mma_gemm<0><<<8, 256, SMT>>>(elut, pack + (size_t)5 * 32768, ekvlut, 256, 0,
                                 nullptr, nullptr, nullptr, nullptr, 1024);
    mma_gemm<0><<<8, 256, SMT>>>(elut, pack + (size_t)6 * 32768, ekvlut, 256, 128,
                                 nullptr, nullptr, nullptr, nullptr, 1024);
    k_expand_ekv<<<gE64, TPB>>>(code, ekvlut, ekv);

    float* fc = feat0; float* fn = feat1;
    float* ec = e0;    float* en = e1;

    for (int l = 0; l < LL; l++) {
        const __nv_bfloat16* pb = pack + (size_t)l * 9 * 32768;

        mma_gemm<0><<<GN, 256, SMT>>>(fc, pb + (size_t)0 * 32768, qkv, 384, 0,
                                      nullptr, nullptr, nullptr, nullptr, NN);
        mma_gemm<0><<<GN, 256, SMT>>>(fc, pb + (size_t)1 * 32768, qkv, 384, 128,
                                      nullptr, nullptr, nullptr, nullptr, NN);
        mma_gemm<0><<<GN, 256, SMT>>>(fc, pb + (size_t)2 * 32768, qkv, 384, 256,
                                      nullptr, nullptr, nullptr, nullptr, NN);
        mma_gemm<0><<<GN, 256, SMT>>>(fc, pb + (size_t)3 * 32768, PQ, 256, 0,
                                      nullptr, nullptr, nullptr, nullptr, NN);
        mma_gemm<0><<<GN, 256, SMT>>>(fc, pb + (size_t)4 * 32768, PQ, 256, 128,
                                      nullptr, nullptr, nullptr, nullptr, NN);
        if (l > 0) {
            mma_gemm<0><<<GE, 256, SMT>>>(ec, pb + (size_t)5 * 32768, ekv, 256, 0,
                                          nullptr, nullptr, nullptr, nullptr, EE);
            mma_gemm<0><<<GE, 256, SMT>>>(ec, pb + (size_t)6 * 32768, ekv, 256, 128,
                                          nullptr, nullptr, nullptr, nullptr, EE);
        }

        k_fill<<<(NN * 4 + TPB - 1) / TPB, TPB>>>(m, NN * 4, -3.4e38f);
        cudaMemsetAsync(den, 0, (size_t)NN * 4 * sizeof(float));
        cudaMemsetAsync(agg, 0, (size_t)NN * 128 * sizeof(float));

        k_scores<<<gE32, TPB>>>(qkv, ekv, src, dst, sc, m);
        k_expden<<<(EE * 4 + TPB - 1) / TPB, TPB>>>(dst, sc, m, den);
        k_agg<<<gE32, TPB>>>(qkv, ekv, src, dst, sc, den, agg);

        // feat_new = relu(fc + agg@Wo)
        mma_gemm<1><<<GN, 256, SMT>>>(agg, pb + (size_t)7 * 32768, fn, 128, 0,
                                      fc, nullptr, nullptr, nullptr, NN);
        // e_new = relu(ec + ec@WeuE + P[src] + Q[dst])
        mma_gemm<2><<<GE, 256, SMT>>>(ec, pb + (size_t)8 * 32768, en, 128, 0,
                                      ec, PQ, src, dst, EE);

        float* tf = fc; fc = fn; fn = tf;
        float* te = ec; ec = en; en = te;
    }

    cudaMemsetAsync(ga, 0, (size_t)GG * 256 * sizeof(float));
    cudaMemsetAsync(cn, 0, GG * sizeof(float));
    cudaMemsetAsync(ce, 0, GG * sizeof(float));
    k_gnode<<<gN32, TPB>>>(fc, ntype, batch, ga, cn);
    k_gedge<<<gE32, TPB>>>(ec, src, batch, ga, ce);
    k_head<<<GG, 128>>>(ga, cn, ce, QW1, Qb1, QW2, Qb2, out);
}

// round 8
// speedup vs baseline: 1.5791x; 1.2539x over previous
#include <cuda_runtime.h>
#include <cuda_bf16.h>
#include <math.h>
#include <stdint.h>

#define NN 100000
#define EE 500000
#define DD 128
#define LL 8
#define GG 64
#define AA 100

// ---------------- scratch (static device arrays; no cudaMalloc) -------------
__device__ float g_feat0[(size_t)NN * DD];
__device__ float g_feat1[(size_t)NN * DD];
__device__ float g_e0[(size_t)EE * DD];
__device__ float g_e1[(size_t)EE * DD];
__device__ float g_qkv[(size_t)NN * 3 * DD];
__device__ float g_ekv[(size_t)EE * 2 * DD];
__device__ float g_sc[(size_t)EE * 4];
__device__ float g_m[NN * 4];
__device__ float g_den[NN * 4];
__device__ float g_agg[(size_t)NN * DD];
__device__ float g_PQ[(size_t)NN * 256];
__device__ float g_ga[GG * 256];
__device__ float g_cn[GG];
__device__ float g_ce[GG];
__device__ int   g_code[EE];
__device__ float g_elut[1024 * DD];
__device__ float g_ekvlut[1024 * 2 * DD];
// packed weights: 8 layers x 9 mats x (16384 hi + 16384 lo) bf16, [k][n] row-major
__device__ __nv_bfloat16 g_pack[(size_t)LL * 9 * 32768];

// ---------------- PTX helpers (baseline features only) ----------------------
__device__ __forceinline__ uint32_t smem_u32(const void* p) {
    return (uint32_t)__cvta_generic_to_shared(p);
}
__device__ __forceinline__ void cp_async16(uint32_t smem, const void* gmem) {
    asm volatile("cp.async.cg.shared.global [%0], [%1], 16;\n" :: "r"(smem), "l"(gmem));
}
__device__ __forceinline__ void cp_commit() { asm volatile("cp.async.commit_group;\n"); }
__device__ __forceinline__ void cp_wait0() { asm volatile("cp.async.wait_group 0;\n"); }
__device__ __forceinline__ void cp_wait1() { asm volatile("cp.async.wait_group 1;\n"); }

__device__ __forceinline__ void ldmx4(uint32_t* r, uint32_t addr) {
    asm volatile("ldmatrix.sync.aligned.m8n8.x4.shared.b16 {%0,%1,%2,%3}, [%4];"
                 : "=r"(r[0]), "=r"(r[1]), "=r"(r[2]), "=r"(r[3]) : "r"(addr));
}
__device__ __forceinline__ void ldmx4t(uint32_t* r, uint32_t addr) {
    asm volatile("ldmatrix.sync.aligned.m8n8.x4.trans.shared.b16 {%0,%1,%2,%3}, [%4];"
                 : "=r"(r[0]), "=r"(r[1]), "=r"(r[2]), "=r"(r[3]) : "r"(addr));
}
__device__ __forceinline__ void mma_bf16(float* c, const uint32_t* a, const uint32_t* b) {
    asm volatile("mma.sync.aligned.m16n8k16.row.col.f32.bf16.bf16.f32 "
                 "{%0,%1,%2,%3}, {%4,%5,%6,%7}, {%8,%9}, {%0,%1,%2,%3};"
                 : "+f"(c[0]), "+f"(c[1]), "+f"(c[2]), "+f"(c[3])
                 : "r"(a[0]), "r"(a[1]), "r"(a[2]), "r"(a[3]), "r"(b[0]), "r"(b[1]));
}

// ---------------- weight pack: split hi/lo bf16, keep [k][n] layout ---------
__global__ void k_packall(const float* __restrict__ Wq, const float* __restrict__ Wk,
                          const float* __restrict__ Wv, const float* __restrict__ Wek,
                          const float* __restrict__ Wev, const float* __restrict__ Wo,
                          const float* __restrict__ Weu, __nv_bfloat16* __restrict__ pack)
{
    int b = blockIdx.x;        // 72 = 8 layers * 9 mats
    int l = b / 9, mt = b % 9;
    const float* W;
    switch (mt) {
        case 0: W = Wq  + (size_t)l * 16384; break;
        case 1: W = Wk  + (size_t)l * 16384; break;
        case 2: W = Wv  + (size_t)l * 16384; break;
        case 3: W = Weu + (size_t)l * 49152; break;           // WeuS
        case 4: W = Weu + (size_t)l * 49152 + 16384; break;   // WeuD
        case 5: W = Wek + (size_t)l * 16384; break;
        case 6: W = Wev + (size_t)l * 16384; break;
        case 7: W = Wo  + (size_t)l * 16384; break;
        default: W = Weu + (size_t)l * 49152 + 32768; break;  // WeuE
    }
    __nv_bfloat16* dst = pack + (size_t)b * 32768;
    for (int idx = threadIdx.x; idx < 16384; idx += blockDim.x) {
        float a = W[idx];
        __nv_bfloat16 h = __float2bfloat16(a);
        __nv_bfloat16 lo = __float2bfloat16(a - __bfloat162float(h));
        dst[idx] = h;
        dst[16384 + idx] = lo;
    }
}

// ---------------- multi-matrix tensor-core GEMM (bf16x3 split) --------------
// For j in [0,NB): C_j[M, co_j:co_j+128] = A[M,128] @ B_j     (B_j = Bp + j*32768)
// MODE 0: plain.  MODE 1: C = relu(R + C).
// MODE 2: C = relu(A + C + P[src] + Q[dst])   (residual = A reconstructed from smem)
// smem: Ah | Al (34816 each) | B double buffer (2 x 69632: Bh|Bl padded)
struct Outs { float* C[5]; int ldc[5]; int co[5]; };

template<int MODE, int NB>
__global__ void __launch_bounds__(256, 1) mma_gemm(
    const float* __restrict__ A, const __nv_bfloat16* __restrict__ Bp, Outs outs,
    const float* __restrict__ R, const float* __restrict__ PQ,
    const int* __restrict__ src, const int* __restrict__ dst, int M)
{
    extern __shared__ char smem[];
    const uint32_t sb = smem_u32(smem);
    const int tid = threadIdx.x;
    const int lane = tid & 31, wid = tid >> 5;
    const int wm = wid & 3, wn = wid >> 2;     // 4x2 warp grid
    const int m0 = blockIdx.x * 128;
    const int PS = 272;                        // padded row stride (bytes)
    const uint32_t OFF_AH = 0, OFF_AL = 34816;
    const uint32_t OFF_B0 = 69632, BUFSZ = 69632;   // per-buf: Bh | Bl (34816 each)

    // prefetch B0 into buf 0
    for (int idx = tid; idx < 4096; idx += 256) {
        int hl = idx >> 11, rem = idx & 2047, r = rem >> 4, c = rem & 15;
        cp_async16(sb + OFF_B0 + hl * 34816 + r * PS + c * 16,
                   (const char*)Bp + hl * 32768 + r * 256 + c * 16);
    }
    cp_commit();

    // A: load fp32, split bf16 hi/lo, store padded
    for (int idx = tid; idx < 4096; idx += 256) {
        int r = idx >> 5, f4 = idx & 31;
        int rg = m0 + r; if (rg >= M) rg = M - 1;
        float4 v = *reinterpret_cast<const float4*>(A + (size_t)rg * 128 + f4 * 4);
        __nv_bfloat16 hx = __float2bfloat16(v.x), hy = __float2bfloat16(v.y);
        __nv_bfloat16 hz = __float2bfloat16(v.z), hw = __float2bfloat16(v.w);
        __nv_bfloat16 lx = __float2bfloat16(v.x - __bfloat162float(hx));
        __nv_bfloat16 ly = __float2bfloat16(v.y - __bfloat162float(hy));
        __nv_bfloat16 lz = __float2bfloat16(v.z - __bfloat162float(hz));
        __nv_bfloat16 lw = __float2bfloat16(v.w - __bfloat162float(hw));
        __nv_bfloat162 h01 = __halves2bfloat162(hx, hy), h23 = __halves2bfloat162(hz, hw);
        __nv_bfloat162 l01 = __halves2bfloat162(lx, ly), l23 = __halves2bfloat162(lz, lw);
        int off = r * PS + f4 * 8;
        *reinterpret_cast<uint2*>(smem + OFF_AH + off) =
            make_uint2(*(uint32_t*)&h01, *(uint32_t*)&h23);
        *reinterpret_cast<uint2*>(smem + OFF_AL + off) =
            make_uint2(*(uint32_t*)&l01, *(uint32_t*)&l23);
    }

#pragma unroll
    for (int j = 0; j < NB; j++) {
        // prefetch next B while computing current
        if (j + 1 < NB) {
            const uint32_t dstb = sb + OFF_B0 + ((j + 1) & 1) * BUFSZ;
            const char* srcb = (const char*)Bp + (size_t)(j + 1) * 65536;
            for (int idx = tid; idx < 4096; idx += 256) {
                int hl = idx >> 11, rem = idx & 2047, r = rem >> 4, c = rem & 15;
                cp_async16(dstb + hl * 34816 + r * PS + c * 16,
                           srcb + hl * 32768 + r * 256 + c * 16);
            }
            cp_commit();
            cp_wait1();
        } else {
            cp_wait0();
        }
        __syncthreads();

        float acc[2][8][4];
#pragma unroll
        for (int i = 0; i < 2; i++)
#pragma unroll
            for (int n = 0; n < 8; n++)
#pragma unroll
                for (int q = 0; q < 4; q++) acc[i][n][q] = 0.f;

        const uint32_t Bbuf = sb + OFF_B0 + (j & 1) * BUFSZ;
        // 3 split terms: (Ah,Bh), (Ah,Bl), (Al,Bh)
#pragma unroll
        for (int term = 0; term < 3; term++) {
            const uint32_t Ab = sb + (term == 2 ? OFF_AL : OFF_AH);
            const uint32_t Bb = Bbuf + (term == 1 ? 34816 : 0);
            const uint32_t aBase = Ab + (wm * 32 + (lane & 15)) * PS + (lane >> 4) * 16;
            // ldmatrix.x4.trans: group g of 8 lanes -> 8x8 tile
            // reg0=(k0-7,nP0) reg1=(k8-15,nP0) reg2=(k0-7,nP1) reg3=(k8-15,nP1)
            const int bg = lane >> 3, br = lane & 7;
            const uint32_t bBase = Bb + ((bg & 1) * 8 + br) * PS + wn * 128 + (bg >> 1) * 16;
#pragma unroll
            for (int ks = 0; ks < 8; ks++) {
                uint32_t a0[4], a1[4], bf[8][2];
                ldmx4(a0, aBase + ks * 32);
                ldmx4(a1, aBase + 16 * PS + ks * 32);
#pragma unroll
                for (int p = 0; p < 4; p++) {
                    uint32_t t4[4];
                    ldmx4t(t4, bBase + ks * 16 * PS + p * 32);
                    bf[2 * p][0] = t4[0]; bf[2 * p][1] = t4[1];
                    bf[2 * p + 1][0] = t4[2]; bf[2 * p + 1][1] = t4[3];
                }
#pragma unroll
                for (int nt = 0; nt < 8; nt++) {
                    mma_bf16(acc[0][nt], a0, bf[nt]);
                    mma_bf16(acc[1][nt], a1, bf[nt]);
                }
            }
        }

        // epilogue
        float* C = outs.C[j];
        const int ldc = outs.ldc[j], co = outs.co[j];
#pragma unroll
        for (int mt = 0; mt < 2; mt++) {
#pragma unroll
            for (int h = 0; h < 2; h++) {
                int rl = wm * 32 + mt * 16 + (lane >> 2) + h * 8;
                int row = m0 + rl;
                if (row >= M) continue;
                int s = 0, d = 0;
                if (MODE == 2) { s = src[row]; d = dst[row]; }
#pragma unroll
                for (int nt = 0; nt < 8; nt++) {
                    int col = wn * 64 + nt * 8 + (lane & 3) * 2;
                    float vx = acc[mt][nt][h * 2], vy = acc[mt][nt][h * 2 + 1];
                    if (MODE == 1) {
                        float2 rv = *reinterpret_cast<const float2*>(R + (size_t)row * 128 + col);
                        vx += rv.x; vy += rv.y;
                    }
                    if (MODE == 2) {
                        // residual = A row reconstructed from smem split (hi+lo)
                        int aoff = rl * PS + col * 2;
                        __nv_bfloat162 hh = *reinterpret_cast<__nv_bfloat162*>(smem + OFF_AH + aoff);
                        __nv_bfloat162 ll = *reinterpret_cast<__nv_bfloat162*>(smem + OFF_AL + aoff);
                        vx += __bfloat162float(hh.x) + __bfloat162float(ll.x);
                        vy += __bfloat162float(hh.y) + __bfloat162float(ll.y);
                        float2 pv = *reinterpret_cast<const float2*>(PQ + (size_t)s * 256 + col);
                        float2 qv = *reinterpret_cast<const float2*>(PQ + (size_t)d * 256 + 128 + col);
                        vx += pv.x + qv.x; vy += pv.y + qv.y;
                    }
                    if (MODE >= 1) { vx = fmaxf(vx, 0.f); vy = fmaxf(vy, 0.f); }
                    *reinterpret_cast<float2*>(C + (size_t)row * ldc + co + col) =
                        make_float2(vx, vy);
                }
            }
        }
        __syncthreads();   // protect B buffer reuse across iterations
    }
}

// ---------------- misc elementwise kernels ----------------------------------
__device__ __forceinline__ void atomicMaxF(float* addr, float v) {
    if (v >= 0.f) atomicMax((int*)addr, __float_as_int(v));
    else          atomicMin((unsigned int*)addr, __float_as_uint(v));
}

__global__ void k_fill(float* p, int n, float v) {
    int i = blockIdx.x * blockDim.x + threadIdx.x;
    if (i < n) p[i] = v;
}

__global__ void k_node_embed(const int* __restrict__ x, const float* __restrict__ emb,
                             float* __restrict__ feat) {
    unsigned t = blockIdx.x * blockDim.x + threadIdx.x;
    if (t >= (unsigned)NN * 32u) return;
    int n = t >> 5, q = t & 31;
    float4 v = *reinterpret_cast<const float4*>(emb + (size_t)x[n] * 128 + q * 4);
    *reinterpret_cast<float4*>(feat + (size_t)n * 128 + q * 4) = v;
}

__global__ void k_lut_e(const float* __restrict__ femb, const float* __restrict__ pemb,
                        const float* __restrict__ bemb, float* __restrict__ elut) {
    int c = blockIdx.x, t = threadIdx.x;
    elut[c * 128 + t] = femb[(c >> 7) * 128 + t] + pemb[((c >> 1) & 63) * 128 + t] +
                        bemb[(c & 1) * 128 + t];
}

__global__ void k_code(const int* __restrict__ flow, const int* __restrict__ pos,
                       const int* __restrict__ blk, const int* __restrict__ src,
                       const int* __restrict__ dst, int* __restrict__ code) {
    int e = blockIdx.x * blockDim.x + threadIdx.x;
    if (e >= EE) return;
    int cr = (blk[src[e]] != blk[dst[e]]) ? 1 : 0;
    code[e] = (flow[e] << 7) | (pos[e] << 1) | cr;
}

__global__ void k_expand_e(const int* __restrict__ code, const float* __restrict__ elut,
                           float* __restrict__ e) {
    unsigned t = blockIdx.x * blockDim.x + threadIdx.x;
    if (t >= (unsigned)EE * 32u) return;
    int ed = t >> 5, q = t & 31;
    float4 v = *reinterpret_cast<const float4*>(elut + (size_t)code[ed] * 128 + q * 4);
    *reinterpret_cast<float4*>(e + (size_t)ed * 128 + q * 4) = v;
}

__global__ void k_expand_ekv(const int* __restrict__ code, const float* __restrict__ lut,
                             float* __restrict__ ekv) {
    unsigned t = blockIdx.x * blockDim.x + threadIdx.x;
    if (t >= (unsigned)EE * 64u) return;
    int ed = t >> 6, q = t & 63;
    float4 v = *reinterpret_cast<const float4*>(lut + (size_t)code[ed] * 256 + q * 4);
    *reinterpret_cast<float4*>(ekv + (size_t)ed * 256 + q * 4) = v;
}

__global__ void k_scores(const float* __restrict__ qkv, const float* __restrict__ ekv,
                         const int* __restrict__ src, const int* __restrict__ dst,
                         float* __restrict__ sc, float* __restrict__ m)
{
    unsigned t = blockIdx.x * blockDim.x + threadIdx.x;
    int w = t >> 5;
    int lane = threadIdx.x & 31;
    if (w >= EE) return;
    int s = src[w], d = dst[w];
    float4 q4 = *reinterpret_cast<const float4*>(qkv + (size_t)d * 384 + lane * 4);
    float4 k4 = *reinterpret_cast<const float4*>(qkv + (size_t)s * 384 + 128 + lane * 4);
    float4 e4 = *reinterpret_cast<const float4*>(ekv + (size_t)w * 256 + lane * 4);
    float p = q4.x * (k4.x + e4.x) + q4.y * (k4.y + e4.y) +
              q4.z * (k4.z + e4.z) + q4.w * (k4.w + e4.w);
    p += __shfl_xor_sync(0xffffffffu, p, 4);
    p += __shfl_xor_sync(0xffffffffu, p, 2);
    p += __shfl_xor_sync(0xffffffffu, p, 1);
    if ((lane & 7) == 0) {
        int h = lane >> 3;
        float v = p * 0.17677669529663687f;
        sc[(size_t)w * 4 + h] = v;
        atomicMaxF(&m[d * 4 + h], v);
    }
}

__global__ void k_expden(const int* __restrict__ dst, float* __restrict__ sc,
                         const float* __restrict__ m, float* __restrict__ den)
{
    unsigned i = blockIdx.x * blockDim.x + threadIdx.x;
    if (i >= (unsigned)EE * 4u) return;
    int e = i >> 2, h = i & 3;
    int d = dst[e];
    float ex = __expf(sc[i] - m[d * 4 + h]);
    sc[i] = ex;
    atomicAdd(&den[d * 4 + h], ex);
}

__global__ void k_agg(const float* __restrict__ qkv, const float* __restrict__ ekv,
                      const int* __restrict__ src, const int* __restrict__ dst,
                      const float* __restrict__ sc, const float* __restrict__ den,
                      float* __restrict__ agg)
{
    unsigned t = blockIdx.x * blockDim.x + threadIdx.x;
    int w = t >> 5;
    int lane = threadIdx.x & 31;
    if (w >= EE) return;
    int s = src[w], d = dst[w];
    int h = lane >> 3;
    float alpha = sc[(size_t)w * 4 + h] / (den[d * 4 + h] + 1e-16f);
    float4 v4 = *reinterpret_cast<const float4*>(qkv + (size_t)s * 384 + 256 + lane * 4);
    float4 e4 = *reinterpret_cast<const float4*>(ekv + (size_t)w * 256 + 128 + lane * 4);
    float* p = agg + (size_t)d * 128 + lane * 4;
    atomicAdd(p + 0, alpha * (v4.x + e4.x));
    atomicAdd(p + 1, alpha * (v4.y + e4.y));
    atomicAdd(p + 2, alpha * (v4.z + e4.z));
    atomicAdd(p + 3, alpha * (v4.w + e4.w));
}

__global__ void k_gnode(const float* __restrict__ feat, const int* __restrict__ ntype,
                        const int* __restrict__ batch, float* __restrict__ ga,
                        float* __restrict__ cn)
{
    unsigned t = blockIdx.x * blockDim.x + threadIdx.x;
    if (t >= (unsigned)NN * 32u) return;
    int n = t >> 5, q = t & 31;
    if (ntype[n] != 0) return;
    int b = batch[n];
    float4 f = *reinterpret_cast<const float4*>(feat + (size_t)n * 128 + q * 4);
    float* p = ga + (size_t)b * 256 + q * 4;
    atomicAdd(p + 0, f.x); atomicAdd(p + 1, f.y);
    atomicAdd(p + 2, f.z); atomicAdd(p + 3, f.w);
    if (q == 0) atomicAdd(&cn[b], 1.f);
}

__global__ void k_gedge(const float* __restrict__ e, const int* __restrict__ src,
                        const int* __restrict__ batch, float* __restrict__ ga,
                        float* __restrict__ ce)
{
    unsigned t = blockIdx.x * blockDim.x + threadIdx.x;
    if (t >= (unsigned)EE * 32u) return;
    int ed = t >> 5, q = t & 31;
    int b = batch[src[ed]];
    float4 f = *reinterpret_cast<const float4*>(e + (size_t)ed * 128 + q * 4);
    float* p = ga + (size_t)b * 256 + 128 + q * 4;
    atomicAdd(p + 0, f.x); atomicAdd(p + 1, f.y);
    atomicAdd(p + 2, f.z); atomicAdd(p + 3, f.w);
    if (q == 0) atomicAdd(&ce[b], 1.f);
}

__global__ void k_head(const float* __restrict__ ga, const float* __restrict__ cn,
                       const float* __restrict__ ce,
                       const float* __restrict__ QW1, const float* __restrict__ Qb1,
                       const float* __restrict__ QW2, const float* __restrict__ Qb2,
                       float* __restrict__ out)
{
    int g = blockIdx.x;
    int t = threadIdx.x;  // 128
    __shared__ float s_in[256];
    __shared__ float s_h[128];
    __shared__ float s_l[128];
    __shared__ float s_max, s_lse;
    float nc = fmaxf(cn[g], 1.0f);
    float ec = fmaxf(ce[g], 1.0f);
    s_in[t]       = ga[(size_t)g * 256 + t] / nc;
    s_in[t + 128] = ga[(size_t)g * 256 + 128 + t] / ec;
    __syncthreads();
    float acc = Qb1[t];
    for (int k = 0; k < 256; k++) acc = fmaf(s_in[k], QW1[(size_t)k * 128 + t], acc);
    s_h[t] = fmaxf(acc, 0.f);
    __syncthreads();
    float lg = 0.f;
    if (t < AA) {
        lg = Qb2[t];
        for (int k = 0; k < 128; k++) lg = fmaf(s_h[k], QW2[(size_t)k * AA + t], lg);
        s_l[t] = lg;
    }
    __syncthreads();
    if (t == 0) {
        float mx = -3.4e38f;
        for (int i = 0; i < AA; i++) mx = fmaxf(mx, s_l[i]);
        float s = 0.f;
        for (int i = 0; i < AA; i++) s += expf(s_l[i] - mx);
        s_max = mx;
        s_lse = logf(s);
    }
    __syncthreads();
    if (t < AA) out[(size_t)g * AA + t] = lg - s_max - s_lse;
}

// ---------------- launch ------------------------------------------------------
extern "C" void kernel_launch(void* const* d_in, const int* in_sizes, int n_in,
                              void* d_out, int out_size)
{
    const int* x     = (const int*)d_in[0];
    const int* ntype = (const int*)d_in[1];
    const int* batch = (const int*)d_in[2];
    const int* ei    = (const int*)d_in[3];
    const int* flow  = (const int*)d_in[4];
    const int* pos   = (const int*)d_in[5];
    const int* blk   = (const int*)d_in[6];
    int base = (in_sizes[7] == 8192 * 128) ? 7 : 8;
    const float* emb  = (const float*)d_in[base + 0];
    const float* femb = (const float*)d_in[base + 1];
    const float* pemb = (const float*)d_in[base + 2];
    const float* bemb = (const float*)d_in[base + 3];
    const float* Wq   = (const float*)d_in[base + 4];
    const float* Wk   = (const float*)d_in[base + 5];
    const float* Wv   = (const float*)d_in[base + 6];
    const float* Wek  = (const float*)d_in[base + 7];
    const float* Wev  = (const float*)d_in[base + 8];
    const float* Wo   = (const float*)d_in[base + 9];
    const float* Weu  = (const float*)d_in[base + 10];
    const float* QW1  = (const float*)d_in[base + 11];
    const float* Qb1  = (const float*)d_in[base + 12];
    const float* QW2  = (const float*)d_in[base + 13];
    const float* Qb2  = (const float*)d_in[base + 14];
    const int* src = ei;
    const int* dst = ei + EE;
    float* out = (float*)d_out;

    float *feat0, *feat1, *e0, *e1, *qkv, *ekv, *sc, *m, *den, *agg, *PQ;
    float *ga, *cn, *ce, *elut, *ekvlut;
    int* code;
    __nv_bfloat16* pack;
    cudaGetSymbolAddress((void**)&feat0, g_feat0);
    cudaGetSymbolAddress((void**)&feat1, g_feat1);
    cudaGetSymbolAddress((void**)&e0, g_e0);
    cudaGetSymbolAddress((void**)&e1, g_e1);
    cudaGetSymbolAddress((void**)&qkv, g_qkv);
    cudaGetSymbolAddress((void**)&ekv, g_ekv);
    cudaGetSymbolAddress((void**)&sc, g_sc);
    cudaGetSymbolAddress((void**)&m, g_m);
    cudaGetSymbolAddress((void**)&den, g_den);
    cudaGetSymbolAddress((void**)&agg, g_agg);
    cudaGetSymbolAddress((void**)&PQ, g_PQ);
    cudaGetSymbolAddress((void**)&ga, g_ga);
    cudaGetSymbolAddress((void**)&cn, g_cn);
    cudaGetSymbolAddress((void**)&ce, g_ce);
    cudaGetSymbolAddress((void**)&code, g_code);
    cudaGetSymbolAddress((void**)&elut, g_elut);
    cudaGetSymbolAddress((void**)&ekvlut, g_ekvlut);
    cudaGetSymbolAddress((void**)&pack, g_pack);

    const int SMT1 = 69632 + 69632;        // NB=1: A + 1 buf
    const int SMT2 = 69632 + 2 * 69632;    // NB>=2: A + 2 bufs (208896)
    cudaFuncSetAttribute(mma_gemm<0, 5>, cudaFuncAttributeMaxDynamicSharedMemorySize, SMT2);
    cudaFuncSetAttribute(mma_gemm<0, 2>, cudaFuncAttributeMaxDynamicSharedMemorySize, SMT2);
    cudaFuncSetAttribute(mma_gemm<1, 1>, cudaFuncAttributeMaxDynamicSharedMemorySize, SMT1);
    cudaFuncSetAttribute(mma_gemm<2, 1>, cudaFuncAttributeMaxDynamicSharedMemorySize, SMT1);

    const int TPB = 256;
    const int gN32 = (NN * 32 + TPB - 1) / TPB;
    const int gE32 = (EE * 32 + TPB - 1) / TPB;
    const int gE64 = (EE * 64 + TPB - 1) / TPB;
    const int GN = (NN + 127) / 128;
    const int GE = (EE + 127) / 128;

    // prologue
    k_packall<<<72, 256>>>(Wq, Wk, Wv, Wek, Wev, Wo, Weu, pack);
    k_node_embed<<<gN32, TPB>>>(x, emb, feat0);
    k_lut_e<<<1024, 128>>>(femb, pemb, bemb, elut);
    k_code<<<(EE + TPB - 1) / TPB, TPB>>>(flow, pos, blk, src, dst, code);
    k_expand_e<<<gE32, TPB>>>(code, elut, e0);
    // layer-0 ek/ev via LUT (Wek0, Wev0 are consecutive in pack at mt=5,6)
    {
        Outs o{}; o.C[0] = ekvlut; o.ldc[0] = 256; o.co[0] = 0;
        o.C[1] = ekvlut; o.ldc[1] = 256; o.co[1] = 128;
        mma_gemm<0, 2><<<8, 256, SMT2>>>(elut, pack + (size_t)5 * 32768, o,
                                         nullptr, nullptr, nullptr, nullptr, 1024);
    }
    k_expand_ekv<<<gE64, TPB>>>(code, ekvlut, ekv);

    float* fc = feat0; float* fn = feat1;
    float* ec = e0;    float* en = e1;

    for (int l = 0; l < LL; l++) {
        const __nv_bfloat16* pb = pack + (size_t)l * 9 * 32768;

        // q,k,v,P,Q from fc in ONE kernel (Wq,Wk,Wv,WeuS,WeuD consecutive)
        {
            Outs o{};
            o.C[0] = qkv; o.ldc[0] = 384; o.co[0] = 0;
            o.C[1] = qkv; o.ldc[1] = 384; o.co[1] = 128;
            o.C[2] = qkv; o.ldc[2] = 384; o.co[2] = 256;
            o.C[3] = PQ;  o.ldc[3] = 256; o.co[3] = 0;
            o.C[4] = PQ;  o.ldc[4] = 256; o.co[4] = 128;
            mma_gemm<0, 5><<<GN, 256, SMT2>>>(fc, pb, o, nullptr, nullptr,
                                              nullptr, nullptr, NN);
        }
        // ek, ev from ec in ONE kernel (layer 0 comes from LUT)
        if (l > 0) {
            Outs o{};
            o.C[0] = ekv; o.ldc[0] = 256; o.co[0] = 0;
            o.C[1] = ekv; o.ldc[1] = 256; o.co[1] = 128;
            mma_gemm<0, 2><<<GE, 256, SMT2>>>(ec, pb + (size_t)5 * 32768, o,
                                              nullptr, nullptr, nullptr, nullptr, EE);
        }

        k_fill<<<(NN * 4 + TPB - 1) / TPB, TPB>>>(m, NN * 4, -3.4e38f);
        cudaMemsetAsync(den, 0, (size_t)NN * 4 * sizeof(float));
        cudaMemsetAsync(agg, 0, (size_t)NN * 128 * sizeof(float));

        k_scores<<<gE32, TPB>>>(qkv, ekv, src, dst, sc, m);
        k_expden<<<(EE * 4 + TPB - 1) / TPB, TPB>>>(dst, sc, m, den);
        k_agg<<<gE32, TPB>>>(qkv, ekv, src, dst, sc, den, agg);

        // feat_new = relu(fc + agg@Wo)
        {
            Outs o{}; o.C[0] = fn; o.ldc[0] = 128; o.co[0] = 0;
            mma_gemm<1, 1><<<GN, 256, SMT1>>>(agg, pb + (size_t)7 * 32768, o,
                                              fc, nullptr, nullptr, nullptr, NN);
        }
        // e_new = relu(ec + ec@WeuE + P[src] + Q[dst])  (residual from smem)
        {
            Outs o{}; o.C[0] = en; o.ldc[0] = 128; o.co[0] = 0;
            mma_gemm<2, 1><<<GE, 256, SMT1>>>(ec, pb + (size_t)8 * 32768, o,
                                              nullptr, PQ, src, dst, EE);
        }

        float* tf = fc; fc = fn; fn = tf;
        float* te = ec; ec = en; en = te;
    }

    cudaMemsetAsync(ga, 0, (size_t)GG * 256 * sizeof(float));
    cudaMemsetAsync(cn, 0, GG * sizeof(float));
    cudaMemsetAsync(ce, 0, GG * sizeof(float));
    k_gnode<<<gN32, TPB>>>(fc, ntype, batch, ga, cn);
    k_gedge<<<gE32, TPB>>>(ec, src, batch, ga, ce);
    k_head<<<GG, 128>>>(ga, cn, ce, QW1, Qb1, QW2, Qb2, out);
}

// round 9
// speedup vs baseline: 1.8061x; 1.1438x over previous
#include <cuda_runtime.h>
#include <cuda_bf16.h>
#include <cuda_fp16.h>
#include <math.h>
#include <stdint.h>

#define NN 100000
#define EE 500000
#define DD 128
#define LL 8
#define GG 64
#define AA 100

// ---------------- scratch (static device arrays; no cudaMalloc) -------------
__device__ float  g_feat0[(size_t)NN * DD];
__device__ float  g_feat1[(size_t)NN * DD];
__device__ float  g_e0[(size_t)EE * DD];
__device__ float  g_e1[(size_t)EE * DD];
__device__ float  g_qkv[(size_t)NN * 3 * DD];
__device__ __half g_ekv[(size_t)EE * 2 * DD];
__device__ float  g_sc[(size_t)EE * 4];
__device__ float  g_m[NN * 4];
__device__ float  g_den[NN * 4];
__device__ float  g_agg[(size_t)NN * DD];
__device__ float  g_PQ[(size_t)NN * 256];
__device__ float  g_ga[GG * 256];
__device__ float  g_cn[GG];
__device__ float  g_ce[GG];
__device__ int    g_code[EE];
__device__ float  g_elut[1024 * DD];
// packed weights: 8 layers x 9 mats x (16384 hi + 16384 lo) bf16, [k][n] row-major
// mat order: Wq,Wk,Wv,WeuS,WeuD,Wek,Wev,WeuE,Wo
__device__ __nv_bfloat16 g_pack[(size_t)LL * 9 * 32768];

// ---------------- PTX helpers (baseline features only) ----------------------
__device__ __forceinline__ uint32_t smem_u32(const void* p) {
    return (uint32_t)__cvta_generic_to_shared(p);
}
__device__ __forceinline__ void cp_async16(uint32_t smem, const void* gmem) {
    asm volatile("cp.async.cg.shared.global [%0], [%1], 16;\n" :: "r"(smem), "l"(gmem));
}
__device__ __forceinline__ void cp_commit() { asm volatile("cp.async.commit_group;\n"); }
__device__ __forceinline__ void cp_wait0() { asm volatile("cp.async.wait_group 0;\n"); }
__device__ __forceinline__ void cp_wait1() { asm volatile("cp.async.wait_group 1;\n"); }

__device__ __forceinline__ void ldmx4(uint32_t* r, uint32_t addr) {
    asm volatile("ldmatrix.sync.aligned.m8n8.x4.shared.b16 {%0,%1,%2,%3}, [%4];"
                 : "=r"(r[0]), "=r"(r[1]), "=r"(r[2]), "=r"(r[3]) : "r"(addr));
}
__device__ __forceinline__ void ldmx4t(uint32_t* r, uint32_t addr) {
    asm volatile("ldmatrix.sync.aligned.m8n8.x4.trans.shared.b16 {%0,%1,%2,%3}, [%4];"
                 : "=r"(r[0]), "=r"(r[1]), "=r"(r[2]), "=r"(r[3]) : "r"(addr));
}
__device__ __forceinline__ void mma_bf16(float* c, const uint32_t* a, const uint32_t* b) {
    asm volatile("mma.sync.aligned.m16n8k16.row.col.f32.bf16.bf16.f32 "
                 "{%0,%1,%2,%3}, {%4,%5,%6,%7}, {%8,%9}, {%0,%1,%2,%3};"
                 : "+f"(c[0]), "+f"(c[1]), "+f"(c[2]), "+f"(c[3])
                 : "r"(a[0]), "r"(a[1]), "r"(a[2]), "r"(a[3]), "r"(b[0]), "r"(b[1]));
}

// ---------------- weight pack: split hi/lo bf16, keep [k][n] layout ---------
__global__ void k_packall(const float* __restrict__ Wq, const float* __restrict__ Wk,
                          const float* __restrict__ Wv, const float* __restrict__ Wek,
                          const float* __restrict__ Wev, const float* __restrict__ Wo,
                          const float* __restrict__ Weu, __nv_bfloat16* __restrict__ pack)
{
    int b = blockIdx.x;        // 72 = 8 layers * 9 mats
    int l = b / 9, mt = b % 9;
    const float* W;
    switch (mt) {
        case 0: W = Wq  + (size_t)l * 16384; break;
        case 1: W = Wk  + (size_t)l * 16384; break;
        case 2: W = Wv  + (size_t)l * 16384; break;
        case 3: W = Weu + (size_t)l * 49152; break;           // WeuS
        case 4: W = Weu + (size_t)l * 49152 + 16384; break;   // WeuD
        case 5: W = Wek + (size_t)l * 16384; break;
        case 6: W = Wev + (size_t)l * 16384; break;
        case 7: W = Weu + (size_t)l * 49152 + 32768; break;   // WeuE
        default: W = Wo + (size_t)l * 16384; break;           // Wo
    }
    __nv_bfloat16* dst = pack + (size_t)b * 32768;
    for (int idx = threadIdx.x; idx < 16384; idx += blockDim.x) {
        float a = W[idx];
        __nv_bfloat16 h = __float2bfloat16(a);
        __nv_bfloat16 lo = __float2bfloat16(a - __bfloat162float(h));
        dst[idx] = h;
        dst[16384 + idx] = lo;
    }
}

// ---------------- multi-matrix tensor-core GEMM (bf16x3 split) --------------
// KIND 0: node pass, NB=5 fp32 outs via Outs (qkv x3, PQ x2)
// KIND 1: Wo pass, NB=1: C = relu(R + (A/den)@B); den divide folded into A load
// KIND 2: edge pass, NB=3: j<2 -> half out to HO (ekv); j==2 ->
//         en = relu(A + C + P[src] + Q[dst]) fp32 (A residual from smem split)
struct Outs { float* C[5]; int ldc[5]; int co[5]; };

template<int KIND>
__global__ void __launch_bounds__(256, 1) mma_gemm(
    const float* __restrict__ A, const __nv_bfloat16* __restrict__ Bp, Outs outs,
    __half* __restrict__ HO, const float* __restrict__ R, const float* __restrict__ PQ,
    const int* __restrict__ src, const int* __restrict__ dst,
    const float* __restrict__ den, int M)
{
    constexpr int NB = (KIND == 0) ? 5 : (KIND == 2) ? 3 : 1;
    extern __shared__ char smem[];
    const uint32_t sb = smem_u32(smem);
    const int tid = threadIdx.x;
    const int lane = tid & 31, wid = tid >> 5;
    const int wm = wid & 3, wn = wid >> 2;     // 4x2 warp grid
    const int m0 = blockIdx.x * 128;
    const int PS = 272;                        // padded row stride (bytes)
    const uint32_t OFF_AH = 0, OFF_AL = 34816;
    const uint32_t OFF_B0 = 69632, BUFSZ = 69632;   // per-buf: Bh | Bl

    // prefetch B0 into buf 0
    for (int idx = tid; idx < 4096; idx += 256) {
        int hl = idx >> 11, rem = idx & 2047, r = rem >> 4, c = rem & 15;
        cp_async16(sb + OFF_B0 + hl * 34816 + r * PS + c * 16,
                   (const char*)Bp + hl * 32768 + r * 256 + c * 16);
    }
    cp_commit();

    // A: load fp32 (optionally / den per head block), split bf16 hi/lo
    for (int idx = tid; idx < 4096; idx += 256) {
        int r = idx >> 5, f4 = idx & 31;
        int rg = m0 + r; if (rg >= M) rg = M - 1;
        float4 v = *reinterpret_cast<const float4*>(A + (size_t)rg * 128 + f4 * 4);
        if (KIND == 1) {
            float dd = den[(size_t)rg * 4 + (f4 >> 3)];
            float inv = (dd > 0.f) ? 1.f / dd : 0.f;
            v.x *= inv; v.y *= inv; v.z *= inv; v.w *= inv;
        }
        __nv_bfloat16 hx = __float2bfloat16(v.x), hy = __float2bfloat16(v.y);
        __nv_bfloat16 hz = __float2bfloat16(v.z), hw = __float2bfloat16(v.w);
        __nv_bfloat16 lx = __float2bfloat16(v.x - __bfloat162float(hx));
        __nv_bfloat16 ly = __float2bfloat16(v.y - __bfloat162float(hy));
        __nv_bfloat16 lz = __float2bfloat16(v.z - __bfloat162float(hz));
        __nv_bfloat16 lw = __float2bfloat16(v.w - __bfloat162float(hw));
        __nv_bfloat162 h01 = __halves2bfloat162(hx, hy), h23 = __halves2bfloat162(hz, hw);
        __nv_bfloat162 l01 = __halves2bfloat162(lx, ly), l23 = __halves2bfloat162(lz, lw);
        int off = r * PS + f4 * 8;
        *reinterpret_cast<uint2*>(smem + OFF_AH + off) =
            make_uint2(*(uint32_t*)&h01, *(uint32_t*)&h23);
        *reinterpret_cast<uint2*>(smem + OFF_AL + off) =
            make_uint2(*(uint32_t*)&l01, *(uint32_t*)&l23);
    }

#pragma unroll
    for (int j = 0; j < NB; j++) {
        if (j + 1 < NB) {
            const uint32_t dstb = sb + OFF_B0 + ((j + 1) & 1) * BUFSZ;
            const char* srcb = (const char*)Bp + (size_t)(j + 1) * 65536;
            for (int idx = tid; idx < 4096; idx += 256) {
                int hl = idx >> 11, rem = idx & 2047, r = rem >> 4, c = rem & 15;
                cp_async16(dstb + hl * 34816 + r * PS + c * 16,
                           srcb + hl * 32768 + r * 256 + c * 16);
            }
            cp_commit();
            cp_wait1();
        } else {
            cp_wait0();
        }
        __syncthreads();

        float acc[2][8][4];
#pragma unroll
        for (int i = 0; i < 2; i++)
#pragma unroll
            for (int n = 0; n < 8; n++)
#pragma unroll
                for (int q = 0; q < 4; q++) acc[i][n][q] = 0.f;

        const uint32_t Bbuf = sb + OFF_B0 + (j & 1) * BUFSZ;
#pragma unroll
        for (int term = 0; term < 3; term++) {
            const uint32_t Ab = sb + (term == 2 ? OFF_AL : OFF_AH);
            const uint32_t Bb = Bbuf + (term == 1 ? 34816 : 0);
            const uint32_t aBase = Ab + (wm * 32 + (lane & 15)) * PS + (lane >> 4) * 16;
            const int bg = lane >> 3, br = lane & 7;
            const uint32_t bBase = Bb + ((bg & 1) * 8 + br) * PS + wn * 128 + (bg >> 1) * 16;
#pragma unroll
            for (int ks = 0; ks < 8; ks++) {
                uint32_t a0[4], a1[4], bf[8][2];
                ldmx4(a0, aBase + ks * 32);
                ldmx4(a1, aBase + 16 * PS + ks * 32);
#pragma unroll
                for (int p = 0; p < 4; p++) {
                    uint32_t t4[4];
                    ldmx4t(t4, bBase + ks * 16 * PS + p * 32);
                    bf[2 * p][0] = t4[0]; bf[2 * p][1] = t4[1];
                    bf[2 * p + 1][0] = t4[2]; bf[2 * p + 1][1] = t4[3];
                }
#pragma unroll
                for (int nt = 0; nt < 8; nt++) {
                    mma_bf16(acc[0][nt], a0, bf[nt]);
                    mma_bf16(acc[1][nt], a1, bf[nt]);
                }
            }
        }

        // ----- epilogue -----
#pragma unroll
        for (int mt = 0; mt < 2; mt++) {
#pragma unroll
            for (int h = 0; h < 2; h++) {
                int rl = wm * 32 + mt * 16 + (lane >> 2) + h * 8;
                int row = m0 + rl;
                if (row >= M) continue;
                if (KIND == 2 && j < 2) {
                    // half store to ekv
#pragma unroll
                    for (int nt = 0; nt < 8; nt++) {
                        int col = wn * 64 + nt * 8 + (lane & 3) * 2;
                        __half2 hv = __floats2half2_rn(acc[mt][nt][h * 2],
                                                       acc[mt][nt][h * 2 + 1]);
                        *reinterpret_cast<__half2*>(HO + (size_t)row * 256 + j * 128 + col) = hv;
                    }
                } else {
                    int s = 0, d = 0;
                    if (KIND == 2) { s = src[row]; d = dst[row]; }
                    float* C = outs.C[KIND == 2 ? 0 : j];
                    const int ldc = outs.ldc[KIND == 2 ? 0 : j];
                    const int co = outs.co[KIND == 2 ? 0 : j];
#pragma unroll
                    for (int nt = 0; nt < 8; nt++) {
                        int col = wn * 64 + nt * 8 + (lane & 3) * 2;
                        float vx = acc[mt][nt][h * 2], vy = acc[mt][nt][h * 2 + 1];
                        if (KIND == 1) {
                            float2 rv = *reinterpret_cast<const float2*>(R + (size_t)row * 128 + col);
                            vx += rv.x; vy += rv.y;
                            vx = fmaxf(vx, 0.f); vy = fmaxf(vy, 0.f);
                        }
                        if (KIND == 2) {
                            int aoff = rl * PS + col * 2;
                            __nv_bfloat162 hh = *reinterpret_cast<__nv_bfloat162*>(smem + OFF_AH + aoff);
                            __nv_bfloat162 ll = *reinterpret_cast<__nv_bfloat162*>(smem + OFF_AL + aoff);
                            vx += __bfloat162float(hh.x) + __bfloat162float(ll.x);
                            vy += __bfloat162float(hh.y) + __bfloat162float(ll.y);
                            float2 pv = *reinterpret_cast<const float2*>(PQ + (size_t)s * 256 + col);
                            float2 qv = *reinterpret_cast<const float2*>(PQ + (size_t)d * 256 + 128 + col);
                            vx += pv.x + qv.x; vy += pv.y + qv.y;
                            vx = fmaxf(vx, 0.f); vy = fmaxf(vy, 0.f);
                        }
                        *reinterpret_cast<float2*>(C + (size_t)row * ldc + co + col) =
                            make_float2(vx, vy);
                    }
                }
            }
        }
        __syncthreads();   // protect B buffer reuse
    }
}

// ---------------- misc elementwise kernels ----------------------------------
__device__ __forceinline__ void atomicMaxF(float* addr, float v) {
    if (v >= 0.f) atomicMax((int*)addr, __float_as_int(v));
    else          atomicMin((unsigned int*)addr, __float_as_uint(v));
}

__global__ void k_fill(float* p, int n, float v) {
    int i = blockIdx.x * blockDim.x + threadIdx.x;
    if (i < n) p[i] = v;
}

__global__ void k_node_embed(const int* __restrict__ x, const float* __restrict__ emb,
                             float* __restrict__ feat) {
    unsigned t = blockIdx.x * blockDim.x + threadIdx.x;
    if (t >= (unsigned)NN * 32u) return;
    int n = t >> 5, q = t & 31;
    float4 v = *reinterpret_cast<const float4*>(emb + (size_t)x[n] * 128 + q * 4);
    *reinterpret_cast<float4*>(feat + (size_t)n * 128 + q * 4) = v;
}

__global__ void k_lut_e(const float* __restrict__ femb, const float* __restrict__ pemb,
                        const float* __restrict__ bemb, float* __restrict__ elut) {
    int c = blockIdx.x, t = threadIdx.x;
    elut[c * 128 + t] = femb[(c >> 7) * 128 + t] + pemb[((c >> 1) & 63) * 128 + t] +
                        bemb[(c & 1) * 128 + t];
}

__global__ void k_code(const int* __restrict__ flow, const int* __restrict__ pos,
                       const int* __restrict__ blk, const int* __restrict__ src,
                       const int* __restrict__ dst, int* __restrict__ code) {
    int e = blockIdx.x * blockDim.x + threadIdx.x;
    if (e >= EE) return;
    int cr = (blk[src[e]] != blk[dst[e]]) ? 1 : 0;
    code[e] = (flow[e] << 7) | (pos[e] << 1) | cr;
}

__global__ void k_expand_e(const int* __restrict__ code, const float* __restrict__ elut,
                           float* __restrict__ e) {
    unsigned t = blockIdx.x * blockDim.x + threadIdx.x;
    if (t >= (unsigned)EE * 32u) return;
    int ed = t >> 5, q = t & 31;
    float4 v = *reinterpret_cast<const float4*>(elut + (size_t)code[ed] * 128 + q * 4);
    *reinterpret_cast<float4*>(e + (size_t)ed * 128 + q * 4) = v;
}

// scores + segment max
__global__ void k_scores(const float* __restrict__ qkv, const __half* __restrict__ ekv,
                         const int* __restrict__ src, const int* __restrict__ dst,
                         float* __restrict__ sc, float* __restrict__ m)
{
    unsigned t = blockIdx.x * blockDim.x + threadIdx.x;
    int w = t >> 5;
    int lane = threadIdx.x & 31;
    if (w >= EE) return;
    int s = src[w], d = dst[w];
    float4 q4 = *reinterpret_cast<const float4*>(qkv + (size_t)d * 384 + lane * 4);
    float4 k4 = *reinterpret_cast<const float4*>(qkv + (size_t)s * 384 + 128 + lane * 4);
    const __half2* eh = reinterpret_cast<const __half2*>(ekv + (size_t)w * 256 + lane * 4);
    float2 e01 = __half22float2(eh[0]), e23 = __half22float2(eh[1]);
    float p = q4.x * (k4.x + e01.x) + q4.y * (k4.y + e01.y) +
              q4.z * (k4.z + e23.x) + q4.w * (k4.w + e23.y);
    p += __shfl_xor_sync(0xffffffffu, p, 4);
    p += __shfl_xor_sync(0xffffffffu, p, 2);
    p += __shfl_xor_sync(0xffffffffu, p, 1);
    if ((lane & 7) == 0) {
        int h = lane >> 3;
        float v = p * 0.17677669529663687f;
        sc[(size_t)w * 4 + h] = v;
        atomicMaxF(&m[d * 4 + h], v);
    }
}

// ex = exp(sc - m[dst]); den[dst] += ex; agg[dst] += ex * (v[src] + ev)
__global__ void k_agg(const float* __restrict__ qkv, const __half* __restrict__ ekv,
                      const int* __restrict__ src, const int* __restrict__ dst,
                      const float* __restrict__ sc, const float* __restrict__ m,
                      float* __restrict__ den, float* __restrict__ agg)
{
    unsigned t = blockIdx.x * blockDim.x + threadIdx.x;
    int w = t >> 5;
    int lane = threadIdx.x & 31;
    if (w >= EE) return;
    int s = src[w], d = dst[w];
    int h = lane >> 3;
    float ex = __expf(sc[(size_t)w * 4 + h] - m[d * 4 + h]);
    if ((lane & 7) == 0) atomicAdd(&den[d * 4 + h], ex);
    float4 v4 = *reinterpret_cast<const float4*>(qkv + (size_t)s * 384 + 256 + lane * 4);
    const __half2* eh = reinterpret_cast<const __half2*>(ekv + (size_t)w * 256 + 128 + lane * 4);
    float2 e01 = __half22float2(eh[0]), e23 = __half22float2(eh[1]);
    float* p = agg + (size_t)d * 128 + lane * 4;
    atomicAdd(p + 0, ex * (v4.x + e01.x));
    atomicAdd(p + 1, ex * (v4.y + e01.y));
    atomicAdd(p + 2, ex * (v4.z + e23.x));
    atomicAdd(p + 3, ex * (v4.w + e23.y));
}

__global__ void k_gnode(const float* __restrict__ feat, const int* __restrict__ ntype,
                        const int* __restrict__ batch, float* __restrict__ ga,
                        float* __restrict__ cn)
{
    unsigned t = blockIdx.x * blockDim.x + threadIdx.x;
    if (t >= (unsigned)NN * 32u) return;
    int n = t >> 5, q = t & 31;
    if (ntype[n] != 0) return;
    int b = batch[n];
    float4 f = *reinterpret_cast<const float4*>(feat + (size_t)n * 128 + q * 4);
    float* p = ga + (size_t)b * 256 + q * 4;
    atomicAdd(p + 0, f.x); atomicAdd(p + 1, f.y);
    atomicAdd(p + 2, f.z); atomicAdd(p + 3, f.w);
    if (q == 0) atomicAdd(&cn[b], 1.f);
}

__global__ void k_gedge(const float* __restrict__ e, const int* __restrict__ src,
                        const int* __restrict__ batch, float* __restrict__ ga,
                        float* __restrict__ ce)
{
    unsigned t = blockIdx.x * blockDim.x + threadIdx.x;
    if (t >= (unsigned)EE * 32u) return;
    int ed = t >> 5, q = t & 31;
    int b = batch[src[ed]];
    float4 f = *reinterpret_cast<const float4*>(e + (size_t)ed * 128 + q * 4);
    float* p = ga + (size_t)b * 256 + 128 + q * 4;
    atomicAdd(p + 0, f.x); atomicAdd(p + 1, f.y);
    atomicAdd(p + 2, f.z); atomicAdd(p + 3, f.w);
    if (q == 0) atomicAdd(&ce[b], 1.f);
}

__global__ void k_head(const float* __restrict__ ga, const float* __restrict__ cn,
                       const float* __restrict__ ce,
                       const float* __restrict__ QW1, const float* __restrict__ Qb1,
                       const float* __restrict__ QW2, const float* __restrict__ Qb2,
                       float* __restrict__ out)
{
    int g = blockIdx.x;
    int t = threadIdx.x;  // 128
    __shared__ float s_in[256];
    __shared__ float s_h[128];
    __shared__ float s_l[128];
    __shared__ float s_max, s_lse;
    float nc = fmaxf(cn[g], 1.0f);
    float ec = fmaxf(ce[g], 1.0f);
    s_in[t]       = ga[(size_t)g * 256 + t] / nc;
    s_in[t + 128] = ga[(size_t)g * 256 + 128 + t] / ec;
    __syncthreads();
    float acc = Qb1[t];
    for (int k = 0; k < 256; k++) acc = fmaf(s_in[k], QW1[(size_t)k * 128 + t], acc);
    s_h[t] = fmaxf(acc, 0.f);
    __syncthreads();
    float lg = 0.f;
    if (t < AA) {
        lg = Qb2[t];
        for (int k = 0; k < 128; k++) lg = fmaf(s_h[k], QW2[(size_t)k * AA + t], lg);
        s_l[t] = lg;
    }
    __syncthreads();
    if (t == 0) {
        float mx = -3.4e38f;
        for (int i = 0; i < AA; i++) mx = fmaxf(mx, s_l[i]);
        float s = 0.f;
        for (int i = 0; i < AA; i++) s += expf(s_l[i] - mx);
        s_max = mx;
        s_lse = logf(s);
    }
    __syncthreads();
    if (t < AA) out[(size_t)g * AA + t] = lg - s_max - s_lse;
}

// ---------------- launch ------------------------------------------------------
extern "C" void kernel_launch(void* const* d_in, const int* in_sizes, int n_in,
                              void* d_out, int out_size)
{
    const int* x     = (const int*)d_in[0];
    const int* ntype = (const int*)d_in[1];
    const int* batch = (const int*)d_in[2];
    const int* ei    = (const int*)d_in[3];
    const int* flow  = (const int*)d_in[4];
    const int* pos   = (const int*)d_in[5];
    const int* blk   = (const int*)d_in[6];
    int base = (in_sizes[7] == 8192 * 128) ? 7 : 8;
    const float* emb  = (const float*)d_in[base + 0];
    const float* femb = (const float*)d_in[base + 1];
    const float* pemb = (const float*)d_in[base + 2];
    const float* bemb = (const float*)d_in[base + 3];
    const float* Wq   = (const float*)d_in[base + 4];
    const float* Wk   = (const float*)d_in[base + 5];
    const float* Wv   = (const float*)d_in[base + 6];
    const float* Wek  = (const float*)d_in[base + 7];
    const float* Wev  = (const float*)d_in[base + 8];
    const float* Wo   = (const float*)d_in[base + 9];
    const float* Weu  = (const float*)d_in[base + 10];
    const float* QW1  = (const float*)d_in[base + 11];
    const float* Qb1  = (const float*)d_in[base + 12];
    const float* QW2  = (const float*)d_in[base + 13];
    const float* Qb2  = (const float*)d_in[base + 14];
    const int* src = ei;
    const int* dst = ei + EE;
    float* out = (float*)d_out;

    float *feat0, *feat1, *e0, *e1, *qkv, *sc, *m, *den, *agg, *PQ;
    float *ga, *cn, *ce, *elut;
    __half* ekv;
    int* code;
    __nv_bfloat16* pack;
    cudaGetSymbolAddress((void**)&feat0, g_feat0);
    cudaGetSymbolAddress((void**)&feat1, g_feat1);
    cudaGetSymbolAddress((void**)&e0, g_e0);
    cudaGetSymbolAddress((void**)&e1, g_e1);
    cudaGetSymbolAddress((void**)&qkv, g_qkv);
    cudaGetSymbolAddress((void**)&ekv, g_ekv);
    cudaGetSymbolAddress((void**)&sc, g_sc);
    cudaGetSymbolAddress((void**)&m, g_m);
    cudaGetSymbolAddress((void**)&den, g_den);
    cudaGetSymbolAddress((void**)&agg, g_agg);
    cudaGetSymbolAddress((void**)&PQ, g_PQ);
    cudaGetSymbolAddress((void**)&ga, g_ga);
    cudaGetSymbolAddress((void**)&cn, g_cn);
    cudaGetSymbolAddress((void**)&ce, g_ce);
    cudaGetSymbolAddress((void**)&code, g_code);
    cudaGetSymbolAddress((void**)&elut, g_elut);
    cudaGetSymbolAddress((void**)&pack, g_pack);

    const int SMT1 = 69632 + 69632;        // NB=1
    const int SMT2 = 69632 + 2 * 69632;    // NB>=2 (208896)
    cudaFuncSetAttribute(mma_gemm<0>, cudaFuncAttributeMaxDynamicSharedMemorySize, SMT2);
    cudaFuncSetAttribute(mma_gemm<1>, cudaFuncAttributeMaxDynamicSharedMemorySize, SMT1);
    cudaFuncSetAttribute(mma_gemm<2>, cudaFuncAttributeMaxDynamicSharedMemorySize, SMT2);

    const int TPB = 256;
    const int gN32 = (NN * 32 + TPB - 1) / TPB;
    const int gE32 = (EE * 32 + TPB - 1) / TPB;
    const int GN = (NN + 127) / 128;
    const int GE = (EE + 127) / 128;

    // prologue
    k_packall<<<72, 256>>>(Wq, Wk, Wv, Wek, Wev, Wo, Weu, pack);
    k_node_embed<<<gN32, TPB>>>(x, emb, feat0);
    k_lut_e<<<1024, 128>>>(femb, pemb, bemb, elut);
    k_code<<<(EE + TPB - 1) / TPB, TPB>>>(flow, pos, blk, src, dst, code);
    k_expand_e<<<gE32, TPB>>>(code, elut, e0);

    float* fc = feat0; float* fn = feat1;
    float* ec = e0;    float* en = e1;

    for (int l = 0; l < LL; l++) {
        const __nv_bfloat16* pb = pack + (size_t)l * 9 * 32768;

        // node pass: q,k,v,P,Q from fc (Wq,Wk,Wv,WeuS,WeuD contiguous)
        {
            Outs o{};
            o.C[0] = qkv; o.ldc[0] = 384; o.co[0] = 0;
            o.C[1] = qkv; o.ldc[1] = 384; o.co[1] = 128;
            o.C[2] = qkv; o.ldc[2] = 384; o.co[2] = 256;
            o.C[3] = PQ;  o.ldc[3] = 256; o.co[3] = 0;
            o.C[4] = PQ;  o.ldc[4] = 256; o.co[4] = 128;
            mma_gemm<0><<<GN, 256, SMT2>>>(fc, pb, o, nullptr, nullptr, nullptr,
                                           nullptr, nullptr, nullptr, NN);
        }
        // edge pass: ek,ev (half) + en, reading ec ONCE (Wek,Wev,WeuE contiguous)
        {
            Outs o{}; o.C[0] = en; o.ldc[0] = 128; o.co[0] = 0;
            mma_gemm<2><<<GE, 256, SMT2>>>(ec, pb + (size_t)5 * 32768, o, ekv,
                                           nullptr, PQ, src, dst, nullptr, EE);
        }

        k_fill<<<(NN * 4 + TPB - 1) / TPB, TPB>>>(m, NN * 4, -3.4e38f);
        cudaMemsetAsync(den, 0, (size_t)NN * 4 * sizeof(float));
        cudaMemsetAsync(agg, 0, (size_t)NN * 128 * sizeof(float));

        k_scores<<<gE32, TPB>>>(qkv, ekv, src, dst, sc, m);
        k_agg<<<gE32, TPB>>>(qkv, ekv, src, dst, sc, m, den, agg);

        // feat_new = relu(fc + (agg/den)@Wo)   (Wo at mt=8)
        {
            Outs o{}; o.C[0] = fn; o.ldc[0] = 128; o.co[0] = 0;
            mma_gemm<1><<<GN, 256, SMT1>>>(agg, pb + (size_t)8 * 32768, o, nullptr,
                                           fc, nullptr, nullptr, nullptr, den, NN);
        }

        float* tf = fc; fc = fn; fn = tf;
        float* te = ec; ec = en; en = te;
    }

    cudaMemsetAsync(ga, 0, (size_t)GG * 256 * sizeof(float));
    cudaMemsetAsync(cn, 0, GG * sizeof(float));
    cudaMemsetAsync(ce, 0, GG * sizeof(float));
    k_gnode<<<gN32, TPB>>>(fc, ntype, batch, ga, cn);
    k_gedge<<<gE32, TPB>>>(ec, src, batch, ga, ce);
    k_head<<<GG, 128>>>(ga, cn, ce, QW1, Qb1, QW2, Qb2, out);
}

// round 10
// speedup vs baseline: 1.9450x; 1.0769x over previous
#include <cuda_runtime.h>
#include <cuda_bf16.h>
#include <cuda_fp16.h>
#include <math.h>
#include <stdint.h>

#define NN 100000
#define EE 500000
#define DD 128
#define LL 8
#define GG 64
#define AA 100

// ---------------- scratch (static device arrays; no cudaMalloc) -------------
__device__ float  g_feat0[(size_t)NN * DD];
__device__ float  g_feat1[(size_t)NN * DD];
__device__ float  g_e0[(size_t)EE * DD];
__device__ float  g_e1[(size_t)EE * DD];
__device__ float  g_qkv[(size_t)NN * 3 * DD];
__device__ __half g_ekv[(size_t)EE * 2 * DD];
__device__ float  g_agg[(size_t)NN * DD];
__device__ float  g_PQ[(size_t)NN * 256];
__device__ float  g_ga[GG * 256];
__device__ float  g_cn[GG];
__device__ float  g_ce[GG];
__device__ int    g_code[EE];
__device__ float  g_elut[1024 * DD];
// CSR by dst (graph is static across layers)
__device__ int    g_cnt[NN];
__device__ int    g_rowptr[NN + 1];
__device__ int    g_cursor[NN];
__device__ int    g_csr[EE];
// packed weights: 8 layers x 9 mats x (16384 hi + 16384 lo) bf16, [k][n] row-major
// mat order: Wq,Wk,Wv,WeuS,WeuD,Wek,Wev,WeuE,Wo
__device__ __nv_bfloat16 g_pack[(size_t)LL * 9 * 32768];

// ---------------- PTX helpers (baseline features only) ----------------------
__device__ __forceinline__ uint32_t smem_u32(const void* p) {
    return (uint32_t)__cvta_generic_to_shared(p);
}
__device__ __forceinline__ void cp_async16(uint32_t smem, const void* gmem) {
    asm volatile("cp.async.cg.shared.global [%0], [%1], 16;\n" :: "r"(smem), "l"(gmem));
}
__device__ __forceinline__ void cp_commit() { asm volatile("cp.async.commit_group;\n"); }
__device__ __forceinline__ void cp_wait0() { asm volatile("cp.async.wait_group 0;\n"); }
__device__ __forceinline__ void cp_wait1() { asm volatile("cp.async.wait_group 1;\n"); }

__device__ __forceinline__ void ldmx4(uint32_t* r, uint32_t addr) {
    asm volatile("ldmatrix.sync.aligned.m8n8.x4.shared.b16 {%0,%1,%2,%3}, [%4];"
                 : "=r"(r[0]), "=r"(r[1]), "=r"(r[2]), "=r"(r[3]) : "r"(addr));
}
__device__ __forceinline__ void ldmx4t(uint32_t* r, uint32_t addr) {
    asm volatile("ldmatrix.sync.aligned.m8n8.x4.trans.shared.b16 {%0,%1,%2,%3}, [%4];"
                 : "=r"(r[0]), "=r"(r[1]), "=r"(r[2]), "=r"(r[3]) : "r"(addr));
}
__device__ __forceinline__ void mma_bf16(float* c, const uint32_t* a, const uint32_t* b) {
    asm volatile("mma.sync.aligned.m16n8k16.row.col.f32.bf16.bf16.f32 "
                 "{%0,%1,%2,%3}, {%4,%5,%6,%7}, {%8,%9}, {%0,%1,%2,%3};"
                 : "+f"(c[0]), "+f"(c[1]), "+f"(c[2]), "+f"(c[3])
                 : "r"(a[0]), "r"(a[1]), "r"(a[2]), "r"(a[3]), "r"(b[0]), "r"(b[1]));
}

// ---------------- weight pack: split hi/lo bf16, keep [k][n] layout ---------
__global__ void k_packall(const float* __restrict__ Wq, const float* __restrict__ Wk,
                          const float* __restrict__ Wv, const float* __restrict__ Wek,
                          const float* __restrict__ Wev, const float* __restrict__ Wo,
                          const float* __restrict__ Weu, __nv_bfloat16* __restrict__ pack)
{
    int b = blockIdx.x;        // 72 = 8 layers * 9 mats
    int l = b / 9, mt = b % 9;
    const float* W;
    switch (mt) {
        case 0: W = Wq  + (size_t)l * 16384; break;
        case 1: W = Wk  + (size_t)l * 16384; break;
        case 2: W = Wv  + (size_t)l * 16384; break;
        case 3: W = Weu + (size_t)l * 49152; break;           // WeuS
        case 4: W = Weu + (size_t)l * 49152 + 16384; break;   // WeuD
        case 5: W = Wek + (size_t)l * 16384; break;
        case 6: W = Wev + (size_t)l * 16384; break;
        case 7: W = Weu + (size_t)l * 49152 + 32768; break;   // WeuE
        default: W = Wo + (size_t)l * 16384; break;           // Wo
    }
    __nv_bfloat16* dst = pack + (size_t)b * 32768;
    for (int idx = threadIdx.x; idx < 16384; idx += blockDim.x) {
        float a = W[idx];
        __nv_bfloat16 h = __float2bfloat16(a);
        __nv_bfloat16 lo = __float2bfloat16(a - __bfloat162float(h));
        dst[idx] = h;
        dst[16384 + idx] = lo;
    }
}

// ---------------- multi-matrix tensor-core GEMM (bf16x3 split) --------------
// KIND 0: node pass, NB=5 fp32 outs via Outs (qkv x3, PQ x2)
// KIND 1: Wo pass, NB=1: C = relu(R + A@B)
// KIND 2: edge pass, NB=3: j<2 -> half out to HO (ekv); j==2 ->
//         en = relu(A + C + P[src] + Q[dst]) fp32 (A residual from smem split)
struct Outs { float* C[5]; int ldc[5]; int co[5]; };

template<int KIND>
__global__ void __launch_bounds__(256, 1) mma_gemm(
    const float* __restrict__ A, const __nv_bfloat16* __restrict__ Bp, Outs outs,
    __half* __restrict__ HO, const float* __restrict__ R, const float* __restrict__ PQ,
    const int* __restrict__ src, const int* __restrict__ dst, int M)
{
    constexpr int NB = (KIND == 0) ? 5 : (KIND == 2) ? 3 : 1;
    extern __shared__ char smem[];
    const uint32_t sb = smem_u32(smem);
    const int tid = threadIdx.x;
    const int lane = tid & 31, wid = tid >> 5;
    const int wm = wid & 3, wn = wid >> 2;     // 4x2 warp grid
    const int m0 = blockIdx.x * 128;
    const int PS = 272;                        // padded row stride (bytes)
    const uint32_t OFF_AH = 0, OFF_AL = 34816;
    const uint32_t OFF_B0 = 69632, BUFSZ = 69632;   // per-buf: Bh | Bl

    // prefetch B0 into buf 0
    for (int idx = tid; idx < 4096; idx += 256) {
        int hl = idx >> 11, rem = idx & 2047, r = rem >> 4, c = rem & 15;
        cp_async16(sb + OFF_B0 + hl * 34816 + r * PS + c * 16,
                   (const char*)Bp + hl * 32768 + r * 256 + c * 16);
    }
    cp_commit();

    // A: load fp32, split bf16 hi/lo, store padded
    for (int idx = tid; idx < 4096; idx += 256) {
        int r = idx >> 5, f4 = idx & 31;
        int rg = m0 + r; if (rg >= M) rg = M - 1;
        float4 v = *reinterpret_cast<const float4*>(A + (size_t)rg * 128 + f4 * 4);
        __nv_bfloat16 hx = __float2bfloat16(v.x), hy = __float2bfloat16(v.y);
        __nv_bfloat16 hz = __float2bfloat16(v.z), hw = __float2bfloat16(v.w);
        __nv_bfloat16 lx = __float2bfloat16(v.x - __bfloat162float(hx));
        __nv_bfloat16 ly = __float2bfloat16(v.y - __bfloat162float(hy));
        __nv_bfloat16 lz = __float2bfloat16(v.z - __bfloat162float(hz));
        __nv_bfloat16 lw = __float2bfloat16(v.w - __bfloat162float(hw));
        __nv_bfloat162 h01 = __halves2bfloat162(hx, hy), h23 = __halves2bfloat162(hz, hw);
        __nv_bfloat162 l01 = __halves2bfloat162(lx, ly), l23 = __halves2bfloat162(lz, lw);
        int off = r * PS + f4 * 8;
        *reinterpret_cast<uint2*>(smem + OFF_AH + off) =
            make_uint2(*(uint32_t*)&h01, *(uint32_t*)&h23);
        *reinterpret_cast<uint2*>(smem + OFF_AL + off) =
            make_uint2(*(uint32_t*)&l01, *(uint32_t*)&l23);
    }

#pragma unroll
    for (int j = 0; j < NB; j++) {
        if (j + 1 < NB) {
            const uint32_t dstb = sb + OFF_B0 + ((j + 1) & 1) * BUFSZ;
            const char* srcb = (const char*)Bp + (size_t)(j + 1) * 65536;
            for (int idx = tid; idx < 4096; idx += 256) {
                int hl = idx >> 11, rem = idx & 2047, r = rem >> 4, c = rem & 15;
                cp_async16(dstb + hl * 34816 + r * PS + c * 16,
                           srcb + hl * 32768 + r * 256 + c * 16);
            }
            cp_commit();
            cp_wait1();
        } else {
            cp_wait0();
        }
        __syncthreads();

        float acc[2][8][4];
#pragma unroll
        for (int i = 0; i < 2; i++)
#pragma unroll
            for (int n = 0; n < 8; n++)
#pragma unroll
                for (int q = 0; q < 4; q++) acc[i][n][q] = 0.f;

        const uint32_t Bbuf = sb + OFF_B0 + (j & 1) * BUFSZ;
#pragma unroll
        for (int term = 0; term < 3; term++) {
            const uint32_t Ab = sb + (term == 2 ? OFF_AL : OFF_AH);
            const uint32_t Bb = Bbuf + (term == 1 ? 34816 : 0);
            const uint32_t aBase = Ab + (wm * 32 + (lane & 15)) * PS + (lane >> 4) * 16;
            const int bg = lane >> 3, br = lane & 7;
            const uint32_t bBase = Bb + ((bg & 1) * 8 + br) * PS + wn * 128 + (bg >> 1) * 16;
#pragma unroll
            for (int ks = 0; ks < 8; ks++) {
                uint32_t a0[4], a1[4], bf[8][2];
                ldmx4(a0, aBase + ks * 32);
                ldmx4(a1, aBase + 16 * PS + ks * 32);
#pragma unroll
                for (int p = 0; p < 4; p++) {
                    uint32_t t4[4];
                    ldmx4t(t4, bBase + ks * 16 * PS + p * 32);
                    bf[2 * p][0] = t4[0]; bf[2 * p][1] = t4[1];
                    bf[2 * p + 1][0] = t4[2]; bf[2 * p + 1][1] = t4[3];
                }
#pragma unroll
                for (int nt = 0; nt < 8; nt++) {
                    mma_bf16(acc[0][nt], a0, bf[nt]);
                    mma_bf16(acc[1][nt], a1, bf[nt]);
                }
            }
        }

        // ----- epilogue -----
#pragma unroll
        for (int mt = 0; mt < 2; mt++) {
#pragma unroll
            for (int h = 0; h < 2; h++) {
                int rl = wm * 32 + mt * 16 + (lane >> 2) + h * 8;
                int row = m0 + rl;
                if (row >= M) continue;
                if (KIND == 2 && j < 2) {
#pragma unroll
                    for (int nt = 0; nt < 8; nt++) {
                        int col = wn * 64 + nt * 8 + (lane & 3) * 2;
                        __half2 hv = __floats2half2_rn(acc[mt][nt][h * 2],
                                                       acc[mt][nt][h * 2 + 1]);
                        *reinterpret_cast<__half2*>(HO + (size_t)row * 256 + j * 128 + col) = hv;
                    }
                } else {
                    int s = 0, d = 0;
                    if (KIND == 2) { s = src[row]; d = dst[row]; }
                    float* C = outs.C[KIND == 2 ? 0 : j];
                    const int ldc = outs.ldc[KIND == 2 ? 0 : j];
                    const int co = outs.co[KIND == 2 ? 0 : j];
#pragma unroll
                    for (int nt = 0; nt < 8; nt++) {
                        int col = wn * 64 + nt * 8 + (lane & 3) * 2;
                        float vx = acc[mt][nt][h * 2], vy = acc[mt][nt][h * 2 + 1];
                        if (KIND == 1) {
                            float2 rv = *reinterpret_cast<const float2*>(R + (size_t)row * 128 + col);
                            vx += rv.x; vy += rv.y;
                            vx = fmaxf(vx, 0.f); vy = fmaxf(vy, 0.f);
                        }
                        if (KIND == 2) {
                            int aoff = rl * PS + col * 2;
                            __nv_bfloat162 hh = *reinterpret_cast<__nv_bfloat162*>(smem + OFF_AH + aoff);
                            __nv_bfloat162 ll = *reinterpret_cast<__nv_bfloat162*>(smem + OFF_AL + aoff);
                            vx += __bfloat162float(hh.x) + __bfloat162float(ll.x);
                            vy += __bfloat162float(hh.y) + __bfloat162float(ll.y);
                            float2 pv = *reinterpret_cast<const float2*>(PQ + (size_t)s * 256 + col);
                            float2 qv = *reinterpret_cast<const float2*>(PQ + (size_t)d * 256 + 128 + col);
                            vx += pv.x + qv.x; vy += pv.y + qv.y;
                            vx = fmaxf(vx, 0.f); vy = fmaxf(vy, 0.f);
                        }
                        *reinterpret_cast<float2*>(C + (size_t)row * ldc + co + col) =
                            make_float2(vx, vy);
                    }
                }
            }
        }
        __syncthreads();   // protect B buffer reuse
    }
}

// ---------------- CSR build (once per call; graph static across layers) -----
__global__ void k_count(const int* __restrict__ dst, int* __restrict__ cnt) {
    int e = blockIdx.x * blockDim.x + threadIdx.x;
    if (e < EE) atomicAdd(&cnt[dst[e]], 1);
}

__global__ void k_scan(const int* __restrict__ cnt, int* __restrict__ rowptr,
                       int* __restrict__ cursor) {
    __shared__ int part[1024];
    const int t = threadIdx.x;
    const int CH = (NN + 1023) / 1024;   // 98
    int s = 0;
    for (int i = 0; i < CH; i++) {
        int idx = t * CH + i;
        if (idx < NN) s += cnt[idx];
    }
    part[t] = s;
    __syncthreads();
    for (int off = 1; off < 1024; off <<= 1) {
        int v = 0;
        if (t >= off) v = part[t - off];
        __syncthreads();
        if (t >= off) part[t] += v;
        __syncthreads();
    }
    int base = (t > 0) ? part[t - 1] : 0;
    for (int i = 0; i < CH; i++) {
        int idx = t * CH + i;
        if (idx < NN) {
            rowptr[idx] = base;
            cursor[idx] = base;
            base += cnt[idx];
        }
    }
    if (t == 1023) rowptr[NN] = EE;
}

__global__ void k_scatter(const int* __restrict__ dst, int* __restrict__ cursor,
                          int* __restrict__ csr) {
    int e = blockIdx.x * blockDim.x + threadIdx.x;
    if (e >= EE) return;
    int pos = atomicAdd(&cursor[dst[e]], 1);
    csr[pos] = e;
}

// ---------------- fused attention: warp per dst node, online softmax --------
// agg[n] = sum_e alpha_e * (v[src_e] + ev_e), normalized. No atomics.
__global__ void k_attn(const float* __restrict__ qkv, const __half* __restrict__ ekv,
                       const int* __restrict__ srcArr, const int* __restrict__ rowptr,
                       const int* __restrict__ csr, float* __restrict__ agg)
{
    int w = (blockIdx.x * blockDim.x + threadIdx.x) >> 5;
    int lane = threadIdx.x & 31;
    if (w >= NN) return;
    const int beg = rowptr[w], end = rowptr[w + 1];

    float4 q4 = *reinterpret_cast<const float4*>(qkv + (size_t)w * 384 + lane * 4);
    float m = -3.4e38f, den = 0.f;
    float a0 = 0.f, a1 = 0.f, a2 = 0.f, a3 = 0.f;

    for (int i = beg; i < end; i++) {
        int eid = csr[i];
        int s = srcArr[eid];
        const float* srow = qkv + (size_t)s * 384;
        float4 k4 = *reinterpret_cast<const float4*>(srow + 128 + lane * 4);
        float4 v4 = *reinterpret_cast<const float4*>(srow + 256 + lane * 4);
        const __half2* ep = reinterpret_cast<const __half2*>(ekv + (size_t)eid * 256 + lane * 4);
        float2 ek01 = __half22float2(ep[0]), ek23 = __half22float2(ep[1]);
        float2 ev01 = __half22float2(ep[64]), ev23 = __half22float2(ep[65]);

        float p = q4.x * (k4.x + ek01.x) + q4.y * (k4.y + ek01.y) +
                  q4.z * (k4.z + ek23.x) + q4.w * (k4.w + ek23.y);
        p += __shfl_xor_sync(0xffffffffu, p, 4);
        p += __shfl_xor_sync(0xffffffffu, p, 2);
        p += __shfl_xor_sync(0xffffffffu, p, 1);
        p *= 0.17677669529663687f;   // 1/sqrt(32)

        float nm = fmaxf(m, p);
        float f = __expf(m - nm);
        float ex = __expf(p - nm);
        den = den * f + ex;
        a0 = a0 * f + ex * (v4.x + ev01.x);
        a1 = a1 * f + ex * (v4.y + ev01.y);
        a2 = a2 * f + ex * (v4.z + ev23.x);
        a3 = a3 * f + ex * (v4.w + ev23.y);
        m = nm;
    }
    float inv = (den > 0.f) ? 1.f / den : 0.f;
    *reinterpret_cast<float4*>(agg + (size_t)w * 128 + lane * 4) =
        make_float4(a0 * inv, a1 * inv, a2 * inv, a3 * inv);
}

// ---------------- misc elementwise kernels ----------------------------------
__global__ void k_node_embed(const int* __restrict__ x, const float* __restrict__ emb,
                             float* __restrict__ feat) {
    unsigned t = blockIdx.x * blockDim.x + threadIdx.x;
    if (t >= (unsigned)NN * 32u) return;
    int n = t >> 5, q = t & 31;
    float4 v = *reinterpret_cast<const float4*>(emb + (size_t)x[n] * 128 + q * 4);
    *reinterpret_cast<float4*>(feat + (size_t)n * 128 + q * 4) = v;
}

__global__ void k_lut_e(const float* __restrict__ femb, const float* __restrict__ pemb,
                        const float* __restrict__ bemb, float* __restrict__ elut) {
    int c = blockIdx.x, t = threadIdx.x;
    elut[c * 128 + t] = femb[(c >> 7) * 128 + t] + pemb[((c >> 1) & 63) * 128 + t] +
                        bemb[(c & 1) * 128 + t];
}

__global__ void k_code(const int* __restrict__ flow, const int* __restrict__ pos,
                       const int* __restrict__ blk, const int* __restrict__ src,
                       const int* __restrict__ dst, int* __restrict__ code) {
    int e = blockIdx.x * blockDim.x + threadIdx.x;
    if (e >= EE) return;
    int cr = (blk[src[e]] != blk[dst[e]]) ? 1 : 0;
    code[e] = (flow[e] << 7) | (pos[e] << 1) | cr;
}

__global__ void k_expand_e(const int* __restrict__ code, const float* __restrict__ elut,
                           float* __restrict__ e) {
    unsigned t = blockIdx.x * blockDim.x + threadIdx.x;
    if (t >= (unsigned)EE * 32u) return;
    int ed = t >> 5, q = t & 31;
    float4 v = *reinterpret_cast<const float4*>(elut + (size_t)code[ed] * 128 + q * 4);
    *reinterpret_cast<float4*>(e + (size_t)ed * 128 + q * 4) = v;
}

__global__ void k_gnode(const float* __restrict__ feat, const int* __restrict__ ntype,
                        const int* __restrict__ batch, float* __restrict__ ga,
                        float* __restrict__ cn)
{
    unsigned t = blockIdx.x * blockDim.x + threadIdx.x;
    if (t >= (unsigned)NN * 32u) return;
    int n = t >> 5, q = t & 31;
    if (ntype[n] != 0) return;
    int b = batch[n];
    float4 f = *reinterpret_cast<const float4*>(feat + (size_t)n * 128 + q * 4);
    float* p = ga + (size_t)b * 256 + q * 4;
    atomicAdd(p + 0, f.x); atomicAdd(p + 1, f.y);
    atomicAdd(p + 2, f.z); atomicAdd(p + 3, f.w);
    if (q == 0) atomicAdd(&cn[b], 1.f);
}

__global__ void k_gedge(const float* __restrict__ e, const int* __restrict__ src,
                        const int* __restrict__ batch, float* __restrict__ ga,
                        float* __restrict__ ce)
{
    unsigned t = blockIdx.x * blockDim.x + threadIdx.x;
    if (t >= (unsigned)EE * 32u) return;
    int ed = t >> 5, q = t & 31;
    int b = batch[src[ed]];
    float4 f = *reinterpret_cast<const float4*>(e + (size_t)ed * 128 + q * 4);
    float* p = ga + (size_t)b * 256 + 128 + q * 4;
    atomicAdd(p + 0, f.x); atomicAdd(p + 1, f.y);
    atomicAdd(p + 2, f.z); atomicAdd(p + 3, f.w);
    if (q == 0) atomicAdd(&ce[b], 1.f);
}

__global__ void k_head(const float* __restrict__ ga, const float* __restrict__ cn,
                       const float* __restrict__ ce,
                       const float* __restrict__ QW1, const float* __restrict__ Qb1,
                       const float* __restrict__ QW2, const float* __restrict__ Qb2,
                       float* __restrict__ out)
{
    int g = blockIdx.x;
    int t = threadIdx.x;  // 128
    __shared__ float s_in[256];
    __shared__ float s_h[128];
    __shared__ float s_l[128];
    __shared__ float s_max, s_lse;
    float nc = fmaxf(cn[g], 1.0f);
    float ec = fmaxf(ce[g], 1.0f);
    s_in[t]       = ga[(size_t)g * 256 + t] / nc;
    s_in[t + 128] = ga[(size_t)g * 256 + 128 + t] / ec;
    __syncthreads();
    float acc = Qb1[t];
    for (int k = 0; k < 256; k++) acc = fmaf(s_in[k], QW1[(size_t)k * 128 + t], acc);
    s_h[t] = fmaxf(acc, 0.f);
    __syncthreads();
    float lg = 0.f;
    if (t < AA) {
        lg = Qb2[t];
        for (int k = 0; k < 128; k++) lg = fmaf(s_h[k], QW2[(size_t)k * AA + t], lg);
        s_l[t] = lg;
    }
    __syncthreads();
    if (t == 0) {
        float mx = -3.4e38f;
        for (int i = 0; i < AA; i++) mx = fmaxf(mx, s_l[i]);
        float s = 0.f;
        for (int i = 0; i < AA; i++) s += expf(s_l[i] - mx);
        s_max = mx;
        s_lse = logf(s);
    }
    __syncthreads();
    if (t < AA) out[(size_t)g * AA + t] = lg - s_max - s_lse;
}

// ---------------- launch ------------------------------------------------------
extern "C" void kernel_launch(void* const* d_in, const int* in_sizes, int n_in,
                              void* d_out, int out_size)
{
    const int* x     = (const int*)d_in[0];
    const int* ntype = (const int*)d_in[1];
    const int* batch = (const int*)d_in[2];
    const int* ei    = (const int*)d_in[3];
    const int* flow  = (const int*)d_in[4];
    const int* pos   = (const int*)d_in[5];
    const int* blk   = (const int*)d_in[6];
    int base = (in_sizes[7] == 8192 * 128) ? 7 : 8;
    const float* emb  = (const float*)d_in[base + 0];
    const float* femb = (const float*)d_in[base + 1];
    const float* pemb = (const float*)d_in[base + 2];
    const float* bemb = (const float*)d_in[base + 3];
    const float* Wq   = (const float*)d_in[base + 4];
    const float* Wk   = (const float*)d_in[base + 5];
    const float* Wv   = (const float*)d_in[base + 6];
    const float* Wek  = (const float*)d_in[base + 7];
    const float* Wev  = (const float*)d_in[base + 8];
    const float* Wo   = (const float*)d_in[base + 9];
    const float* Weu  = (const float*)d_in[base + 10];
    const float* QW1  = (const float*)d_in[base + 11];
    const float* Qb1  = (const float*)d_in[base + 12];
    const float* QW2  = (const float*)d_in[base + 13];
    const float* Qb2  = (const float*)d_in[base + 14];
    const int* src = ei;
    const int* dst = ei + EE;
    float* out = (float*)d_out;

    float *feat0, *feat1, *e0, *e1, *qkv, *agg, *PQ;
    float *ga, *cn, *ce, *elut;
    __half* ekv;
    int *code, *cnt, *rowptr, *cursor, *csr;
    __nv_bfloat16* pack;
    cudaGetSymbolAddress((void**)&feat0, g_feat0);
    cudaGetSymbolAddress((void**)&feat1, g_feat1);
    cudaGetSymbolAddress((void**)&e0, g_e0);
    cudaGetSymbolAddress((void**)&e1, g_e1);
    cudaGetSymbolAddress((void**)&qkv, g_qkv);
    cudaGetSymbolAddress((void**)&ekv, g_ekv);
    cudaGetSymbolAddress((void**)&agg, g_agg);
    cudaGetSymbolAddress((void**)&PQ, g_PQ);
    cudaGetSymbolAddress((void**)&ga, g_ga);
    cudaGetSymbolAddress((void**)&cn, g_cn);
    cudaGetSymbolAddress((void**)&ce, g_ce);
    cudaGetSymbolAddress((void**)&code, g_code);
    cudaGetSymbolAddress((void**)&elut, g_elut);
    cudaGetSymbolAddress((void**)&cnt, g_cnt);
    cudaGetSymbolAddress((void**)&rowptr, g_rowptr);
    cudaGetSymbolAddress((void**)&cursor, g_cursor);
    cudaGetSymbolAddress((void**)&csr, g_csr);
    cudaGetSymbolAddress((void**)&pack, g_pack);

    const int SMT1 = 69632 + 69632;        // NB=1
    const int SMT2 = 69632 + 2 * 69632;    // NB>=2 (208896)
    cudaFuncSetAttribute(mma_gemm<0>, cudaFuncAttributeMaxDynamicSharedMemorySize, SMT2);
    cudaFuncSetAttribute(mma_gemm<1>, cudaFuncAttributeMaxDynamicSharedMemorySize, SMT1);
    cudaFuncSetAttribute(mma_gemm<2>, cudaFuncAttributeMaxDynamicSharedMemorySize, SMT2);

    const int TPB = 256;
    const int gN32 = (NN * 32 + TPB - 1) / TPB;
    const int gE32 = (EE * 32 + TPB - 1) / TPB;
    const int gE   = (EE + TPB - 1) / TPB;
    const int GN = (NN + 127) / 128;
    const int GE = (EE + 127) / 128;

    // prologue: weights, embeddings, CSR build
    k_packall<<<72, 256>>>(Wq, Wk, Wv, Wek, Wev, Wo, Weu, pack);
    k_node_embed<<<gN32, TPB>>>(x, emb, feat0);
    k_lut_e<<<1024, 128>>>(femb, pemb, bemb, elut);
    k_code<<<gE, TPB>>>(flow, pos, blk, src, dst, code);
    k_expand_e<<<gE32, TPB>>>(code, elut, e0);
    cudaMemsetAsync(cnt, 0, NN * sizeof(int));
    k_count<<<gE, TPB>>>(dst, cnt);
    k_scan<<<1, 1024>>>(cnt, rowptr, cursor);
    k_scatter<<<gE, TPB>>>(dst, cursor, csr);

    float* fc = feat0; float* fn = feat1;
    float* ec = e0;    float* en = e1;

    for (int l = 0; l < LL; l++) {
        const __nv_bfloat16* pb = pack + (size_t)l * 9 * 32768;

        // node pass: q,k,v,P,Q from fc (Wq,Wk,Wv,WeuS,WeuD contiguous)
        {
            Outs o{};
            o.C[0] = qkv; o.ldc[0] = 384; o.co[0] = 0;
            o.C[1] = qkv; o.ldc[1] = 384; o.co[1] = 128;
            o.C[2] = qkv; o.ldc[2] = 384; o.co[2] = 256;
            o.C[3] = PQ;  o.ldc[3] = 256; o.co[3] = 0;
            o.C[4] = PQ;  o.ldc[4] = 256; o.co[4] = 128;
            mma_gemm<0><<<GN, 256, SMT2>>>(fc, pb, o, nullptr, nullptr, nullptr,
                                           nullptr, nullptr, NN);
        }
        // edge pass: ek,ev (half) + en, reading ec ONCE (Wek,Wev,WeuE contiguous)
        {
            Outs o{}; o.C[0] = en; o.ldc[0] = 128; o.co[0] = 0;
            mma_gemm<2><<<GE, 256, SMT2>>>(ec, pb + (size_t)5 * 32768, o, ekv,
                                           nullptr, PQ, src, dst, EE);
        }

        // fused attention (online softmax, no atomics, normalized output)
        k_attn<<<gN32, TPB>>>(qkv, ekv, src, rowptr, csr, agg);

        // feat_new = relu(fc + agg@Wo)   (Wo at mt=8)
        {
            Outs o{}; o.C[0] = fn; o.ldc[0] = 128; o.co[0] = 0;
            mma_gemm<1><<<GN, 256, SMT1>>>(agg, pb + (size_t)8 * 32768, o, nullptr,
                                           fc, nullptr, nullptr, nullptr, NN);
        }

        float* tf = fc; fc = fn; fn = tf;
        float* te = ec; ec = en; en = te;
    }

    cudaMemsetAsync(ga, 0, (size_t)GG * 256 * sizeof(float));
    cudaMemsetAsync(cn, 0, GG * sizeof(float));
    cudaMemsetAsync(ce, 0, GG * sizeof(float));
    k_gnode<<<gN32, TPB>>>(fc, ntype, batch, ga, cn);
    k_gedge<<<gE32, TPB>>>(ec, src, batch, ga, ce);
    k_head<<<GG, 128>>>(ga, cn, ce, QW1, Qb1, QW2, Qb2, out);
}

// round 11
// speedup vs baseline: 1.9783x; 1.0171x over previous
#include <cuda_runtime.h>
#include <cuda_bf16.h>
#include <cuda_fp16.h>
#include <math.h>
#include <stdint.h>

#define NN 100000
#define EE 500000
#define DD 128
#define LL 8
#define GG 64
#define AA 100

// ---------------- scratch (static device arrays; no cudaMalloc) -------------
__device__ float  g_feat0[(size_t)NN * DD];
__device__ float  g_feat1[(size_t)NN * DD];
__device__ float  g_e0[(size_t)EE * DD];       // CSR order
__device__ float  g_e1[(size_t)EE * DD];       // CSR order
__device__ float  g_qf[(size_t)NN * DD];       // q fp32
__device__ __half g_kvh[(size_t)NN * 256];     // k|v fp16 (L2-resident)
__device__ __half g_PQh[(size_t)NN * 256];     // P|Q fp16 (L2-resident)
__device__ __half g_ekv[(size_t)EE * 2 * DD];  // ek|ev fp16, CSR order
__device__ float  g_agg[(size_t)NN * DD];
__device__ float  g_ga[GG * 256];
__device__ float  g_cn[GG];
__device__ float  g_ce[GG];
__device__ int    g_code[EE];
__device__ float  g_elut[1024 * DD];
// CSR by dst (graph static across layers) + permuted edge arrays
__device__ int    g_cnt[NN];
__device__ int    g_rowptr[NN + 1];
__device__ int    g_cursor[NN];
__device__ int    g_csr[EE];
__device__ int    g_psrc[EE];
__device__ int    g_pdst[EE];
__device__ int    g_pcode[EE];
// packed weights: 8 layers x 9 mats x (16384 hi + 16384 lo) bf16, [k][n] row-major
// mat order: Wq,Wk,Wv,WeuS,WeuD,Wek,Wev,WeuE,Wo
__device__ __nv_bfloat16 g_pack[(size_t)LL * 9 * 32768];

// ---------------- PTX helpers (baseline features only) ----------------------
__device__ __forceinline__ uint32_t smem_u32(const void* p) {
    return (uint32_t)__cvta_generic_to_shared(p);
}
__device__ __forceinline__ void cp_async16(uint32_t smem, const void* gmem) {
    asm volatile("cp.async.cg.shared.global [%0], [%1], 16;\n" :: "r"(smem), "l"(gmem));
}
__device__ __forceinline__ void cp_commit() { asm volatile("cp.async.commit_group;\n"); }
__device__ __forceinline__ void cp_wait0() { asm volatile("cp.async.wait_group 0;\n"); }
__device__ __forceinline__ void cp_wait1() { asm volatile("cp.async.wait_group 1;\n"); }

__device__ __forceinline__ void ldmx4(uint32_t* r, uint32_t addr) {
    asm volatile("ldmatrix.sync.aligned.m8n8.x4.shared.b16 {%0,%1,%2,%3}, [%4];"
                 : "=r"(r[0]), "=r"(r[1]), "=r"(r[2]), "=r"(r[3]) : "r"(addr));
}
__device__ __forceinline__ void ldmx4t(uint32_t* r, uint32_t addr) {
    asm volatile("ldmatrix.sync.aligned.m8n8.x4.trans.shared.b16 {%0,%1,%2,%3}, [%4];"
                 : "=r"(r[0]), "=r"(r[1]), "=r"(r[2]), "=r"(r[3]) : "r"(addr));
}
__device__ __forceinline__ void mma_bf16(float* c, const uint32_t* a, const uint32_t* b) {
    asm volatile("mma.sync.aligned.m16n8k16.row.col.f32.bf16.bf16.f32 "
                 "{%0,%1,%2,%3}, {%4,%5,%6,%7}, {%8,%9}, {%0,%1,%2,%3};"
                 : "+f"(c[0]), "+f"(c[1]), "+f"(c[2]), "+f"(c[3])
                 : "r"(a[0]), "r"(a[1]), "r"(a[2]), "r"(a[3]), "r"(b[0]), "r"(b[1]));
}

// ---------------- weight pack: split hi/lo bf16, keep [k][n] layout ---------
__global__ void k_packall(const float* __restrict__ Wq, const float* __restrict__ Wk,
                          const float* __restrict__ Wv, const float* __restrict__ Wek,
                          const float* __restrict__ Wev, const float* __restrict__ Wo,
                          const float* __restrict__ Weu, __nv_bfloat16* __restrict__ pack)
{
    int b = blockIdx.x;        // 72 = 8 layers * 9 mats
    int l = b / 9, mt = b % 9;
    const float* W;
    switch (mt) {
        case 0: W = Wq  + (size_t)l * 16384; break;
        case 1: W = Wk  + (size_t)l * 16384; break;
        case 2: W = Wv  + (size_t)l * 16384; break;
        case 3: W = Weu + (size_t)l * 49152; break;           // WeuS
        case 4: W = Weu + (size_t)l * 49152 + 16384; break;   // WeuD
        case 5: W = Wek + (size_t)l * 16384; break;
        case 6: W = Wev + (size_t)l * 16384; break;
        case 7: W = Weu + (size_t)l * 49152 + 32768; break;   // WeuE
        default: W = Wo + (size_t)l * 16384; break;           // Wo
    }
    __nv_bfloat16* dst = pack + (size_t)b * 32768;
    for (int idx = threadIdx.x; idx < 16384; idx += blockDim.x) {
        float a = W[idx];
        __nv_bfloat16 h = __float2bfloat16(a);
        __nv_bfloat16 lo = __float2bfloat16(a - __bfloat162float(h));
        dst[idx] = h;
        dst[16384 + idx] = lo;
    }
}

// ---------------- multi-matrix tensor-core GEMM (bf16x3 split) --------------
// KIND 0: node pass, NB=5: j0 -> q fp32 (C[0]); j1,2 -> kvh half; j3,4 -> PQh half
// KIND 1: Wo pass, NB=1: C[0] = relu(R + A@B) fp32
// KIND 2: edge pass, NB=3: j<2 -> half to HOa (ekv); j==2 ->
//         en = relu(A + C + P[psrc] + Q[pdst]) fp32 (A residual from smem split)
struct Outs { float* C[3]; };

template<int KIND>
__global__ void __launch_bounds__(256, 1) mma_gemm(
    const float* __restrict__ A, const __nv_bfloat16* __restrict__ Bp, Outs outs,
    __half* __restrict__ HOa, __half* __restrict__ HOb,
    const float* __restrict__ R, const __half* __restrict__ PQh,
    const int* __restrict__ psrc, const int* __restrict__ pdst, int M)
{
    constexpr int NB = (KIND == 0) ? 5 : (KIND == 2) ? 3 : 1;
    extern __shared__ char smem[];
    const uint32_t sb = smem_u32(smem);
    const int tid = threadIdx.x;
    const int lane = tid & 31, wid = tid >> 5;
    const int wm = wid & 3, wn = wid >> 2;     // 4x2 warp grid
    const int m0 = blockIdx.x * 128;
    const int PS = 272;                        // padded row stride (bytes)
    const uint32_t OFF_AH = 0, OFF_AL = 34816;
    const uint32_t OFF_B0 = 69632, BUFSZ = 69632;   // per-buf: Bh | Bl

    // prefetch B0 into buf 0
    for (int idx = tid; idx < 4096; idx += 256) {
        int hl = idx >> 11, rem = idx & 2047, r = rem >> 4, c = rem & 15;
        cp_async16(sb + OFF_B0 + hl * 34816 + r * PS + c * 16,
                   (const char*)Bp + hl * 32768 + r * 256 + c * 16);
    }
    cp_commit();

    // A: load fp32, split bf16 hi/lo, store padded
    for (int idx = tid; idx < 4096; idx += 256) {
        int r = idx >> 5, f4 = idx & 31;
        int rg = m0 + r; if (rg >= M) rg = M - 1;
        float4 v = *reinterpret_cast<const float4*>(A + (size_t)rg * 128 + f4 * 4);
        __nv_bfloat16 hx = __float2bfloat16(v.x), hy = __float2bfloat16(v.y);
        __nv_bfloat16 hz = __float2bfloat16(v.z), hw = __float2bfloat16(v.w);
        __nv_bfloat16 lx = __float2bfloat16(v.x - __bfloat162float(hx));
        __nv_bfloat16 ly = __float2bfloat16(v.y - __bfloat162float(hy));
        __nv_bfloat16 lz = __float2bfloat16(v.z - __bfloat162float(hz));
        __nv_bfloat16 lw = __float2bfloat16(v.w - __bfloat162float(hw));
        __nv_bfloat162 h01 = __halves2bfloat162(hx, hy), h23 = __halves2bfloat162(hz, hw);
        __nv_bfloat162 l01 = __halves2bfloat162(lx, ly), l23 = __halves2bfloat162(lz, lw);
        int off = r * PS + f4 * 8;
        *reinterpret_cast<uint2*>(smem + OFF_AH + off) =
            make_uint2(*(uint32_t*)&h01, *(uint32_t*)&h23);
        *reinterpret_cast<uint2*>(smem + OFF_AL + off) =
            make_uint2(*(uint32_t*)&l01, *(uint32_t*)&l23);
    }

#pragma unroll
    for (int j = 0; j < NB; j++) {
        if (j + 1 < NB) {
            const uint32_t dstb = sb + OFF_B0 + ((j + 1) & 1) * BUFSZ;
            const char* srcb = (const char*)Bp + (size_t)(j + 1) * 65536;
            for (int idx = tid; idx < 4096; idx += 256) {
                int hl = idx >> 11, rem = idx & 2047, r = rem >> 4, c = rem & 15;
                cp_async16(dstb + hl * 34816 + r * PS + c * 16,
                           srcb + hl * 32768 + r * 256 + c * 16);
            }
            cp_commit();
            cp_wait1();
        } else {
            cp_wait0();
        }
        __syncthreads();

        float acc[2][8][4];
#pragma unroll
        for (int i = 0; i < 2; i++)
#pragma unroll
            for (int n = 0; n < 8; n++)
#pragma unroll
                for (int q = 0; q < 4; q++) acc[i][n][q] = 0.f;

        const uint32_t Bbuf = sb + OFF_B0 + (j & 1) * BUFSZ;
#pragma unroll
        for (int term = 0; term < 3; term++) {
            const uint32_t Ab = sb + (term == 2 ? OFF_AL : OFF_AH);
            const uint32_t Bb = Bbuf + (term == 1 ? 34816 : 0);
            const uint32_t aBase = Ab + (wm * 32 + (lane & 15)) * PS + (lane >> 4) * 16;
            const int bg = lane >> 3, br = lane & 7;
            const uint32_t bBase = Bb + ((bg & 1) * 8 + br) * PS + wn * 128 + (bg >> 1) * 16;
#pragma unroll
            for (int ks = 0; ks < 8; ks++) {
                uint32_t a0[4], a1[4], bf[8][2];
                ldmx4(a0, aBase + ks * 32);
                ldmx4(a1, aBase + 16 * PS + ks * 32);
#pragma unroll
                for (int p = 0; p < 4; p++) {
                    uint32_t t4[4];
                    ldmx4t(t4, bBase + ks * 16 * PS + p * 32);
                    bf[2 * p][0] = t4[0]; bf[2 * p][1] = t4[1];
                    bf[2 * p + 1][0] = t4[2]; bf[2 * p + 1][1] = t4[3];
                }
#pragma unroll
                for (int nt = 0; nt < 8; nt++) {
                    mma_bf16(acc[0][nt], a0, bf[nt]);
                    mma_bf16(acc[1][nt], a1, bf[nt]);
                }
            }
        }

        // ----- epilogue -----
#pragma unroll
        for (int mt = 0; mt < 2; mt++) {
#pragma unroll
            for (int h = 0; h < 2; h++) {
                int rl = wm * 32 + mt * 16 + (lane >> 2) + h * 8;
                int row = m0 + rl;
                if (row >= M) continue;
                if (KIND == 0 && j >= 1) {
                    // half store: j1,2 -> kvh; j3,4 -> PQh
                    __half* HP = (j <= 2) ? HOa : HOb;
                    int co = ((j - 1) & 1) * 128;
#pragma unroll
                    for (int nt = 0; nt < 8; nt++) {
                        int col = wn * 64 + nt * 8 + (lane & 3) * 2;
                        __half2 hv = __floats2half2_rn(acc[mt][nt][h * 2],
                                                       acc[mt][nt][h * 2 + 1]);
                        *reinterpret_cast<__half2*>(HP + (size_t)row * 256 + co + col) = hv;
                    }
                } else if (KIND == 2 && j < 2) {
#pragma unroll
                    for (int nt = 0; nt < 8; nt++) {
                        int col = wn * 64 + nt * 8 + (lane & 3) * 2;
                        __half2 hv = __floats2half2_rn(acc[mt][nt][h * 2],
                                                       acc[mt][nt][h * 2 + 1]);
                        *reinterpret_cast<__half2*>(HOa + (size_t)row * 256 + j * 128 + col) = hv;
                    }
                } else {
                    int s = 0, d = 0;
                    if (KIND == 2) { s = psrc[row]; d = pdst[row]; }
                    float* C = outs.C[0];
#pragma unroll
                    for (int nt = 0; nt < 8; nt++) {
                        int col = wn * 64 + nt * 8 + (lane & 3) * 2;
                        float vx = acc[mt][nt][h * 2], vy = acc[mt][nt][h * 2 + 1];
                        if (KIND == 1) {
                            float2 rv = *reinterpret_cast<const float2*>(R + (size_t)row * 128 + col);
                            vx += rv.x; vy += rv.y;
                            vx = fmaxf(vx, 0.f); vy = fmaxf(vy, 0.f);
                        }
                        if (KIND == 2) {
                            int aoff = rl * PS + col * 2;
                            __nv_bfloat162 hh = *reinterpret_cast<__nv_bfloat162*>(smem + OFF_AH + aoff);
                            __nv_bfloat162 ll = *reinterpret_cast<__nv_bfloat162*>(smem + OFF_AL + aoff);
                            vx += __bfloat162float(hh.x) + __bfloat162float(ll.x);
                            vy += __bfloat162float(hh.y) + __bfloat162float(ll.y);
                            float2 pv = __half22float2(
                                *reinterpret_cast<const __half2*>(PQh + (size_t)s * 256 + col));
                            float2 qv = __half22float2(
                                *reinterpret_cast<const __half2*>(PQh + (size_t)d * 256 + 128 + col));
                            vx += pv.x + qv.x; vy += pv.y + qv.y;
                            vx = fmaxf(vx, 0.f); vy = fmaxf(vy, 0.f);
                        }
                        *reinterpret_cast<float2*>(C + (size_t)row * 128 + col) =
                            make_float2(vx, vy);
                    }
                }
            }
        }
        __syncthreads();   // protect B buffer reuse
    }
}

// ---------------- CSR build + edge permutation ------------------------------
__global__ void k_count(const int* __restrict__ dst, int* __restrict__ cnt) {
    int e = blockIdx.x * blockDim.x + threadIdx.x;
    if (e < EE) atomicAdd(&cnt[dst[e]], 1);
}

__global__ void k_scan(const int* __restrict__ cnt, int* __restrict__ rowptr,
                       int* __restrict__ cursor) {
    __shared__ int part[1024];
    const int t = threadIdx.x;
    const int CH = (NN + 1023) / 1024;
    int s = 0;
    for (int i = 0; i < CH; i++) {
        int idx = t * CH + i;
        if (idx < NN) s += cnt[idx];
    }
    part[t] = s;
    __syncthreads();
    for (int off = 1; off < 1024; off <<= 1) {
        int v = 0;
        if (t >= off) v = part[t - off];
        __syncthreads();
        if (t >= off) part[t] += v;
        __syncthreads();
    }
    int base = (t > 0) ? part[t - 1] : 0;
    for (int i = 0; i < CH; i++) {
        int idx = t * CH + i;
        if (idx < NN) {
            rowptr[idx] = base;
            cursor[idx] = base;
            base += cnt[idx];
        }
    }
    if (t == 1023) rowptr[NN] = EE;
}

__global__ void k_scatter(const int* __restrict__ dst, int* __restrict__ cursor,
                          int* __restrict__ csr) {
    int e = blockIdx.x * blockDim.x + threadIdx.x;
    if (e >= EE) return;
    int pos = atomicAdd(&cursor[dst[e]], 1);
    csr[pos] = e;
}

__global__ void k_permute(const int* __restrict__ csr, const int* __restrict__ src,
                          const int* __restrict__ dst, const int* __restrict__ code,
                          int* __restrict__ psrc, int* __restrict__ pdst,
                          int* __restrict__ pcode) {
    int i = blockIdx.x * blockDim.x + threadIdx.x;
    if (i >= EE) return;
    int e = csr[i];
    psrc[i] = src[e];
    pdst[i] = dst[e];
    pcode[i] = code[e];
}

// ---------------- fused attention: warp per dst node, online softmax --------
__global__ void k_attn(const float* __restrict__ qf, const __half* __restrict__ kvh,
                       const __half* __restrict__ ekv, const int* __restrict__ psrc,
                       const int* __restrict__ rowptr, float* __restrict__ agg)
{
    int w = (blockIdx.x * blockDim.x + threadIdx.x) >> 5;
    int lane = threadIdx.x & 31;
    if (w >= NN) return;
    const int beg = rowptr[w], end = rowptr[w + 1];

    float4 q4 = *reinterpret_cast<const float4*>(qf + (size_t)w * 128 + lane * 4);
    float m = -3.4e38f, den = 0.f;
    float a0 = 0.f, a1 = 0.f, a2 = 0.f, a3 = 0.f;

    for (int i = beg; i < end; i++) {
        int s = psrc[i];
        const __half2* kp = reinterpret_cast<const __half2*>(kvh + (size_t)s * 256) + lane * 2;
        float2 k01 = __half22float2(kp[0]), k23 = __half22float2(kp[1]);
        float2 v01 = __half22float2(kp[64]), v23 = __half22float2(kp[65]);
        const __half2* ep = reinterpret_cast<const __half2*>(ekv + (size_t)i * 256) + lane * 2;
        float2 ek01 = __half22float2(ep[0]), ek23 = __half22float2(ep[1]);
        float2 ev01 = __half22float2(ep[64]), ev23 = __half22float2(ep[65]);

        float p = q4.x * (k01.x + ek01.x) + q4.y * (k01.y + ek01.y) +
                  q4.z * (k23.x + ek23.x) + q4.w * (k23.y + ek23.y);
        p += __shfl_xor_sync(0xffffffffu, p, 4);
        p += __shfl_xor_sync(0xffffffffu, p, 2);
        p += __shfl_xor_sync(0xffffffffu, p, 1);
        p *= 0.17677669529663687f;   // 1/sqrt(32)

        float nm = fmaxf(m, p);
        float f = __expf(m - nm);
        float ex = __expf(p - nm);
        den = den * f + ex;
        a0 = a0 * f + ex * (v01.x + ev01.x);
        a1 = a1 * f + ex * (v01.y + ev01.y);
        a2 = a2 * f + ex * (v23.x + ev23.x);
        a3 = a3 * f + ex * (v23.y + ev23.y);
        m = nm;
    }
    float inv = (den > 0.f) ? 1.f / den : 0.f;
    *reinterpret_cast<float4*>(agg + (size_t)w * 128 + lane * 4) =
        make_float4(a0 * inv, a1 * inv, a2 * inv, a3 * inv);
}

// ---------------- misc elementwise kernels ----------------------------------
__global__ void k_node_embed(const int* __restrict__ x, const float* __restrict__ emb,
                             float* __restrict__ feat) {
    unsigned t = blockIdx.x * blockDim.x + threadIdx.x;
    if (t >= (unsigned)NN * 32u) return;
    int n = t >> 5, q = t & 31;
    float4 v = *reinterpret_cast<const float4*>(emb + (size_t)x[n] * 128 + q * 4);
    *reinterpret_cast<float4*>(feat + (size_t)n * 128 + q * 4) = v;
}

__global__ void k_lut_e(const float* __restrict__ femb, const float* __restrict__ pemb,
                        const float* __restrict__ bemb, float* __restrict__ elut) {
    int c = blockIdx.x, t = threadIdx.x;
    elut[c * 128 + t] = femb[(c >> 7) * 128 + t] + pemb[((c >> 1) & 63) * 128 + t] +
                        bemb[(c & 1) * 128 + t];
}

__global__ void k_code(const int* __restrict__ flow, const int* __restrict__ pos,
                       const int* __restrict__ blk, const int* __restrict__ src,
                       const int* __restrict__ dst, int* __restrict__ code) {
    int e = blockIdx.x * blockDim.x + threadIdx.x;
    if (e >= EE) return;
    int cr = (blk[src[e]] != blk[dst[e]]) ? 1 : 0;
    code[e] = (flow[e] << 7) | (pos[e] << 1) | cr;
}

__global__ void k_expand_e(const int* __restrict__ pcode, const float* __restrict__ elut,
                           float* __restrict__ e) {
    unsigned t = blockIdx.x * blockDim.x + threadIdx.x;
    if (t >= (unsigned)EE * 32u) return;
    int ed = t >> 5, q = t & 31;
    float4 v = *reinterpret_cast<const float4*>(elut + (size_t)pcode[ed] * 128 + q * 4);
    *reinterpret_cast<float4*>(e + (size_t)ed * 128 + q * 4) = v;
}

__global__ void k_gnode(const float* __restrict__ feat, const int* __restrict__ ntype,
                        const int* __restrict__ batch, float* __restrict__ ga,
                        float* __restrict__ cn)
{
    unsigned t = blockIdx.x * blockDim.x + threadIdx.x;
    if (t >= (unsigned)NN * 32u) return;
    int n = t >> 5, q = t & 31;
    if (ntype[n] != 0) return;
    int b = batch[n];
    float4 f = *reinterpret_cast<const float4*>(feat + (size_t)n * 128 + q * 4);
    float* p = ga + (size_t)b * 256 + q * 4;
    atomicAdd(p + 0, f.x); atomicAdd(p + 1, f.y);
    atomicAdd(p + 2, f.z); atomicAdd(p + 3, f.w);
    if (q == 0) atomicAdd(&cn[b], 1.f);
}

__global__ void k_gedge(const float* __restrict__ e, const int* __restrict__ psrc,
                        const int* __restrict__ batch, float* __restrict__ ga,
                        float* __restrict__ ce)
{
    unsigned t = blockIdx.x * blockDim.x + threadIdx.x;
    if (t >= (unsigned)EE * 32u) return;
    int ed = t >> 5, q = t & 31;
    int b = batch[psrc[ed]];
    float4 f = *reinterpret_cast<const float4*>(e + (size_t)ed * 128 + q * 4);
    float* p = ga + (size_t)b * 256 + 128 + q * 4;
    atomicAdd(p + 0, f.x); atomicAdd(p + 1, f.y);
    atomicAdd(p + 2, f.z); atomicAdd(p + 3, f.w);
    if (q == 0) atomicAdd(&ce[b], 1.f);
}

__global__ void k_head(const float* __restrict__ ga, const float* __restrict__ cn,
                       const float* __restrict__ ce,
                       const float* __restrict__ QW1, const float* __restrict__ Qb1,
                       const float* __restrict__ QW2, const float* __restrict__ Qb2,
                       float* __restrict__ out)
{
    int g = blockIdx.x;
    int t = threadIdx.x;  // 128
    __shared__ float s_in[256];
    __shared__ float s_h[128];
    __shared__ float s_l[128];
    __shared__ float s_max, s_lse;
    float nc = fmaxf(cn[g], 1.0f);
    float ec = fmaxf(ce[g], 1.0f);
    s_in[t]       = ga[(size_t)g * 256 + t] / nc;
    s_in[t + 128] = ga[(size_t)g * 256 + 128 + t] / ec;
    __syncthreads();
    float acc = Qb1[t];
    for (int k = 0; k < 256; k++) acc = fmaf(s_in[k], QW1[(size_t)k * 128 + t], acc);
    s_h[t] = fmaxf(acc, 0.f);
    __syncthreads();
    float lg = 0.f;
    if (t < AA) {
        lg = Qb2[t];
        for (int k = 0; k < 128; k++) lg = fmaf(s_h[k], QW2[(size_t)k * AA + t], lg);
        s_l[t] = lg;
    }
    __syncthreads();
    if (t == 0) {
        float mx = -3.4e38f;
        for (int i = 0; i < AA; i++) mx = fmaxf(mx, s_l[i]);
        float s = 0.f;
        for (int i = 0; i < AA; i++) s += expf(s_l[i] - mx);
        s_max = mx;
        s_lse = logf(s);
    }
    __syncthreads();
    if (t < AA) out[(size_t)g * AA + t] = lg - s_max - s_lse;
}

// ---------------- launch ------------------------------------------------------
extern "C" void kernel_launch(void* const* d_in, const int* in_sizes, int n_in,
                              void* d_out, int out_size)
{
    const int* x     = (const int*)d_in[0];
    const int* ntype = (const int*)d_in[1];
    const int* batch = (const int*)d_in[2];
    const int* ei    = (const int*)d_in[3];
    const int* flow  = (const int*)d_in[4];
    const int* pos   = (const int*)d_in[5];
    const int* blk   = (const int*)d_in[6];
    int base = (in_sizes[7] == 8192 * 128) ? 7 : 8;
    const float* emb  = (const float*)d_in[base + 0];
    const float* femb = (const float*)d_in[base + 1];
    const float* pemb = (const float*)d_in[base + 2];
    const float* bemb = (const float*)d_in[base + 3];
    const float* Wq   = (const float*)d_in[base + 4];
    const float* Wk   = (const float*)d_in[base + 5];
    const float* Wv   = (const float*)d_in[base + 6];
    const float* Wek  = (const float*)d_in[base + 7];
    const float* Wev  = (const float*)d_in[base + 8];
    const float* Wo   = (const float*)d_in[base + 9];
    const float* Weu  = (const float*)d_in[base + 10];
    const float* QW1  = (const float*)d_in[base + 11];
    const float* Qb1  = (const float*)d_in[base + 12];
    const float* QW2  = (const float*)d_in[base + 13];
    const float* Qb2  = (const float*)d_in[base + 14];
    const int* src = ei;
    const int* dst = ei + EE;
    float* out = (float*)d_out;

    float *feat0, *feat1, *e0, *e1, *qf, *agg, *ga, *cn, *ce, *elut;
    __half *kvh, *PQh, *ekv;
    int *code, *cnt, *rowptr, *cursor, *csr, *psrc, *pdst, *pcode;
    __nv_bfloat16* pack;
    cudaGetSymbolAddress((void**)&feat0, g_feat0);
    cudaGetSymbolAddress((void**)&feat1, g_feat1);
    cudaGetSymbolAddress((void**)&e0, g_e0);
    cudaGetSymbolAddress((void**)&e1, g_e1);
    cudaGetSymbolAddress((void**)&qf, g_qf);
    cudaGetSymbolAddress((void**)&kvh, g_kvh);
    cudaGetSymbolAddress((void**)&PQh, g_PQh);
    cudaGetSymbolAddress((void**)&ekv, g_ekv);
    cudaGetSymbolAddress((void**)&agg, g_agg);
    cudaGetSymbolAddress((void**)&ga, g_ga);
    cudaGetSymbolAddress((void**)&cn, g_cn);
    cudaGetSymbolAddress((void**)&ce, g_ce);
    cudaGetSymbolAddress((void**)&code, g_code);
    cudaGetSymbolAddress((void**)&elut, g_elut);
    cudaGetSymbolAddress((void**)&cnt, g_cnt);
    cudaGetSymbolAddress((void**)&rowptr, g_rowptr);
    cudaGetSymbolAddress((void**)&cursor, g_cursor);
    cudaGetSymbolAddress((void**)&csr, g_csr);
    cudaGetSymbolAddress((void**)&psrc, g_psrc);
    cudaGetSymbolAddress((void**)&pdst, g_pdst);
    cudaGetSymbolAddress((void**)&pcode, g_pcode);
    cudaGetSymbolAddress((void**)&pack, g_pack);

    const int SMT1 = 69632 + 69632;        // NB=1
    const int SMT2 = 69632 + 2 * 69632;    // NB>=2 (208896)
    cudaFuncSetAttribute(mma_gemm<0>, cudaFuncAttributeMaxDynamicSharedMemorySize, SMT2);
    cudaFuncSetAttribute(mma_gemm<1>, cudaFuncAttributeMaxDynamicSharedMemorySize, SMT1);
    cudaFuncSetAttribute(mma_gemm<2>, cudaFuncAttributeMaxDynamicSharedMemorySize, SMT2);

    const int TPB = 256;
    const int gN32 = (NN * 32 + TPB - 1) / TPB;
    const int gE32 = (EE * 32 + TPB - 1) / TPB;
    const int gE   = (EE + TPB - 1) / TPB;
    const int GN = (NN + 127) / 128;
    const int GE = (EE + 127) / 128;

    // prologue: weights, embeddings, CSR build + permuted edge arrays
    k_packall<<<72, 256>>>(Wq, Wk, Wv, Wek, Wev, Wo, Weu, pack);
    k_node_embed<<<gN32, TPB>>>(x, emb, feat0);
    k_lut_e<<<1024, 128>>>(femb, pemb, bemb, elut);
    k_code<<<gE, TPB>>>(flow, pos, blk, src, dst, code);
    cudaMemsetAsync(cnt, 0, NN * sizeof(int));
    k_count<<<gE, TPB>>>(dst, cnt);
    k_scan<<<1, 1024>>>(cnt, rowptr, cursor);
    k_scatter<<<gE, TPB>>>(dst, cursor, csr);
    k_permute<<<gE, TPB>>>(csr, src, dst, code, psrc, pdst, pcode);
    k_expand_e<<<gE32, TPB>>>(pcode, elut, e0);   // e0 in CSR order

    float* fc = feat0; float* fn = feat1;
    float* ec = e0;    float* en = e1;

    for (int l = 0; l < LL; l++) {
        const __nv_bfloat16* pb = pack + (size_t)l * 9 * 32768;

        // node pass: q (fp32), k,v (half->kvh), P,Q (half->PQh) from fc
        {
            Outs o{}; o.C[0] = qf;
            mma_gemm<0><<<GN, 256, SMT2>>>(fc, pb, o, kvh, PQh, nullptr, nullptr,
                                           nullptr, nullptr, NN);
        }
        // edge pass: ek,ev (half, CSR order) + en, reading ec ONCE
        {
            Outs o{}; o.C[0] = en;
            mma_gemm<2><<<GE, 256, SMT2>>>(ec, pb + (size_t)5 * 32768, o, ekv, nullptr,
                                           nullptr, PQh, psrc, pdst, EE);
        }

        // fused attention (sequential ekv, L2-resident kv gathers)
        k_attn<<<gN32, TPB>>>(qf, kvh, ekv, psrc, rowptr, agg);

        // feat_new = relu(fc + agg@Wo)   (Wo at mt=8)
        {
            Outs o{}; o.C[0] = fn;
            mma_gemm<1><<<GN, 256, SMT1>>>(agg, pb + (size_t)8 * 32768, o, nullptr,
                                           nullptr, fc, nullptr, nullptr, nullptr, NN);
        }

        float* tf = fc; fc = fn; fn = tf;
        float* te = ec; ec = en; en = te;
    }

    cudaMemsetAsync(ga, 0, (size_t)GG * 256 * sizeof(float));
    cudaMemsetAsync(cn, 0, GG * sizeof(float));
    cudaMemsetAsync(ce, 0, GG * sizeof(float));
    k_gnode<<<gN32, TPB>>>(fc, ntype, batch, ga, cn);
    k_gedge<<<gE32, TPB>>>(ec, psrc, batch, ga, ce);
    k_head<<<GG, 128>>>(ga, cn, ce, QW1, Qb1, QW2, Qb2, out);
}

// round 13
// speedup vs baseline: 2.1014x; 1.0622x over previous
#include <cuda_runtime.h>
#include <cuda_bf16.h>
#include <cuda_fp16.h>
#include <math.h>
#include <stdint.h>

#define NN 100000
#define EE 500000
#define DD 128
#define LL 8
#define GG 64
#define AA 100

// ---------------- scratch (static device arrays; no cudaMalloc) -------------
__device__ float  g_feat0[(size_t)NN * DD];
__device__ float  g_feat1[(size_t)NN * DD];
__device__ __half g_e0[(size_t)EE * DD];       // edge feats fp16, CSR order
__device__ __half g_e1[(size_t)EE * DD];
__device__ float  g_qf[(size_t)NN * DD];       // q fp32
__device__ __half g_kvh[(size_t)NN * 256];     // k|v fp16
__device__ __half g_PQh[(size_t)NN * 256];     // P|Q fp16
__device__ __half g_ekv[(size_t)EE * 2 * DD];  // ek|ev fp16, CSR order
__device__ float  g_agg[(size_t)NN * DD];
__device__ float  g_ga[GG * 256];
__device__ float  g_cn[GG];
__device__ float  g_ce[GG];
__device__ int    g_code[EE];
__device__ float  g_elut[1024 * DD];
// CSR by dst (graph static across layers) + permuted edge arrays
__device__ int    g_cnt[NN];
__device__ int    g_rowptr[NN + 1];
__device__ int    g_cursor[NN];
__device__ int    g_csr[EE];
__device__ int    g_psrc[EE];
__device__ int    g_pdst[EE];
__device__ int    g_pcode[EE];
// packed weights: 8 layers x 9 mats x (16384 hi + 16384 lo) bf16, [k][n] row-major
// mat order: Wq,Wk,Wv,WeuS,WeuD,Wek,Wev,WeuE,Wo
__device__ __nv_bfloat16 g_pack[(size_t)LL * 9 * 32768];

// ---------------- PTX helpers (baseline features only) ----------------------
__device__ __forceinline__ uint32_t smem_u32(const void* p) {
    return (uint32_t)__cvta_generic_to_shared(p);
}
__device__ __forceinline__ void cp_async16(uint32_t smem, const void* gmem) {
    asm volatile("cp.async.cg.shared.global [%0], [%1], 16;\n" :: "r"(smem), "l"(gmem));
}
__device__ __forceinline__ void cp_commit() { asm volatile("cp.async.commit_group;\n"); }
__device__ __forceinline__ void cp_wait0() { asm volatile("cp.async.wait_group 0;\n"); }
__device__ __forceinline__ void cp_wait1() { asm volatile("cp.async.wait_group 1;\n"); }

__device__ __forceinline__ void ldmx4(uint32_t* r, uint32_t addr) {
    asm volatile("ldmatrix.sync.aligned.m8n8.x4.shared.b16 {%0,%1,%2,%3}, [%4];"
                 : "=r"(r[0]), "=r"(r[1]), "=r"(r[2]), "=r"(r[3]) : "r"(addr));
}
__device__ __forceinline__ void ldmx4t(uint32_t* r, uint32_t addr) {
    asm volatile("ldmatrix.sync.aligned.m8n8.x4.trans.shared.b16 {%0,%1,%2,%3}, [%4];"
                 : "=r"(r[0]), "=r"(r[1]), "=r"(r[2]), "=r"(r[3]) : "r"(addr));
}
__device__ __forceinline__ void mma_bf16(float* c, const uint32_t* a, const uint32_t* b) {
    asm volatile("mma.sync.aligned.m16n8k16.row.col.f32.bf16.bf16.f32 "
                 "{%0,%1,%2,%3}, {%4,%5,%6,%7}, {%8,%9}, {%0,%1,%2,%3};"
                 : "+f"(c[0]), "+f"(c[1]), "+f"(c[2]), "+f"(c[3])
                 : "r"(a[0]), "r"(a[1]), "r"(a[2]), "r"(a[3]), "r"(b[0]), "r"(b[1]));
}

// ---------------- weight pack: split hi/lo bf16, keep [k][n] layout ---------
__global__ void k_packall(const float* __restrict__ Wq, const float* __restrict__ Wk,
                          const float* __restrict__ Wv, const float* __restrict__ Wek,
                          const float* __restrict__ Wev, const float* __restrict__ Wo,
                          const float* __restrict__ Weu, __nv_bfloat16* __restrict__ pack)
{
    int b = blockIdx.x;        // 72 = 8 layers * 9 mats
    int l = b / 9, mt = b % 9;
    const float* W;
    switch (mt) {
        case 0: W = Wq  + (size_t)l * 16384; break;
        case 1: W = Wk  + (size_t)l * 16384; break;
        case 2: W = Wv  + (size_t)l * 16384; break;
        case 3: W = Weu + (size_t)l * 49152; break;           // WeuS
        case 4: W = Weu + (size_t)l * 49152 + 16384; break;   // WeuD
        case 5: W = Wek + (size_t)l * 16384; break;
        case 6: W = Wev + (size_t)l * 16384; break;
        case 7: W = Weu + (size_t)l * 49152 + 32768; break;   // WeuE
        default: W = Wo + (size_t)l * 16384; break;           // Wo
    }
    __nv_bfloat16* dst = pack + (size_t)b * 32768;
    for (int idx = threadIdx.x; idx < 16384; idx += blockDim.x) {
        float a = W[idx];
        __nv_bfloat16 h = __float2bfloat16(a);
        __nv_bfloat16 lo = __float2bfloat16(a - __bfloat162float(h));
        dst[idx] = h;
        dst[16384 + idx] = lo;
    }
}

// ---------------- multi-matrix tensor-core GEMM (bf16x3 split) --------------
// 512 threads, 16 warps, warp tile 32 rows x 32 cols
// KIND 0: node pass (A fp32), NB=5: j0 -> q fp32; j1,2 -> kvh half; j3,4 -> PQh half
// KIND 1: Wo pass (A fp32), NB=1: C = relu(R + A@B) fp32
// KIND 2: edge pass (A fp16), NB=3: j<2 -> half to HOa (ekv); j==2 ->
//         HOb = relu(A + A@B + P[psrc] + Q[pdst]) fp16 (A residual from smem split)
struct Outs { float* C[1]; };

template<int KIND>
__global__ void __launch_bounds__(512, 1) mma_gemm(
    const void* __restrict__ Av, const __nv_bfloat16* __restrict__ Bp, Outs outs,
    __half* __restrict__ HOa, __half* __restrict__ HOb,
    const float* __restrict__ R, const __half* __restrict__ PQh,
    const int* __restrict__ psrc, const int* __restrict__ pdst, int M)
{
    constexpr int NB = (KIND == 0) ? 5 : (KIND == 2) ? 3 : 1;
    extern __shared__ char smem[];
    const uint32_t sb = smem_u32(smem);
    const int tid = threadIdx.x;
    const int lane = tid & 31, wid = tid >> 5;
    const int wm = wid & 3, wn = wid >> 2;     // 4x4 warp grid (32 rows x 32 cols)
    const int m0 = blockIdx.x * 128;
    const int PS = 272;                        // padded row stride (bytes)
    const uint32_t OFF_AH = 0, OFF_AL = 34816;
    const uint32_t OFF_B0 = 69632, BUFSZ = 69632;   // per-buf: Bh | Bl

    // prefetch B0 into buf 0
    for (int idx = tid; idx < 4096; idx += 512) {
        int hl = idx >> 11, rem = idx & 2047, r = rem >> 4, c = rem & 15;
        cp_async16(sb + OFF_B0 + hl * 34816 + r * PS + c * 16,
                   (const char*)Bp + hl * 32768 + r * 256 + c * 16);
    }
    cp_commit();

    // A: load (fp32 or fp16), split bf16 hi/lo, store padded
    for (int idx = tid; idx < 4096; idx += 512) {
        int r = idx >> 5, f4 = idx & 31;
        int rg = m0 + r; if (rg >= M) rg = M - 1;
        float4 v;
        if (KIND == 2) {
            const __half* Ahp = (const __half*)Av;
            uint2 raw = *reinterpret_cast<const uint2*>(Ahp + (size_t)rg * 128 + f4 * 4);
            __half2 p01 = *reinterpret_cast<__half2*>(&raw.x);
            __half2 p23 = *reinterpret_cast<__half2*>(&raw.y);
            float2 f01 = __half22float2(p01), f23 = __half22float2(p23);
            v = make_float4(f01.x, f01.y, f23.x, f23.y);
        } else {
            v = *reinterpret_cast<const float4*>((const float*)Av + (size_t)rg * 128 + f4 * 4);
        }
        __nv_bfloat16 hx = __float2bfloat16(v.x), hy = __float2bfloat16(v.y);
        __nv_bfloat16 hz = __float2bfloat16(v.z), hw = __float2bfloat16(v.w);
        __nv_bfloat16 lx = __float2bfloat16(v.x - __bfloat162float(hx));
        __nv_bfloat16 ly = __float2bfloat16(v.y - __bfloat162float(hy));
        __nv_bfloat16 lz = __float2bfloat16(v.z - __bfloat162float(hz));
        __nv_bfloat16 lw = __float2bfloat16(v.w - __bfloat162float(hw));
        __nv_bfloat162 h01 = __halves2bfloat162(hx, hy), h23 = __halves2bfloat162(hz, hw);
        __nv_bfloat162 l01 = __halves2bfloat162(lx, ly), l23 = __halves2bfloat162(lz, lw);
        int off = r * PS + f4 * 8;
        *reinterpret_cast<uint2*>(smem + OFF_AH + off) =
            make_uint2(*(uint32_t*)&h01, *(uint32_t*)&h23);
        *reinterpret_cast<uint2*>(smem + OFF_AL + off) =
            make_uint2(*(uint32_t*)&l01, *(uint32_t*)&l23);
    }

#pragma unroll
    for (int j = 0; j < NB; j++) {
        if (j + 1 < NB) {
            const uint32_t dstb = sb + OFF_B0 + ((j + 1) & 1) * BUFSZ;
            const char* srcb = (const char*)Bp + (size_t)(j + 1) * 65536;
            for (int idx = tid; idx < 4096; idx += 512) {
                int hl = idx >> 11, rem = idx & 2047, r = rem >> 4, c = rem & 15;
                cp_async16(dstb + hl * 34816 + r * PS + c * 16,
                           srcb + hl * 32768 + r * 256 + c * 16);
            }
            cp_commit();
            cp_wait1();
        } else {
            cp_wait0();
        }
        __syncthreads();

        float acc[2][4][4];
#pragma unroll
        for (int i = 0; i < 2; i++)
#pragma unroll
            for (int n = 0; n < 4; n++)
#pragma unroll
                for (int q = 0; q < 4; q++) acc[i][n][q] = 0.f;

        const uint32_t Bbuf = sb + OFF_B0 + (j & 1) * BUFSZ;
#pragma unroll
        for (int term = 0; term < 3; term++) {
            const uint32_t Ab = sb + (term == 2 ? OFF_AL : OFF_AH);
            const uint32_t Bb = Bbuf + (term == 1 ? 34816 : 0);
            const uint32_t aBase = Ab + (wm * 32 + (lane & 15)) * PS + (lane >> 4) * 16;
            const int bg = lane >> 3, br = lane & 7;
            // warp covers cols [wn*32, wn*32+32): 2 ldmx4t per ks (16 cols each)
            const uint32_t bBase = Bb + ((bg & 1) * 8 + br) * PS + wn * 64 + (bg >> 1) * 16;
#pragma unroll
            for (int ks = 0; ks < 8; ks++) {
                uint32_t a0[4], a1[4], bf[4][2];
                ldmx4(a0, aBase + ks * 32);
                ldmx4(a1, aBase + 16 * PS + ks * 32);
#pragma unroll
                for (int p = 0; p < 2; p++) {
                    uint32_t t4[4];
                    ldmx4t(t4, bBase + ks * 16 * PS + p * 32);
                    bf[2 * p][0] = t4[0]; bf[2 * p][1] = t4[1];
                    bf[2 * p + 1][0] = t4[2]; bf[2 * p + 1][1] = t4[3];
                }
#pragma unroll
                for (int nt = 0; nt < 4; nt++) {
                    mma_bf16(acc[0][nt], a0, bf[nt]);
                    mma_bf16(acc[1][nt], a1, bf[nt]);
                }
            }
        }

        // ----- epilogue (warp tile 32x32) -----
#pragma unroll
        for (int mt = 0; mt < 2; mt++) {
#pragma unroll
            for (int h = 0; h < 2; h++) {
                int rl = wm * 32 + mt * 16 + (lane >> 2) + h * 8;
                int row = m0 + rl;
                if (row >= M) continue;
                if (KIND == 0 && j >= 1) {
                    __half* HP = (j <= 2) ? HOa : HOb;
                    int co = ((j - 1) & 1) * 128;
#pragma unroll
                    for (int nt = 0; nt < 4; nt++) {
                        int col = wn * 32 + nt * 8 + (lane & 3) * 2;
                        __half2 hv = __floats2half2_rn(acc[mt][nt][h * 2],
                                                       acc[mt][nt][h * 2 + 1]);
                        *reinterpret_cast<__half2*>(HP + (size_t)row * 256 + co + col) = hv;
                    }
                } else if (KIND == 2 && j < 2) {
#pragma unroll
                    for (int nt = 0; nt < 4; nt++) {
                        int col = wn * 32 + nt * 8 + (lane & 3) * 2;
                        __half2 hv = __floats2half2_rn(acc[mt][nt][h * 2],
                                                       acc[mt][nt][h * 2 + 1]);
                        *reinterpret_cast<__half2*>(HOa + (size_t)row * 256 + j * 128 + col) = hv;
                    }
                } else if (KIND == 2) {
                    // j==2: en(fp16) = relu(A + A@B + P[src] + Q[dst])
                    int s = psrc[row], d = pdst[row];
#pragma unroll
                    for (int nt = 0; nt < 4; nt++) {
                        int col = wn * 32 + nt * 8 + (lane & 3) * 2;
                        float vx = acc[mt][nt][h * 2], vy = acc[mt][nt][h * 2 + 1];
                        int aoff = rl * PS + col * 2;
                        __nv_bfloat162 hh = *reinterpret_cast<__nv_bfloat162*>(smem + OFF_AH + aoff);
                        __nv_bfloat162 ll = *reinterpret_cast<__nv_bfloat162*>(smem + OFF_AL + aoff);
                        vx += __bfloat162float(hh.x) + __bfloat162float(ll.x);
                        vy += __bfloat162float(hh.y) + __bfloat162float(ll.y);
                        float2 pv = __half22float2(
                            *reinterpret_cast<const __half2*>(PQh + (size_t)s * 256 + col));
                        float2 qv = __half22float2(
                            *reinterpret_cast<const __half2*>(PQh + (size_t)d * 256 + 128 + col));
                        vx += pv.x + qv.x; vy += pv.y + qv.y;
                        vx = fmaxf(vx, 0.f); vy = fmaxf(vy, 0.f);
                        *reinterpret_cast<__half2*>(HOb + (size_t)row * 128 + col) =
                            __floats2half2_rn(vx, vy);
                    }
                } else {
                    float* C = outs.C[0];
#pragma unroll
                    for (int nt = 0; nt < 4; nt++) {
                        int col = wn * 32 + nt * 8 + (lane & 3) * 2;
                        float vx = acc[mt][nt][h * 2], vy = acc[mt][nt][h * 2 + 1];
                        if (KIND == 1) {
                            float2 rv = *reinterpret_cast<const float2*>(R + (size_t)row * 128 + col);
                            vx += rv.x; vy += rv.y;
                            vx = fmaxf(vx, 0.f); vy = fmaxf(vy, 0.f);
                        }
                        *reinterpret_cast<float2*>(C + (size_t)row * 128 + col) =
                            make_float2(vx, vy);
                    }
                }
            }
        }
        __syncthreads();   // protect B buffer reuse
    }
}

// ---------------- CSR build + edge permutation ------------------------------
__global__ void k_count(const int* __restrict__ dst, int* __restrict__ cnt) {
    int e = blockIdx.x * blockDim.x + threadIdx.x;
    if (e < EE) atomicAdd(&cnt[dst[e]], 1);
}

__global__ void k_scan(const int* __restrict__ cnt, int* __restrict__ rowptr,
                       int* __restrict__ cursor) {
    __shared__ int part[1024];
    const int t = threadIdx.x;
    const int CH = (NN + 1023) / 1024;
    int s = 0;
    for (int i = 0; i < CH; i++) {
        int idx = t * CH + i;
        if (idx < NN) s += cnt[idx];
    }
    part[t] = s;
    __syncthreads();
    for (int off = 1; off < 1024; off <<= 1) {
        int v = 0;
        if (t >= off) v = part[t - off];
        __syncthreads();
        if (t >= off) part[t] += v;
        __syncthreads();
    }
    int base = (t > 0) ? part[t - 1] : 0;
    for (int i = 0; i < CH; i++) {
        int idx = t * CH + i;
        if (idx < NN) {
            rowptr[idx] = base;
            cursor[idx] = base;
            base += cnt[idx];
        }
    }
    if (t == 1023) rowptr[NN] = EE;
}

__global__ void k_scatter(const int* __restrict__ dst, int* __restrict__ cursor,
                          int* __restrict__ csr) {
    int e = blockIdx.x * blockDim.x + threadIdx.x;
    if (e >= EE) return;
    int pos = atomicAdd(&cursor[dst[e]], 1);
    csr[pos] = e;
}

__global__ void k_permute(const int* __restrict__ csr, const int* __restrict__ src,
                          const int* __restrict__ dst, const int* __restrict__ code,
                          int* __restrict__ psrc, int* __restrict__ pdst,
                          int* __restrict__ pcode) {
    int i = blockIdx.x * blockDim.x + threadIdx.x;
    if (i >= EE) return;
    int e = csr[i];
    psrc[i] = src[e];
    pdst[i] = dst[e];
    pcode[i] = code[e];
}

// ---------------- fused attention: warp per dst node, online softmax --------
__global__ void k_attn(const float* __restrict__ qf, const __half* __restrict__ kvh,
                       const __half* __restrict__ ekv, const int* __restrict__ psrc,
                       const int* __restrict__ rowptr, float* __restrict__ agg)
{
    int w = (blockIdx.x * blockDim.x + threadIdx.x) >> 5;
    int lane = threadIdx.x & 31;
    if (w >= NN) return;
    const int beg = rowptr[w], end = rowptr[w + 1];

    float4 q4 = *reinterpret_cast<const float4*>(qf + (size_t)w * 128 + lane * 4);
    float m = -3.4e38f, den = 0.f;
    float a0 = 0.f, a1 = 0.f, a2 = 0.f, a3 = 0.f;

    for (int i = beg; i < end; i++) {
        int s = psrc[i];
        const __half2* kp = reinterpret_cast<const __half2*>(kvh + (size_t)s * 256) + lane * 2;
        float2 k01 = __half22float2(kp[0]), k23 = __half22float2(kp[1]);
        float2 v01 = __half22float2(kp[64]), v23 = __half22float2(kp[65]);
        const __half2* ep = reinterpret_cast<const __half2*>(ekv + (size_t)i * 256) + lane * 2;
        float2 ek01 = __half22float2(ep[0]), ek23 = __half22float2(ep[1]);
        float2 ev01 = __half22float2(ep[64]), ev23 = __half22float2(ep[65]);

        float p = q4.x * (k01.x + ek01.x) + q4.y * (k01.y + ek01.y) +
                  q4.z * (k23.x + ek23.x) + q4.w * (k23.y + ek23.y);
        p += __shfl_xor_sync(0xffffffffu, p, 4);
        p += __shfl_xor_sync(0xffffffffu, p, 2);
        p += __shfl_xor_sync(0xffffffffu, p, 1);
        p *= 0.17677669529663687f;   // 1/sqrt(32)

        float nm = fmaxf(m, p);
        float f = __expf(m - nm);
        float ex = __expf(p - nm);
        den = den * f + ex;
        a0 = a0 * f + ex * (v01.x + ev01.x);
        a1 = a1 * f + ex * (v01.y + ev01.y);
        a2 = a2 * f + ex * (v23.x + ev23.x);
        a3 = a3 * f + ex * (v23.y + ev23.y);
        m = nm;
    }
    float inv = (den > 0.f) ? 1.f / den : 0.f;
    *reinterpret_cast<float4*>(agg + (size_t)w * 128 + lane * 4) =
        make_float4(a0 * inv, a1 * inv, a2 * inv, a3 * inv);
}

// ---------------- misc elementwise kernels ----------------------------------
__global__ void k_node_embed(const int* __restrict__ x, const float* __restrict__ emb,
                             float* __restrict__ feat) {
    unsigned t = blockIdx.x * blockDim.x + threadIdx.x;
    if (t >= (unsigned)NN * 32u) return;
    int n = t >> 5, q = t & 31;
    float4 v = *reinterpret_cast<const float4*>(emb + (size_t)x[n] * 128 + q * 4);
    *reinterpret_cast<float4*>(feat + (size_t)n * 128 + q * 4) = v;
}

__global__ void k_lut_e(const float* __restrict__ femb, const float* __restrict__ pemb,
                        const float* __restrict__ bemb, float* __restrict__ elut) {
    int c = blockIdx.x, t = threadIdx.x;
    elut[c * 128 + t] = femb[(c >> 7) * 128 + t] + pemb[((c >> 1) & 63) * 128 + t] +
                        bemb[(c & 1) * 128 + t];
}

__global__ void k_code(const int* __restrict__ flow, const int* __restrict__ pos,
                       const int* __restrict__ blk, const int* __restrict__ src,
                       const int* __restrict__ dst, int* __restrict__ code) {
    int e = blockIdx.x * blockDim.x + threadIdx.x;
    if (e >= EE) return;
    int cr = (blk[src[e]] != blk[dst[e]]) ? 1 : 0;
    code[e] = (flow[e] << 7) | (pos[e] << 1) | cr;
}

__global__ void k_expand_e(const int* __restrict__ pcode, const float* __restrict__ elut,
                           __half* __restrict__ e) {
    unsigned t = blockIdx.x * blockDim.x + threadIdx.x;
    if (t >= (unsigned)EE * 32u) return;
    int ed = t >> 5, q = t & 31;
    float4 v = *reinterpret_cast<const float4*>(elut + (size_t)pcode[ed] * 128 + q * 4);
    __half2 h0 = __floats2half2_rn(v.x, v.y);
    __half2 h1 = __floats2half2_rn(v.z, v.w);
    uint2 packed = make_uint2(*(uint32_t*)&h0, *(uint32_t*)&h1);
    *reinterpret_cast<uint2*>(e + (size_t)ed * 128 + q * 4) = packed;
}

__global__ void k_gnode(const float* __restrict__ feat, const int* __restrict__ ntype,
                        const int* __restrict__ batch, float* __restrict__ ga,
                        float* __restrict__ cn)
{
    unsigned t = blockIdx.x * blockDim.x + threadIdx.x;
    if (t >= (unsigned)NN * 32u) return;
    int n = t >> 5, q = t & 31;
    if (ntype[n] != 0) return;
    int b = batch[n];
    float4 f = *reinterpret_cast<const float4*>(feat + (size_t)n * 128 + q * 4);
    float* p = ga + (size_t)b * 256 + q * 4;
    atomicAdd(p + 0, f.x); atomicAdd(p + 1, f.y);
    atomicAdd(p + 2, f.z); atomicAdd(p + 3, f.w);
    if (q == 0) atomicAdd(&cn[b], 1.f);
}

__global__ void k_gedge(const __half* __restrict__ e, const int* __restrict__ psrc,
                        const int* __restrict__ batch, float* __restrict__ ga,
                        float* __restrict__ ce)
{
    unsigned t = blockIdx.x * blockDim.x + threadIdx.x;
    if (t >= (unsigned)EE * 32u) return;
    int ed = t >> 5, q = t & 31;
    int b = batch[psrc[ed]];
    uint2 raw = *reinterpret_cast<const uint2*>(e + (size_t)ed * 128 + q * 4);
    __half2 p01 = *reinterpret_cast<__half2*>(&raw.x);
    __half2 p23 = *reinterpret_cast<__half2*>(&raw.y);
    float2 f01 = __half22float2(p01), f23 = __half22float2(p23);
    float* p = ga + (size_t)b * 256 + 128 + q * 4;
    atomicAdd(p + 0, f01.x); atomicAdd(p + 1, f01.y);
    atomicAdd(p + 2, f23.x); atomicAdd(p + 3, f23.y);
    if (q == 0) atomicAdd(&ce[b], 1.f);
}

__global__ void k_head(const float* __restrict__ ga, const float* __restrict__ cn,
                       const float* __restrict__ ce,
                       const float* __restrict__ QW1, const float* __restrict__ Qb1,
                       const float* __restrict__ QW2, const float* __restrict__ Qb2,
                       float* __restrict__ out)
{
    int g = blockIdx.x;
    int t = threadIdx.x;  // 128
    __shared__ float s_in[256];
    __shared__ float s_h[128];
    __shared__ float s_l[128];
    __shared__ float s_max, s_lse;
    float nc = fmaxf(cn[g], 1.0f);
    float ec = fmaxf(ce[g], 1.0f);
    s_in[t]       = ga[(size_t)g * 256 + t] / nc;
    s_in[t + 128] = ga[(size_t)g * 256 + 128 + t] / ec;
    __syncthreads();
    float acc = Qb1[t];
    for (int k = 0; k < 256; k++) acc = fmaf(s_in[k], QW1[(size_t)k * 128 + t], acc);
    s_h[t] = fmaxf(acc, 0.f);
    __syncthreads();
    float lg = 0.f;
    if (t < AA) {
        lg = Qb2[t];
        for (int k = 0; k < 128; k++) lg = fmaf(s_h[k], QW2[(size_t)k * AA + t], lg);
        s_l[t] = lg;
    }
    __syncthreads();
    if (t == 0) {
        float mx = -3.4e38f;
        for (int i = 0; i < AA; i++) mx = fmaxf(mx, s_l[i]);
        float s = 0.f;
        for (int i = 0; i < AA; i++) s += expf(s_l[i] - mx);
        s_max = mx;
        s_lse = logf(s);
    }
    __syncthreads();
    if (t < AA) out[(size_t)g * AA + t] = lg - s_max - s_lse;
}

// ---------------- launch ------------------------------------------------------
extern "C" void kernel_launch(void* const* d_in, const int* in_sizes, int n_in,
                              void* d_out, int out_size)
{
    const int* x     = (const int*)d_in[0];
    const int* ntype = (const int*)d_in[1];
    const int* batch = (const int*)d_in[2];
    const int* ei    = (const int*)d_in[3];
    const int* flow  = (const int*)d_in[4];
    const int* pos   = (const int*)d_in[5];
    const int* blk   = (const int*)d_in[6];
    int base = (in_sizes[7] == 8192 * 128) ? 7 : 8;
    const float* emb  = (const float*)d_in[base + 0];
    const float* femb = (const float*)d_in[base + 1];
    const float* pemb = (const float*)d_in[base + 2];
    const float* bemb = (const float*)d_in[base + 3];
    const float* Wq   = (const float*)d_in[base + 4];
    const float* Wk   = (const float*)d_in[base + 5];
    const float* Wv   = (const float*)d_in[base + 6];
    const float* Wek  = (const float*)d_in[base + 7];
    const float* Wev  = (const float*)d_in[base + 8];
    const float* Wo   = (const float*)d_in[base + 9];
    const float* Weu  = (const float*)d_in[base + 10];
    const float* QW1  = (const float*)d_in[base + 11];
    const float* Qb1  = (const float*)d_in[base + 12];
    const float* QW2  = (const float*)d_in[base + 13];
    const float* Qb2  = (const float*)d_in[base + 14];
    const int* src = ei;
    const int* dst = ei + EE;
    float* out = (float*)d_out;

    float *feat0, *feat1, *qf, *agg, *ga, *cn, *ce, *elut;
    __half *e0, *e1, *kvh, *PQh, *ekv;
    int *code, *cnt, *rowptr, *cursor, *csr, *psrc, *pdst, *pcode;
    __nv_bfloat16* pack;
    cudaGetSymbolAddress((void**)&feat0, g_feat0);
    cudaGetSymbolAddress((void**)&feat1, g_feat1);
    cudaGetSymbolAddress((void**)&e0, g_e0);
    cudaGetSymbolAddress((void**)&e1, g_e1);
    cudaGetSymbolAddress((void**)&qf, g_qf);
    cudaGetSymbolAddress((void**)&kvh, g_kvh);
    cudaGetSymbolAddress((void**)&PQh, g_PQh);
    cudaGetSymbolAddress((void**)&ekv, g_ekv);
    cudaGetSymbolAddress((void**)&agg, g_agg);
    cudaGetSymbolAddress((void**)&ga, g_ga);
    cudaGetSymbolAddress((void**)&cn, g_cn);
    cudaGetSymbolAddress((void**)&ce, g_ce);
    cudaGetSymbolAddress((void**)&code, g_code);
    cudaGetSymbolAddress((void**)&elut, g_elut);
    cudaGetSymbolAddress((void**)&cnt, g_cnt);
    cudaGetSymbolAddress((void**)&rowptr, g_rowptr);
    cudaGetSymbolAddress((void**)&cursor, g_cursor);
    cudaGetSymbolAddress((void**)&csr, g_csr);
    cudaGetSymbolAddress((void**)&psrc, g_psrc);
    cudaGetSymbolAddress((void**)&pdst, g_pdst);
    cudaGetSymbolAddress((void**)&pcode, g_pcode);
    cudaGetSymbolAddress((void**)&pack, g_pack);

    const int SMT1 = 69632 + 69632;        // NB=1
    const int SMT2 = 69632 + 2 * 69632;    // NB>=2 (208896)
    cudaFuncSetAttribute(mma_gemm<0>, cudaFuncAttributeMaxDynamicSharedMemorySize, SMT2);
    cudaFuncSetAttribute(mma_gemm<1>, cudaFuncAttributeMaxDynamicSharedMemorySize, SMT1);
    cudaFuncSetAttribute(mma_gemm<2>, cudaFuncAttributeMaxDynamicSharedMemorySize, SMT2);

    const int TPB = 256;
    const int gN32 = (NN * 32 + TPB - 1) / TPB;
    const int gE32 = (EE * 32 + TPB - 1) / TPB;
    const int gE   = (EE + TPB - 1) / TPB;
    const int GN = (NN + 127) / 128;
    const int GE = (EE + 127) / 128;

    // prologue: weights, embeddings, CSR build + permuted edge arrays
    k_packall<<<72, 256>>>(Wq, Wk, Wv, Wek, Wev, Wo, Weu, pack);
    k_node_embed<<<gN32, TPB>>>(x, emb, feat0);
    k_lut_e<<<1024, 128>>>(femb, pemb, bemb, elut);
    k_code<<<gE, TPB>>>(flow, pos, blk, src, dst, code);
    cudaMemsetAsync(cnt, 0, NN * sizeof(int));
    k_count<<<gE, TPB>>>(dst, cnt);
    k_scan<<<1, 1024>>>(cnt, rowptr, cursor);
    k_scatter<<<gE, TPB>>>(dst, cursor, csr);
    k_permute<<<gE, TPB>>>(csr, src, dst, code, psrc, pdst, pcode);
    k_expand_e<<<gE32, TPB>>>(pcode, elut, e0);   // e0 fp16, CSR order

    float* fc = feat0; float* fn = feat1;
    __half* ec = e0;   __half* en = e1;

    for (int l = 0; l < LL; l++) {
        const __nv_bfloat16* pb = pack + (size_t)l * 9 * 32768;

        // node pass: q (fp32), k,v (half->kvh), P,Q (half->PQh) from fc
        {
            Outs o{}; o.C[0] = qf;
            mma_gemm<0><<<GN, 512, SMT2>>>(fc, pb, o, kvh, PQh, nullptr, nullptr,
                                           nullptr, nullptr, NN);
        }
        // edge pass: ek,ev (half, CSR order) + en (half), reading ec ONCE
        {
            Outs o{};
            mma_gemm<2><<<GE, 512, SMT2>>>(ec, pb + (size_t)5 * 32768, o, ekv, en,
                                           nullptr, PQh, psrc, pdst, EE);
        }

        // fused attention (sequential ekv, L2-resident kv gathers)
        k_attn<<<gN32, TPB>>>(qf, kvh, ekv, psrc, rowptr, agg);

        // feat_new = relu(fc + agg@Wo)   (Wo at mt=8)
        {
            Outs o{}; o.C[0] = fn;
            mma_gemm<1><<<GN, 512, SMT1>>>(agg, pb + (size_t)8 * 32768, o, nullptr,
                                           nullptr, fc, nullptr, nullptr, nullptr, NN);
        }

        float* tf = fc; fc = fn; fn = tf;
        __half* te = ec; ec = en; en = te;
    }

    cudaMemsetAsync(ga, 0, (size_t)GG * 256 * sizeof(float));
    cudaMemsetAsync(cn, 0, GG * sizeof(float));
    cudaMemsetAsync(ce, 0, GG * sizeof(float));
    k_gnode<<<gN32, TPB>>>(fc, ntype, batch, ga, cn);
    k_gedge<<<gE32, TPB>>>(ec, psrc, batch, ga, ce);
    k_head<<<GG, 128>>>(ga, cn, ce, QW1, Qb1, QW2, Qb2, out);
}

// round 14
// speedup vs baseline: 3.0900x; 1.4704x over previous
#include <cuda_runtime.h>
#include <cuda_fp16.h>
#include <math.h>
#include <stdint.h>

#define NN 100000
#define EE 500000
#define DD 128
#define LL 8
#define GG 64
#define AA 100

// ---------------- scratch (static device arrays; no cudaMalloc) -------------
__device__ __half g_feat0[(size_t)NN * DD];    // node feats fp16
__device__ __half g_feat1[(size_t)NN * DD];
__device__ __half g_e0[(size_t)EE * DD];       // edge feats fp16, CSR order
__device__ __half g_e1[(size_t)EE * DD];
__device__ float  g_qf[(size_t)NN * DD];       // q fp32
__device__ __half g_kvh[(size_t)NN * 256];     // k|v fp16
__device__ __half g_PQh[(size_t)NN * 256];     // P|Q fp16
__device__ __half g_ekv[(size_t)EE * 2 * DD];  // ek|ev fp16, CSR order
__device__ __half g_aggh[(size_t)NN * DD];     // attention output fp16
__device__ float  g_ga[GG * 256];
__device__ float  g_cn[GG];
__device__ float  g_ce[GG];
__device__ int    g_code[EE];
__device__ float  g_elut[1024 * DD];
// CSR by dst (graph static across layers) + permuted edge arrays
__device__ int    g_cnt[NN];
__device__ int    g_rowptr[NN + 1];
__device__ int    g_cursor[NN];
__device__ int    g_csr[EE];
__device__ int    g_psrc[EE];
__device__ int    g_pdst[EE];
__device__ int    g_pcode[EE];
// packed weights: 8 layers x 9 mats x (16384 hi + 16384 lo) fp16, [k][n] row-major
// mat order: Wq,Wk,Wv,WeuS,WeuD,Wek,Wev,WeuE,Wo
__device__ __half g_pack[(size_t)LL * 9 * 32768];

// ---------------- PTX helpers (baseline features only) ----------------------
__device__ __forceinline__ uint32_t smem_u32(const void* p) {
    return (uint32_t)__cvta_generic_to_shared(p);
}
__device__ __forceinline__ void cp_async16(uint32_t smem, const void* gmem) {
    asm volatile("cp.async.cg.shared.global [%0], [%1], 16;\n" :: "r"(smem), "l"(gmem));
}
__device__ __forceinline__ void cp_commit() { asm volatile("cp.async.commit_group;\n"); }
__device__ __forceinline__ void cp_wait0() { asm volatile("cp.async.wait_group 0;\n"); }
__device__ __forceinline__ void cp_wait1() { asm volatile("cp.async.wait_group 1;\n"); }

__device__ __forceinline__ void ldmx4(uint32_t* r, uint32_t addr) {
    asm volatile("ldmatrix.sync.aligned.m8n8.x4.shared.b16 {%0,%1,%2,%3}, [%4];"
                 : "=r"(r[0]), "=r"(r[1]), "=r"(r[2]), "=r"(r[3]) : "r"(addr));
}
__device__ __forceinline__ void ldmx4t(uint32_t* r, uint32_t addr) {
    asm volatile("ldmatrix.sync.aligned.m8n8.x4.trans.shared.b16 {%0,%1,%2,%3}, [%4];"
                 : "=r"(r[0]), "=r"(r[1]), "=r"(r[2]), "=r"(r[3]) : "r"(addr));
}
__device__ __forceinline__ void mma_f16(float* c, const uint32_t* a, const uint32_t* b) {
    asm volatile("mma.sync.aligned.m16n8k16.row.col.f32.f16.f16.f32 "
                 "{%0,%1,%2,%3}, {%4,%5,%6,%7}, {%8,%9}, {%0,%1,%2,%3};"
                 : "+f"(c[0]), "+f"(c[1]), "+f"(c[2]), "+f"(c[3])
                 : "r"(a[0]), "r"(a[1]), "r"(a[2]), "r"(a[3]), "r"(b[0]), "r"(b[1]));
}

// ---------------- weight pack: split fp16 hi/lo, keep [k][n] layout ---------
__global__ void k_packall(const float* __restrict__ Wq, const float* __restrict__ Wk,
                          const float* __restrict__ Wv, const float* __restrict__ Wek,
                          const float* __restrict__ Wev, const float* __restrict__ Wo,
                          const float* __restrict__ Weu, __half* __restrict__ pack)
{
    int b = blockIdx.x;        // 72 = 8 layers * 9 mats
    int l = b / 9, mt = b % 9;
    const float* W;
    switch (mt) {
        case 0: W = Wq  + (size_t)l * 16384; break;
        case 1: W = Wk  + (size_t)l * 16384; break;
        case 2: W = Wv  + (size_t)l * 16384; break;
        case 3: W = Weu + (size_t)l * 49152; break;           // WeuS
        case 4: W = Weu + (size_t)l * 49152 + 16384; break;   // WeuD
        case 5: W = Wek + (size_t)l * 16384; break;
        case 6: W = Wev + (size_t)l * 16384; break;
        case 7: W = Weu + (size_t)l * 49152 + 32768; break;   // WeuE
        default: W = Wo + (size_t)l * 16384; break;           // Wo
    }
    __half* dst = pack + (size_t)b * 32768;
    for (int idx = threadIdx.x; idx < 16384; idx += blockDim.x) {
        float a = W[idx];
        __half h = __float2half_rn(a);
        __half lo = __float2half_rn(a - __half2float(h));
        dst[idx] = h;
        dst[16384 + idx] = lo;
    }
}

// ---------------- multi-matrix fp16 tensor-core GEMM (B split hi/lo) --------
// 512 threads, 16 warps, warp tile 32 rows x 32 cols; A fp16 (no split)
// KIND 0: node pass, NB=5: j0 -> q fp32 (outs.C[0]); j1,2 -> HOa (kvh); j3,4 -> HOb (PQh)
// KIND 1: Wo pass, NB=1: HOa = relu(Rh + A@B) fp16
// KIND 2: edge pass, NB=3: j<2 -> HOa (ekv); j==2 ->
//         HOb = relu(A + A@B + P[psrc] + Q[pdst]) fp16 (A residual from smem)
struct Outs { float* C[1]; };

template<int KIND>
__global__ void __launch_bounds__(512, 1) mma_gemm(
    const __half* __restrict__ A, const __half* __restrict__ Bp, Outs outs,
    __half* __restrict__ HOa, __half* __restrict__ HOb,
    const __half* __restrict__ Rh, const __half* __restrict__ PQh,
    const int* __restrict__ psrc, const int* __restrict__ pdst, int M)
{
    constexpr int NB = (KIND == 0) ? 5 : (KIND == 2) ? 3 : 1;
    extern __shared__ char smem[];
    const uint32_t sb = smem_u32(smem);
    const int tid = threadIdx.x;
    const int lane = tid & 31, wid = tid >> 5;
    const int wm = wid & 3, wn = wid >> 2;     // 4x4 warp grid (32 rows x 32 cols)
    const int m0 = blockIdx.x * 128;
    const int PS = 272;                        // padded row stride (bytes)
    const uint32_t OFF_A = 0;                  // 128 rows x 272 = 34816
    const uint32_t OFF_B0 = 34816, BUFSZ = 69632;   // per-buf: Bh | Bl

    // group 1: prefetch B0
    for (int idx = tid; idx < 4096; idx += 512) {
        int hl = idx >> 11, rem = idx & 2047, r = rem >> 4, c = rem & 15;
        cp_async16(sb + OFF_B0 + hl * 34816 + r * PS + c * 16,
                   (const char*)Bp + hl * 32768 + r * 256 + c * 16);
    }
    cp_commit();

    // group 2: A fp16 straight copy (row = 256 bytes = 16 chunks)
    for (int idx = tid; idx < 2048; idx += 512) {
        int r = idx >> 4, c = idx & 15;
        int rg = m0 + r; if (rg >= M) rg = M - 1;
        cp_async16(sb + OFF_A + r * PS + c * 16,
                   (const char*)A + (size_t)rg * 256 + c * 16);
    }
    cp_commit();

#pragma unroll
    for (int j = 0; j < NB; j++) {
        if (j + 1 < NB) {
            const uint32_t dstb = sb + OFF_B0 + ((j + 1) & 1) * BUFSZ;
            const char* srcb = (const char*)Bp + (size_t)(j + 1) * 65536;
            for (int idx = tid; idx < 4096; idx += 512) {
                int hl = idx >> 11, rem = idx & 2047, r = rem >> 4, c = rem & 15;
                cp_async16(dstb + hl * 34816 + r * PS + c * 16,
                           srcb + hl * 32768 + r * 256 + c * 16);
            }
            cp_commit();
            cp_wait1();
        } else {
            cp_wait0();
        }
        __syncthreads();

        float acc[2][4][4];
#pragma unroll
        for (int i = 0; i < 2; i++)
#pragma unroll
            for (int n = 0; n < 4; n++)
#pragma unroll
                for (int q = 0; q < 4; q++) acc[i][n][q] = 0.f;

        const uint32_t Bbuf = sb + OFF_B0 + (j & 1) * BUFSZ;
        const uint32_t aBase = sb + OFF_A + (wm * 32 + (lane & 15)) * PS + (lane >> 4) * 16;
        const int bg = lane >> 3, br = lane & 7;
        // 2 terms: B hi, B lo (A fp16 is exact)
#pragma unroll
        for (int term = 0; term < 2; term++) {
            const uint32_t Bb = Bbuf + (term == 1 ? 34816 : 0);
            const uint32_t bBase = Bb + ((bg & 1) * 8 + br) * PS + wn * 64 + (bg >> 1) * 16;
#pragma unroll
            for (int ks = 0; ks < 8; ks++) {
                uint32_t a0[4], a1[4], bf[4][2];
                ldmx4(a0, aBase + ks * 32);
                ldmx4(a1, aBase + 16 * PS + ks * 32);
#pragma unroll
                for (int p = 0; p < 2; p++) {
                    uint32_t t4[4];
                    ldmx4t(t4, bBase + ks * 16 * PS + p * 32);
                    bf[2 * p][0] = t4[0]; bf[2 * p][1] = t4[1];
                    bf[2 * p + 1][0] = t4[2]; bf[2 * p + 1][1] = t4[3];
                }
#pragma unroll
                for (int nt = 0; nt < 4; nt++) {
                    mma_f16(acc[0][nt], a0, bf[nt]);
                    mma_f16(acc[1][nt], a1, bf[nt]);
                }
            }
        }

        // ----- epilogue (warp tile 32x32) -----
#pragma unroll
        for (int mt = 0; mt < 2; mt++) {
#pragma unroll
            for (int h = 0; h < 2; h++) {
                int rl = wm * 32 + mt * 16 + (lane >> 2) + h * 8;
                int row = m0 + rl;
                if (row >= M) continue;
                if (KIND == 0 && j == 0) {
                    float* C = outs.C[0];
#pragma unroll
                    for (int nt = 0; nt < 4; nt++) {
                        int col = wn * 32 + nt * 8 + (lane & 3) * 2;
                        *reinterpret_cast<float2*>(C + (size_t)row * 128 + col) =
                            make_float2(acc[mt][nt][h * 2], acc[mt][nt][h * 2 + 1]);
                    }
                } else if (KIND == 0) {
                    __half* HP = (j <= 2) ? HOa : HOb;
                    int co = ((j - 1) & 1) * 128;
#pragma unroll
                    for (int nt = 0; nt < 4; nt++) {
                        int col = wn * 32 + nt * 8 + (lane & 3) * 2;
                        *reinterpret_cast<__half2*>(HP + (size_t)row * 256 + co + col) =
                            __floats2half2_rn(acc[mt][nt][h * 2], acc[mt][nt][h * 2 + 1]);
                    }
                } else if (KIND == 1) {
#pragma unroll
                    for (int nt = 0; nt < 4; nt++) {
                        int col = wn * 32 + nt * 8 + (lane & 3) * 2;
                        float2 rv = __half22float2(
                            *reinterpret_cast<const __half2*>(Rh + (size_t)row * 128 + col));
                        float vx = fmaxf(acc[mt][nt][h * 2] + rv.x, 0.f);
                        float vy = fmaxf(acc[mt][nt][h * 2 + 1] + rv.y, 0.f);
                        *reinterpret_cast<__half2*>(HOa + (size_t)row * 128 + col) =
                            __floats2half2_rn(vx, vy);
                    }
                } else if (KIND == 2 && j < 2) {
#pragma unroll
                    for (int nt = 0; nt < 4; nt++) {
                        int col = wn * 32 + nt * 8 + (lane & 3) * 2;
                        *reinterpret_cast<__half2*>(HOa + (size_t)row * 256 + j * 128 + col) =
                            __floats2half2_rn(acc[mt][nt][h * 2], acc[mt][nt][h * 2 + 1]);
                    }
                } else {
                    // KIND 2, j==2: en = relu(A + A@B + P[src] + Q[dst]) fp16
                    int s = psrc[row], d = pdst[row];
#pragma unroll
                    for (int nt = 0; nt < 4; nt++) {
                        int col = wn * 32 + nt * 8 + (lane & 3) * 2;
                        float vx = acc[mt][nt][h * 2], vy = acc[mt][nt][h * 2 + 1];
                        float2 av = __half22float2(
                            *reinterpret_cast<const __half2*>(smem + OFF_A + rl * PS + col * 2));
                        float2 pv = __half22float2(
                            *reinterpret_cast<const __half2*>(PQh + (size_t)s * 256 + col));
                        float2 qv = __half22float2(
                            *reinterpret_cast<const __half2*>(PQh + (size_t)d * 256 + 128 + col));
                        vx = fmaxf(vx + av.x + pv.x + qv.x, 0.f);
                        vy = fmaxf(vy + av.y + pv.y + qv.y, 0.f);
                        *reinterpret_cast<__half2*>(HOb + (size_t)row * 128 + col) =
                            __floats2half2_rn(vx, vy);
                    }
                }
            }
        }
        __syncthreads();   // protect B buffer reuse
    }
}

// ---------------- CSR build + edge permutation ------------------------------
__global__ void k_count(const int* __restrict__ dst, int* __restrict__ cnt) {
    int e = blockIdx.x * blockDim.x + threadIdx.x;
    if (e < EE) atomicAdd(&cnt[dst[e]], 1);
}

__global__ void k_scan(const int* __restrict__ cnt, int* __restrict__ rowptr,
                       int* __restrict__ cursor) {
    __shared__ int part[1024];
    const int t = threadIdx.x;
    const int CH = (NN + 1023) / 1024;
    int s = 0;
    for (int i = 0; i < CH; i++) {
        int idx = t * CH + i;
        if (idx < NN) s += cnt[idx];
    }
    part[t] = s;
    __syncthreads();
    for (int off = 1; off < 1024; off <<= 1) {
        int v = 0;
        if (t >= off) v = part[t - off];
        __syncthreads();
        if (t >= off) part[t] += v;
        __syncthreads();
    }
    int base = (t > 0) ? part[t - 1] : 0;
    for (int i = 0; i < CH; i++) {
        int idx = t * CH + i;
        if (idx < NN) {
            rowptr[idx] = base;
            cursor[idx] = base;
            base += cnt[idx];
        }
    }
    if (t == 1023) rowptr[NN] = EE;
}

__global__ void k_scatter(const int* __restrict__ dst, int* __restrict__ cursor,
                          int* __restrict__ csr) {
    int e = blockIdx.x * blockDim.x + threadIdx.x;
    if (e >= EE) return;
    int pos = atomicAdd(&cursor[dst[e]], 1);
    csr[pos] = e;
}

__global__ void k_permute(const int* __restrict__ csr, const int* __restrict__ src,
                          const int* __restrict__ dst, const int* __restrict__ code,
                          int* __restrict__ psrc, int* __restrict__ pdst,
                          int* __restrict__ pcode) {
    int i = blockIdx.x * blockDim.x + threadIdx.x;
    if (i >= EE) return;
    int e = csr[i];
    psrc[i] = src[e];
    pdst[i] = dst[e];
    pcode[i] = code[e];
}

// ---------------- fused attention: warp per dst node, online softmax --------
__global__ void k_attn(const float* __restrict__ qf, const __half* __restrict__ kvh,
                       const __half* __restrict__ ekv, const int* __restrict__ psrc,
                       const int* __restrict__ rowptr, __half* __restrict__ aggh)
{
    int w = (blockIdx.x * blockDim.x + threadIdx.x) >> 5;
    int lane = threadIdx.x & 31;
    if (w >= NN) return;
    const int beg = rowptr[w], end = rowptr[w + 1];

    float4 q4 = *reinterpret_cast<const float4*>(qf + (size_t)w * 128 + lane * 4);
    float m = -3.4e38f, den = 0.f;
    float a0 = 0.f, a1 = 0.f, a2 = 0.f, a3 = 0.f;

    for (int i = beg; i < end; i++) {
        int s = psrc[i];
        const __half2* kp = reinterpret_cast<const __half2*>(kvh + (size_t)s * 256) + lane * 2;
        float2 k01 = __half22float2(kp[0]), k23 = __half22float2(kp[1]);
        float2 v01 = __half22float2(kp[64]), v23 = __half22float2(kp[65]);
        const __half2* ep = reinterpret_cast<const __half2*>(ekv + (size_t)i * 256) + lane * 2;
        float2 ek01 = __half22float2(ep[0]), ek23 = __half22float2(ep[1]);
        float2 ev01 = __half22float2(ep[64]), ev23 = __half22float2(ep[65]);

        float p = q4.x * (k01.x + ek01.x) + q4.y * (k01.y + ek01.y) +
                  q4.z * (k23.x + ek23.x) + q4.w * (k23.y + ek23.y);
        p += __shfl_xor_sync(0xffffffffu, p, 4);
        p += __shfl_xor_sync(0xffffffffu, p, 2);
        p += __shfl_xor_sync(0xffffffffu, p, 1);
        p *= 0.17677669529663687f;   // 1/sqrt(32)

        float nm = fmaxf(m, p);
        float f = __expf(m - nm);
        float ex = __expf(p - nm);
        den = den * f + ex;
        a0 = a0 * f + ex * (v01.x + ev01.x);
        a1 = a1 * f + ex * (v01.y + ev01.y);
        a2 = a2 * f + ex * (v23.x + ev23.x);
        a3 = a3 * f + ex * (v23.y + ev23.y);
        m = nm;
    }
    float inv = (den > 0.f) ? 1.f / den : 0.f;
    __half2 o01 = __floats2half2_rn(a0 * inv, a1 * inv);
    __half2 o23 = __floats2half2_rn(a2 * inv, a3 * inv);
    *reinterpret_cast<uint2*>(aggh + (size_t)w * 128 + lane * 4) =
        make_uint2(*(uint32_t*)&o01, *(uint32_t*)&o23);
}

// ---------------- misc elementwise kernels ----------------------------------
__global__ void k_node_embed(const int* __restrict__ x, const float* __restrict__ emb,
                             __half* __restrict__ feat) {
    unsigned t = blockIdx.x * blockDim.x + threadIdx.x;
    if (t >= (unsigned)NN * 32u) return;
    int n = t >> 5, q = t & 31;
    float4 v = *reinterpret_cast<const float4*>(emb + (size_t)x[n] * 128 + q * 4);
    __half2 h0 = __floats2half2_rn(v.x, v.y);
    __half2 h1 = __floats2half2_rn(v.z, v.w);
    *reinterpret_cast<uint2*>(feat + (size_t)n * 128 + q * 4) =
        make_uint2(*(uint32_t*)&h0, *(uint32_t*)&h1);
}

__global__ void k_lut_e(const float* __restrict__ femb, const float* __restrict__ pemb,
                        const float* __restrict__ bemb, float* __restrict__ elut) {
    int c = blockIdx.x, t = threadIdx.x;
    elut[c * 128 + t] = femb[(c >> 7) * 128 + t] + pemb[((c >> 1) & 63) * 128 + t] +
                        bemb[(c & 1) * 128 + t];
}

__global__ void k_code(const int* __restrict__ flow, const int* __restrict__ pos,
                       const int* __restrict__ blk, const int* __restrict__ src,
                       const int* __restrict__ dst, int* __restrict__ code) {
    int e = blockIdx.x * blockDim.x + threadIdx.x;
    if (e >= EE) return;
    int cr = (blk[src[e]] != blk[dst[e]]) ? 1 : 0;
    code[e] = (flow[e] << 7) | (pos[e] << 1) | cr;
}

__global__ void k_expand_e(const int* __restrict__ pcode, const float* __restrict__ elut,
                           __half* __restrict__ e) {
    unsigned t = blockIdx.x * blockDim.x + threadIdx.x;
    if (t >= (unsigned)EE * 32u) return;
    int ed = t >> 5, q = t & 31;
    float4 v = *reinterpret_cast<const float4*>(elut + (size_t)pcode[ed] * 128 + q * 4);
    __half2 h0 = __floats2half2_rn(v.x, v.y);
    __half2 h1 = __floats2half2_rn(v.z, v.w);
    *reinterpret_cast<uint2*>(e + (size_t)ed * 128 + q * 4) =
        make_uint2(*(uint32_t*)&h0, *(uint32_t*)&h1);
}

__global__ void k_gnode(const __half* __restrict__ feat, const int* __restrict__ ntype,
                        const int* __restrict__ batch, float* __restrict__ ga,
                        float* __restrict__ cn)
{
    unsigned t = blockIdx.x * blockDim.x + threadIdx.x;
    if (t >= (unsigned)NN * 32u) return;
    int n = t >> 5, q = t & 31;
    if (ntype[n] != 0) return;
    int b = batch[n];
    uint2 raw = *reinterpret_cast<const uint2*>(feat + (size_t)n * 128 + q * 4);
    __half2 p01 = *reinterpret_cast<__half2*>(&raw.x);
    __half2 p23 = *reinterpret_cast<__half2*>(&raw.y);
    float2 f01 = __half22float2(p01), f23 = __half22float2(p23);
    float* p = ga + (size_t)b * 256 + q * 4;
    atomicAdd(p + 0, f01.x); atomicAdd(p + 1, f01.y);
    atomicAdd(p + 2, f23.x); atomicAdd(p + 3, f23.y);
    if (q == 0) atomicAdd(&cn[b], 1.f);
}

__global__ void k_gedge(const __half* __restrict__ e, const int* __restrict__ psrc,
                        const int* __restrict__ batch, float* __restrict__ ga,
                        float* __restrict__ ce)
{
    unsigned t = blockIdx.x * blockDim.x + threadIdx.x;
    if (t >= (unsigned)EE * 32u) return;
    int ed = t >> 5, q = t & 31;
    int b = batch[psrc[ed]];
    uint2 raw = *reinterpret_cast<const uint2*>(e + (size_t)ed * 128 + q * 4);
    __half2 p01 = *reinterpret_cast<__half2*>(&raw.x);
    __half2 p23 = *reinterpret_cast<__half2*>(&raw.y);
    float2 f01 = __half22float2(p01), f23 = __half22float2(p23);
    float* p = ga + (size_t)b * 256 + 128 + q * 4;
    atomicAdd(p + 0, f01.x); atomicAdd(p + 1, f01.y);
    atomicAdd(p + 2, f23.x); atomicAdd(p + 3, f23.y);
    if (q == 0) atomicAdd(&ce[b], 1.f);
}

__global__ void k_head(const float* __restrict__ ga, const float* __restrict__ cn,
                       const float* __restrict__ ce,
                       const float* __restrict__ QW1, const float* __restrict__ Qb1,
                       const float* __restrict__ QW2, const float* __restrict__ Qb2,
                       float* __restrict__ out)
{
    int g = blockIdx.x;
    int t = threadIdx.x;  // 128
    __shared__ float s_in[256];
    __shared__ float s_h[128];
    __shared__ float s_l[128];
    __shared__ float s_max, s_lse;
    float nc = fmaxf(cn[g], 1.0f);
    float ec = fmaxf(ce[g], 1.0f);
    s_in[t]       = ga[(size_t)g * 256 + t] / nc;
    s_in[t + 128] = ga[(size_t)g * 256 + 128 + t] / ec;
    __syncthreads();
    float acc = Qb1[t];
    for (int k = 0; k < 256; k++) acc = fmaf(s_in[k], QW1[(size_t)k * 128 + t], acc);
    s_h[t] = fmaxf(acc, 0.f);
    __syncthreads();
    float lg = 0.f;
    if (t < AA) {
        lg = Qb2[t];
        for (int k = 0; k < 128; k++) lg = fmaf(s_h[k], QW2[(size_t)k * AA + t], lg);
        s_l[t] = lg;
    }
    __syncthreads();
    if (t == 0) {
        float mx = -3.4e38f;
        for (int i = 0; i < AA; i++) mx = fmaxf(mx, s_l[i]);
        float s = 0.f;
        for (int i = 0; i < AA; i++) s += expf(s_l[i] - mx);
        s_max = mx;
        s_lse = logf(s);
    }
    __syncthreads();
    if (t < AA) out[(size_t)g * AA + t] = lg - s_max - s_lse;
}

// ---------------- launch ------------------------------------------------------
extern "C" void kernel_launch(void* const* d_in, const int* in_sizes, int n_in,
                              void* d_out, int out_size)
{
    const int* x     = (const int*)d_in[0];
    const int* ntype = (const int*)d_in[1];
    const int* batch = (const int*)d_in[2];
    const int* ei    = (const int*)d_in[3];
    const int* flow  = (const int*)d_in[4];
    const int* pos   = (const int*)d_in[5];
    const int* blk   = (const int*)d_in[6];
    int base = (in_sizes[7] == 8192 * 128) ? 7 : 8;
    const float* emb  = (const float*)d_in[base + 0];
    const float* femb = (const float*)d_in[base + 1];
    const float* pemb = (const float*)d_in[base + 2];
    const float* bemb = (const float*)d_in[base + 3];
    const float* Wq   = (const float*)d_in[base + 4];
    const float* Wk   = (const float*)d_in[base + 5];
    const float* Wv   = (const float*)d_in[base + 6];
    const float* Wek  = (const float*)d_in[base + 7];
    const float* Wev  = (const float*)d_in[base + 8];
    const float* Wo   = (const float*)d_in[base + 9];
    const float* Weu  = (const float*)d_in[base + 10];
    const float* QW1  = (const float*)d_in[base + 11];
    const float* Qb1  = (const float*)d_in[base + 12];
    const float* QW2  = (const float*)d_in[base + 13];
    const float* Qb2  = (const float*)d_in[base + 14];
    const int* src = ei;
    const int* dst = ei + EE;
    float* out = (float*)d_out;

    float *qf, *ga, *cn, *ce, *elut;
    __half *feat0, *feat1, *e0, *e1, *kvh, *PQh, *ekv, *aggh, *pack;
    int *code, *cnt, *rowptr, *cursor, *csr, *psrc, *pdst, *pcode;
    cudaGetSymbolAddress((void**)&feat0, g_feat0);
    cudaGetSymbolAddress((void**)&feat1, g_feat1);
    cudaGetSymbolAddress((void**)&e0, g_e0);
    cudaGetSymbolAddress((void**)&e1, g_e1);
    cudaGetSymbolAddress((void**)&qf, g_qf);
    cudaGetSymbolAddress((void**)&kvh, g_kvh);
    cudaGetSymbolAddress((void**)&PQh, g_PQh);
    cudaGetSymbolAddress((void**)&ekv, g_ekv);
    cudaGetSymbolAddress((void**)&aggh, g_aggh);
    cudaGetSymbolAddress((void**)&ga, g_ga);
    cudaGetSymbolAddress((void**)&cn, g_cn);
    cudaGetSymbolAddress((void**)&ce, g_ce);
    cudaGetSymbolAddress((void**)&code, g_code);
    cudaGetSymbolAddress((void**)&elut, g_elut);
    cudaGetSymbolAddress((void**)&cnt, g_cnt);
    cudaGetSymbolAddress((void**)&rowptr, g_rowptr);
    cudaGetSymbolAddress((void**)&cursor, g_cursor);
    cudaGetSymbolAddress((void**)&csr, g_csr);
    cudaGetSymbolAddress((void**)&psrc, g_psrc);
    cudaGetSymbolAddress((void**)&pdst, g_pdst);
    cudaGetSymbolAddress((void**)&pcode, g_pcode);
    cudaGetSymbolAddress((void**)&pack, g_pack);

    const int SMT1 = 34816 + 69632;        // NB=1 (104448)
    const int SMT2 = 34816 + 2 * 69632;    // NB>=2 (174080)
    cudaFuncSetAttribute(mma_gemm<0>, cudaFuncAttributeMaxDynamicSharedMemorySize, SMT2);
    cudaFuncSetAttribute(mma_gemm<1>, cudaFuncAttributeMaxDynamicSharedMemorySize, SMT1);
    cudaFuncSetAttribute(mma_gemm<2>, cudaFuncAttributeMaxDynamicSharedMemorySize, SMT2);

    const int TPB = 256;
    const int gN32 = (NN * 32 + TPB - 1) / TPB;
    const int gE32 = (EE * 32 + TPB - 1) / TPB;
    const int gE   = (EE + TPB - 1) / TPB;
    const int GN = (NN + 127) / 128;
    const int GE = (EE + 127) / 128;

    // prologue: weights, embeddings, CSR build + permuted edge arrays
    k_packall<<<72, 256>>>(Wq, Wk, Wv, Wek, Wev, Wo, Weu, pack);
    k_node_embed<<<gN32, TPB>>>(x, emb, feat0);
    k_lut_e<<<1024, 128>>>(femb, pemb, bemb, elut);
    k_code<<<gE, TPB>>>(flow, pos, blk, src, dst, code);
    cudaMemsetAsync(cnt, 0, NN * sizeof(int));
    k_count<<<gE, TPB>>>(dst, cnt);
    k_scan<<<1, 1024>>>(cnt, rowptr, cursor);
    k_scatter<<<gE, TPB>>>(dst, cursor, csr);
    k_permute<<<gE, TPB>>>(csr, src, dst, code, psrc, pdst, pcode);
    k_expand_e<<<gE32, TPB>>>(pcode, elut, e0);   // e0 fp16, CSR order

    __half* fc = feat0; __half* fn = feat1;
    __half* ec = e0;    __half* en = e1;

    for (int l = 0; l < LL; l++) {
        const __half* pb = pack + (size_t)l * 9 * 32768;

        // node pass: q (fp32), k,v (half->kvh), P,Q (half->PQh) from fc
        {
            Outs o{}; o.C[0] = qf;
            mma_gemm<0><<<GN, 512, SMT2>>>(fc, pb, o, kvh, PQh, nullptr, nullptr,
                                           nullptr, nullptr, NN);
        }
        // edge pass: ek,ev (half, CSR order) + en (half), reading ec ONCE
        {
            Outs o{};
            mma_gemm<2><<<GE, 512, SMT2>>>(ec, pb + (size_t)5 * 32768, o, ekv, en,
                                           nullptr, PQh, psrc, pdst, EE);
        }

        // fused attention (sequential ekv, L2-resident kv gathers)
        k_attn<<<gN32, TPB>>>(qf, kvh, ekv, psrc, rowptr, aggh);

        // feat_new = relu(fc + aggh@Wo)   (Wo at mt=8)
        {
            Outs o{};
            mma_gemm<1><<<GN, 512, SMT1>>>(aggh, pb + (size_t)8 * 32768, o, fn, nullptr,
                                           fc, nullptr, nullptr, nullptr, NN);
        }

        __half* tf = fc; fc = fn; fn = tf;
        __half* te = ec; ec = en; en = te;
    }

    cudaMemsetAsync(ga, 0, (size_t)GG * 256 * sizeof(float));
    cudaMemsetAsync(cn, 0, GG * sizeof(float));
    cudaMemsetAsync(ce, 0, GG * sizeof(float));
    k_gnode<<<gN32, TPB>>>(fc, ntype, batch, ga, cn);
    k_gedge<<<gE32, TPB>>>(ec, psrc, batch, ga, ce);
    k_head<<<GG, 128>>>(ga, cn, ce, QW1, Qb1, QW2, Qb2, out);
}

// round 17
// speedup vs baseline: 3.7547x; 1.2151x over previous
#include <cuda_runtime.h>
#include <cuda_fp16.h>
#include <math.h>
#include <stdint.h>

#define NN 100000
#define EE 500000
#define DD 128
#define LL 8
#define GG 64
#define AA 100

// ---------------- scratch (static device arrays; no cudaMalloc) -------------
__device__ __half g_feat0[(size_t)NN * DD];    // node feats fp16
__device__ __half g_feat1[(size_t)NN * DD];
__device__ __half g_e0[(size_t)EE * DD];       // edge feats fp16, CSR order
__device__ __half g_e1[(size_t)EE * DD];
__device__ float  g_qf[(size_t)NN * DD];       // q fp32
__device__ __half g_kvh[(size_t)NN * 256];     // k|v fp16
__device__ __half g_PQh[(size_t)NN * 256];     // P|Q fp16
__device__ __half g_ekv[(size_t)EE * 2 * DD];  // ek|ev fp16, CSR order
__device__ __half g_aggh[(size_t)NN * DD];     // attention output fp16
__device__ float  g_ga[GG * 256];
__device__ float  g_cn[GG];
__device__ float  g_ce[GG];
__device__ int    g_code[EE];
__device__ float  g_elut[1024 * DD];
// CSR by dst (graph static across layers) + permuted edge arrays
__device__ int    g_cnt[NN];
__device__ int    g_rowptr[NN + 1];
__device__ int    g_cursor[NN];
__device__ int    g_csr[EE];
__device__ int    g_psrc[EE];
__device__ int    g_pdst[EE];
__device__ int    g_pcode[EE];
// packed weights: 8 layers x 9 mats x (16384 hi + 16384 lo) fp16, [k][n] row-major
// mat order: Wq,Wk,Wv,WeuS,WeuD,Wek,Wev,WeuE,Wo
__device__ __half g_pack[(size_t)LL * 9 * 32768];

// ---------------- PTX helpers (baseline features only) ----------------------
__device__ __forceinline__ uint32_t smem_u32(const void* p) {
    return (uint32_t)__cvta_generic_to_shared(p);
}
__device__ __forceinline__ void cp_async16(uint32_t smem, const void* gmem) {
    asm volatile("cp.async.cg.shared.global [%0], [%1], 16;\n" :: "r"(smem), "l"(gmem));
}
__device__ __forceinline__ void cp_commit() { asm volatile("cp.async.commit_group;\n"); }
__device__ __forceinline__ void cp_wait0() { asm volatile("cp.async.wait_group 0;\n"); }
__device__ __forceinline__ void cp_wait1() { asm volatile("cp.async.wait_group 1;\n"); }

__device__ __forceinline__ void ldmx4(uint32_t* r, uint32_t addr) {
    asm volatile("ldmatrix.sync.aligned.m8n8.x4.shared.b16 {%0,%1,%2,%3}, [%4];"
                 : "=r"(r[0]), "=r"(r[1]), "=r"(r[2]), "=r"(r[3]) : "r"(addr));
}
__device__ __forceinline__ void ldmx4t(uint32_t* r, uint32_t addr) {
    asm volatile("ldmatrix.sync.aligned.m8n8.x4.trans.shared.b16 {%0,%1,%2,%3}, [%4];"
                 : "=r"(r[0]), "=r"(r[1]), "=r"(r[2]), "=r"(r[3]) : "r"(addr));
}
__device__ __forceinline__ void mma_f16(float* c, const uint32_t* a, const uint32_t* b) {
    asm volatile("mma.sync.aligned.m16n8k16.row.col.f32.f16.f16.f32 "
                 "{%0,%1,%2,%3}, {%4,%5,%6,%7}, {%8,%9}, {%0,%1,%2,%3};"
                 : "+f"(c[0]), "+f"(c[1]), "+f"(c[2]), "+f"(c[3])
                 : "r"(a[0]), "r"(a[1]), "r"(a[2]), "r"(a[3]), "r"(b[0]), "r"(b[1]));
}

// ---------------- weight pack: split fp16 hi/lo, keep [k][n] layout ---------
__global__ void k_packall(const float* __restrict__ Wq, const float* __restrict__ Wk,
                          const float* __restrict__ Wv, const float* __restrict__ Wek,
                          const float* __restrict__ Wev, const float* __restrict__ Wo,
                          const float* __restrict__ Weu, __half* __restrict__ pack)
{
    int b = blockIdx.x;        // 72 = 8 layers * 9 mats
    int l = b / 9, mt = b % 9;
    const float* W;
    switch (mt) {
        case 0: W = Wq  + (size_t)l * 16384; break;
        case 1: W = Wk  + (size_t)l * 16384; break;
        case 2: W = Wv  + (size_t)l * 16384; break;
        case 3: W = Weu + (size_t)l * 49152; break;           // WeuS
        case 4: W = Weu + (size_t)l * 49152 + 16384; break;   // WeuD
        case 5: W = Wek + (size_t)l * 16384; break;
        case 6: W = Wev + (size_t)l * 16384; break;
        case 7: W = Weu + (size_t)l * 49152 + 32768; break;   // WeuE
        default: W = Wo + (size_t)l * 16384; break;           // Wo
    }
    __half* dst = pack + (size_t)b * 32768;
    for (int idx = threadIdx.x; idx < 16384; idx += blockDim.x) {
        float a = W[idx];
        __half h = __float2half_rn(a);
        __half lo = __float2half_rn(a - __half2float(h));
        dst[idx] = h;
        dst[16384 + idx] = lo;
    }
}

// ---------------- multi-matrix fp16 tensor-core GEMM ------------------------
// 512 threads, 16 warps, warp tile 32 rows x 32 cols; A fp16 (no split)
// B-term count per matrix: 2 (hi+lo) only for Wq and Wo; else 1 (fp16-hi).
// KIND 0: node pass, NB=5: j0 -> q fp32 (2-term); j1,2 -> HOa (kvh); j3,4 -> HOb (PQh)
// KIND 1: Wo pass, NB=1 (2-term): HOa = relu(Rh + A@B) fp16
// KIND 2: edge pass, NB=3 (1-term): j<2 -> HOa (ekv); j==2 ->
//         HOb = relu(A + A@B + P[psrc] + Q[pdst]) fp16 (A residual from smem)
struct Outs { float* C[1]; };

template<int KIND>
__device__ __forceinline__ int n_terms(int j) {
    if (KIND == 0) return (j == 0) ? 2 : 1;
    if (KIND == 1) return 2;
    return 1;
}

template<int KIND>
__global__ void __launch_bounds__(512, 1) mma_gemm(
    const __half* __restrict__ A, const __half* __restrict__ Bp, Outs outs,
    __half* __restrict__ HOa, __half* __restrict__ HOb,
    const __half* __restrict__ Rh, const __half* __restrict__ PQh,
    const int* __restrict__ psrc, const int* __restrict__ pdst, int M)
{
    constexpr int NB = (KIND == 0) ? 5 : (KIND == 2) ? 3 : 1;
    extern __shared__ char smem[];
    const uint32_t sb = smem_u32(smem);
    const int tid = threadIdx.x;
    const int lane = tid & 31, wid = tid >> 5;
    const int wm = wid & 3, wn = wid >> 2;     // 4x4 warp grid (32 rows x 32 cols)
    const int m0 = blockIdx.x * 128;
    const int PS = 272;                        // padded row stride (bytes)
    const uint32_t OFF_A = 0;                  // 128 rows x 272 = 34816
    const uint32_t OFF_B0 = 34816, BUFSZ = 69632;   // per-buf: Bh | Bl

    // group 1: prefetch B0 (hi always; lo only if 2-term)
    {
        int nch = n_terms<KIND>(0) * 2048;
        for (int idx = tid; idx < nch; idx += 512) {
            int hl = idx >> 11, rem = idx & 2047, r = rem >> 4, c = rem & 15;
            cp_async16(sb + OFF_B0 + hl * 34816 + r * PS + c * 16,
                       (const char*)Bp + hl * 32768 + r * 256 + c * 16);
        }
        cp_commit();
    }

    // group 2: A fp16 straight copy (row = 256 bytes = 16 chunks)
    for (int idx = tid; idx < 2048; idx += 512) {
        int r = idx >> 4, c = idx & 15;
        int rg = m0 + r; if (rg >= M) rg = M - 1;
        cp_async16(sb + OFF_A + r * PS + c * 16,
                   (const char*)A + (size_t)rg * 256 + c * 16);
    }
    cp_commit();

#pragma unroll
    for (int j = 0; j < NB; j++) {
        const int terms = n_terms<KIND>(j);
        if (j + 1 < NB) {
            const uint32_t dstb = sb + OFF_B0 + ((j + 1) & 1) * BUFSZ;
            const char* srcb = (const char*)Bp + (size_t)(j + 1) * 65536;
            int nch = n_terms<KIND>(j + 1) * 2048;
            for (int idx = tid; idx < nch; idx += 512) {
                int hl = idx >> 11, rem = idx & 2047, r = rem >> 4, c = rem & 15;
                cp_async16(dstb + hl * 34816 + r * PS + c * 16,
                           srcb + hl * 32768 + r * 256 + c * 16);
            }
            cp_commit();
            cp_wait1();
        } else {
            cp_wait0();
        }
        __syncthreads();

        float acc[2][4][4];
#pragma unroll
        for (int i = 0; i < 2; i++)
#pragma unroll
            for (int n = 0; n < 4; n++)
#pragma unroll
                for (int q = 0; q < 4; q++) acc[i][n][q] = 0.f;

        const uint32_t Bbuf = sb + OFF_B0 + (j & 1) * BUFSZ;
        const uint32_t aBase = sb + OFF_A + (wm * 32 + (lane & 15)) * PS + (lane >> 4) * 16;
        const int bg = lane >> 3, br = lane & 7;
#pragma unroll
        for (int term = 0; term < 2; term++) {
            if (term >= terms) break;
            const uint32_t Bb = Bbuf + (term == 1 ? 34816 : 0);
            const uint32_t bBase = Bb + ((bg & 1) * 8 + br) * PS + wn * 64 + (bg >> 1) * 16;
#pragma unroll
            for (int ks = 0; ks < 8; ks++) {
                uint32_t a0[4], a1[4], bf[4][2];
                ldmx4(a0, aBase + ks * 32);
                ldmx4(a1, aBase + 16 * PS + ks * 32);
#pragma unroll
                for (int p = 0; p < 2; p++) {
                    uint32_t t4[4];
                    ldmx4t(t4, bBase + ks * 16 * PS + p * 32);
                    bf[2 * p][0] = t4[0]; bf[2 * p][1] = t4[1];
                    bf[2 * p + 1][0] = t4[2]; bf[2 * p + 1][1] = t4[3];
                }
#pragma unroll
                for (int nt = 0; nt < 4; nt++) {
                    mma_f16(acc[0][nt], a0, bf[nt]);
                    mma_f16(acc[1][nt], a1, bf[nt]);
                }
            }
        }

        // ----- epilogue (warp tile 32x32) -----
#pragma unroll
        for (int mt = 0; mt < 2; mt++) {
#pragma unroll
            for (int h = 0; h < 2; h++) {
                int rl = wm * 32 + mt * 16 + (lane >> 2) + h * 8;
                int row = m0 + rl;
                if (row >= M) continue;
                if (KIND == 0 && j == 0) {
                    float* C = outs.C[0];
#pragma unroll
                    for (int nt = 0; nt < 4; nt++) {
                        int col = wn * 32 + nt * 8 + (lane & 3) * 2;
                        *reinterpret_cast<float2*>(C + (size_t)row * 128 + col) =
                            make_float2(acc[mt][nt][h * 2], acc[mt][nt][h * 2 + 1]);
                    }
                } else if (KIND == 0) {
                    __half* HP = (j <= 2) ? HOa : HOb;
                    int co = ((j - 1) & 1) * 128;
#pragma unroll
                    for (int nt = 0; nt < 4; nt++) {
                        int col = wn * 32 + nt * 8 + (lane & 3) * 2;
                        *reinterpret_cast<__half2*>(HP + (size_t)row * 256 + co + col) =
                            __floats2half2_rn(acc[mt][nt][h * 2], acc[mt][nt][h * 2 + 1]);
                    }
                } else if (KIND == 1) {
#pragma unroll
                    for (int nt = 0; nt < 4; nt++) {
                        int col = wn * 32 + nt * 8 + (lane & 3) * 2;
                        float2 rv = __half22float2(
                            *reinterpret_cast<const __half2*>(Rh + (size_t)row * 128 + col));
                        float vx = fmaxf(acc[mt][nt][h * 2] + rv.x, 0.f);
                        float vy = fmaxf(acc[mt][nt][h * 2 + 1] + rv.y, 0.f);
                        *reinterpret_cast<__half2*>(HOa + (size_t)row * 128 + col) =
                            __floats2half2_rn(vx, vy);
                    }
                } else if (KIND == 2 && j < 2) {
#pragma unroll
                    for (int nt = 0; nt < 4; nt++) {
                        int col = wn * 32 + nt * 8 + (lane & 3) * 2;
                        *reinterpret_cast<__half2*>(HOa + (size_t)row * 256 + j * 128 + col) =
                            __floats2half2_rn(acc[mt][nt][h * 2], acc[mt][nt][h * 2 + 1]);
                    }
                } else {
                    // KIND 2, j==2: en = relu(A + A@B + P[src] + Q[dst]) fp16
                    int s = psrc[row], d = pdst[row];
#pragma unroll
                    for (int nt = 0; nt < 4; nt++) {
                        int col = wn * 32 + nt * 8 + (lane & 3) * 2;
                        float vx = acc[mt][nt][h * 2], vy = acc[mt][nt][h * 2 + 1];
                        float2 av = __half22float2(
                            *reinterpret_cast<const __half2*>(smem + OFF_A + rl * PS + col * 2));
                        float2 pv = __half22float2(
                            *reinterpret_cast<const __half2*>(PQh + (size_t)s * 256 + col));
                        float2 qv = __half22float2(
                            *reinterpret_cast<const __half2*>(PQh + (size_t)d * 256 + 128 + col));
                        vx = fmaxf(vx + av.x + pv.x + qv.x, 0.f);
                        vy = fmaxf(vy + av.y + pv.y + qv.y, 0.f);
                        *reinterpret_cast<__half2*>(HOb + (size_t)row * 128 + col) =
                            __floats2half2_rn(vx, vy);
                    }
                }
            }
        }
        __syncthreads();   // protect B buffer reuse
    }
}

// ---------------- CSR build + edge permutation ------------------------------
__global__ void k_count(const int* __restrict__ dst, int* __restrict__ cnt) {
    int e = blockIdx.x * blockDim.x + threadIdx.x;
    if (e < EE) atomicAdd(&cnt[dst[e]], 1);
}

__global__ void k_scan(const int* __restrict__ cnt, int* __restrict__ rowptr,
                       int* __restrict__ cursor) {
    __shared__ int part[1024];
    const int t = threadIdx.x;
    const int CH = (NN + 1023) / 1024;
    int s = 0;
    for (int i = 0; i < CH; i++) {
        int idx = t * CH + i;
        if (idx < NN) s += cnt[idx];
    }
    part[t] = s;
    __syncthreads();
    for (int off = 1; off < 1024; off <<= 1) {
        int v = 0;
        if (t >= off) v = part[t - off];
        __syncthreads();
        if (t >= off) part[t] += v;
        __syncthreads();
    }
    int base = (t > 0) ? part[t - 1] : 0;
    for (int i = 0; i < CH; i++) {
        int idx = t * CH + i;
        if (idx < NN) {
            rowptr[idx] = base;
            cursor[idx] = base;
            base += cnt[idx];
        }
    }
    if (t == 1023) rowptr[NN] = EE;
}

__global__ void k_scatter(const int* __restrict__ dst, int* __restrict__ cursor,
                          int* __restrict__ csr) {
    int e = blockIdx.x * blockDim.x + threadIdx.x;
    if (e >= EE) return;
    int pos = atomicAdd(&cursor[dst[e]], 1);
    csr[pos] = e;
}

__global__ void k_permute(const int* __restrict__ csr, const int* __restrict__ src,
                          const int* __restrict__ dst, const int* __restrict__ code,
                          int* __restrict__ psrc, int* __restrict__ pdst,
                          int* __restrict__ pcode) {
    int i = blockIdx.x * blockDim.x + threadIdx.x;
    if (i >= EE) return;
    int e = csr[i];
    psrc[i] = src[e];
    pdst[i] = dst[e];
    pcode[i] = code[e];
}

// ---------------- fused attention: warp per dst node, online softmax --------
__global__ void k_attn(const float* __restrict__ qf, const __half* __restrict__ kvh,
                       const __half* __restrict__ ekv, const int* __restrict__ psrc,
                       const int* __restrict__ rowptr, __half* __restrict__ aggh)
{
    int w = (blockIdx.x * blockDim.x + threadIdx.x) >> 5;
    int lane = threadIdx.x & 31;
    if (w >= NN) return;
    const int beg = rowptr[w], end = rowptr[w + 1];

    float4 q4 = *reinterpret_cast<const float4*>(qf + (size_t)w * 128 + lane * 4);
    float m = -3.4e38f, den = 0.f;
    float a0 = 0.f, a1 = 0.f, a2 = 0.f, a3 = 0.f;

    for (int i = beg; i < end; i++) {
        int s = psrc[i];
        const __half2* kp = reinterpret_cast<const __half2*>(kvh + (size_t)s * 256) + lane * 2;
        float2 k01 = __half22float2(kp[0]), k23 = __half22float2(kp[1]);
        float2 v01 = __half22float2(kp[64]), v23 = __half22float2(kp[65]);
        const __half2* ep = reinterpret_cast<const __half2*>(ekv + (size_t)i * 256) + lane * 2;
        float2 ek01 = __half22float2(ep[0]), ek23 = __half22float2(ep[1]);
        float2 ev01 = __half22float2(ep[64]), ev23 = __half22float2(ep[65]);

        float p = q4.x * (k01.x + ek01.x) + q4.y * (k01.y + ek01.y) +
                  q4.z * (k23.x + ek23.x) + q4.w * (k23.y + ek23.y);
        p += __shfl_xor_sync(0xffffffffu, p, 4);
        p += __shfl_xor_sync(0xffffffffu, p, 2);
        p += __shfl_xor_sync(0xffffffffu, p, 1);
        p *= 0.17677669529663687f;   // 1/sqrt(32)

        float nm = fmaxf(m, p);
        float f = __expf(m - nm);
        float ex = __expf(p - nm);
        den = den * f + ex;
        a0 = a0 * f + ex * (v01.x + ev01.x);
        a1 = a1 * f + ex * (v01.y + ev01.y);
        a2 = a2 * f + ex * (v23.x + ev23.x);
        a3 = a3 * f + ex * (v23.y + ev23.y);
        m = nm;
    }
    float inv = (den > 0.f) ? 1.f / den : 0.f;
    __half2 o01 = __floats2half2_rn(a0 * inv, a1 * inv);
    __half2 o23 = __floats2half2_rn(a2 * inv, a3 * inv);
    *reinterpret_cast<uint2*>(aggh + (size_t)w * 128 + lane * 4) =
        make_uint2(*(uint32_t*)&o01, *(uint32_t*)&o23);
}

// ---------------- misc elementwise kernels ----------------------------------
__global__ void k_node_embed(const int* __restrict__ x, const float* __restrict__ emb,
                             __half* __restrict__ feat) {
    unsigned t = blockIdx.x * blockDim.x + threadIdx.x;
    if (t >= (unsigned)NN * 32u) return;
    int n = t >> 5, q = t & 31;
    float4 v = *reinterpret_cast<const float4*>(emb + (size_t)x[n] * 128 + q * 4);
    __half2 h0 = __floats2half2_rn(v.x, v.y);
    __half2 h1 = __floats2half2_rn(v.z, v.w);
    *reinterpret_cast<uint2*>(feat + (size_t)n * 128 + q * 4) =
        make_uint2(*(uint32_t*)&h0, *(uint32_t*)&h1);
}

__global__ void k_lut_e(const float* __restrict__ femb, const float* __restrict__ pemb,
                        const float* __restrict__ bemb, float* __restrict__ elut) {
    int c = blockIdx.x, t = threadIdx.x;
    elut[c * 128 + t] = femb[(c >> 7) * 128 + t] + pemb[((c >> 1) & 63) * 128 + t] +
                        bemb[(c & 1) * 128 + t];
}

__global__ void k_code(const int* __restrict__ flow, const int* __restrict__ pos,
                       const int* __restrict__ blk, const int* __restrict__ src,
                       const int* __restrict__ dst, int* __restrict__ code) {
    int e = blockIdx.x * blockDim.x + threadIdx.x;
    if (e >= EE) return;
    int cr = (blk[src[e]] != blk[dst[e]]) ? 1 : 0;
    code[e] = (flow[e] << 7) | (pos[e] << 1) | cr;
}

__global__ void k_expand_e(const int* __restrict__ pcode, const float* __restrict__ elut,
                           __half* __restrict__ e) {
    unsigned t = blockIdx.x * blockDim.x + threadIdx.x;
    if (t >= (unsigned)EE * 32u) return;
    int ed = t >> 5, q = t & 31;
    float4 v = *reinterpret_cast<const float4*>(elut + (size_t)pcode[ed] * 128 + q * 4);
    __half2 h0 = __floats2half2_rn(v.x, v.y);
    __half2 h1 = __floats2half2_rn(v.z, v.w);
    *reinterpret_cast<uint2*>(e + (size_t)ed * 128 + q * 4) =
        make_uint2(*(uint32_t*)&h0, *(uint32_t*)&h1);
}

__global__ void k_gnode(const __half* __restrict__ feat, const int* __restrict__ ntype,
                        const int* __restrict__ batch, float* __restrict__ ga,
                        float* __restrict__ cn)
{
    unsigned t = blockIdx.x * blockDim.x + threadIdx.x;
    if (t >= (unsigned)NN * 32u) return;
    int n = t >> 5, q = t & 31;
    if (ntype[n] != 0) return;
    int b = batch[n];
    uint2 raw = *reinterpret_cast<const uint2*>(feat + (size_t)n * 128 + q * 4);
    __half2 p01 = *reinterpret_cast<__half2*>(&raw.x);
    __half2 p23 = *reinterpret_cast<__half2*>(&raw.y);
    float2 f01 = __half22float2(p01), f23 = __half22float2(p23);
    float* p = ga + (size_t)b * 256 + q * 4;
    atomicAdd(p + 0, f01.x); atomicAdd(p + 1, f01.y);
    atomicAdd(p + 2, f23.x); atomicAdd(p + 3, f23.y);
    if (q == 0) atomicAdd(&cn[b], 1.f);
}

__global__ void k_gedge(const __half* __restrict__ e, const int* __restrict__ psrc,
                        const int* __restrict__ batch, float* __restrict__ ga,
                        float* __restrict__ ce)
{
    unsigned t = blockIdx.x * blockDim.x + threadIdx.x;
    if (t >= (unsigned)EE * 32u) return;
    int ed = t >> 5, q = t & 31;
    int b = batch[psrc[ed]];
    uint2 raw = *reinterpret_cast<const uint2*>(e + (size_t)ed * 128 + q * 4);
    __half2 p01 = *reinterpret_cast<__half2*>(&raw.x);
    __half2 p23 = *reinterpret_cast<__half2*>(&raw.y);
    float2 f01 = __half22float2(p01), f23 = __half22float2(p23);
    float* p = ga + (size_t)b * 256 + 128 + q * 4;
    atomicAdd(p + 0, f01.x); atomicAdd(p + 1, f01.y);
    atomicAdd(p + 2, f23.x); atomicAdd(p + 3, f23.y);
    if (q == 0) atomicAdd(&ce[b], 1.f);
}

__global__ void k_head(const float* __restrict__ ga, const float* __restrict__ cn,
                       const float* __restrict__ ce,
                       const float* __restrict__ QW1, const float* __restrict__ Qb1,
                       const float* __restrict__ QW2, const float* __restrict__ Qb2,
                       float* __restrict__ out)
{
    int g = blockIdx.x;
    int t = threadIdx.x;  // 128
    __shared__ float s_in[256];
    __shared__ float s_h[128];
    __shared__ float s_l[128];
    __shared__ float s_max, s_lse;
    float nc = fmaxf(cn[g], 1.0f);
    float ec = fmaxf(ce[g], 1.0f);
    s_in[t]       = ga[(size_t)g * 256 + t] / nc;
    s_in[t + 128] = ga[(size_t)g * 256 + 128 + t] / ec;
    __syncthreads();
    float acc = Qb1[t];
    for (int k = 0; k < 256; k++) acc = fmaf(s_in[k], QW1[(size_t)k * 128 + t], acc);
    s_h[t] = fmaxf(acc, 0.f);
    __syncthreads();
    float lg = 0.f;
    if (t < AA) {
        lg = Qb2[t];
        for (int k = 0; k < 128; k++) lg = fmaf(s_h[k], QW2[(size_t)k * AA + t], lg);
        s_l[t] = lg;
    }
    __syncthreads();
    if (t == 0) {
        float mx = -3.4e38f;
        for (int i = 0; i < AA; i++) mx = fmaxf(mx, s_l[i]);
        float s = 0.f;
        for (int i = 0; i < AA; i++) s += expf(s_l[i] - mx);
        s_max = mx;
        s_lse = logf(s);
    }
    __syncthreads();
    if (t < AA) out[(size_t)g * AA + t] = lg - s_max - s_lse;
}

// ---------------- launch ------------------------------------------------------
extern "C" void kernel_launch(void* const* d_in, const int* in_sizes, int n_in,
                              void* d_out, int out_size)
{
    const int* x     = (const int*)d_in[0];
    const int* ntype = (const int*)d_in[1];
    const int* batch = (const int*)d_in[2];
    const int* ei    = (const int*)d_in[3];
    const int* flow  = (const int*)d_in[4];
    const int* pos   = (const int*)d_in[5];
    const int* blk   = (const int*)d_in[6];
    int base = (in_sizes[7] == 8192 * 128) ? 7 : 8;
    const float* emb  = (const float*)d_in[base + 0];
    const float* femb = (const float*)d_in[base + 1];
    const float* pemb = (const float*)d_in[base + 2];
    const float* bemb = (const float*)d_in[base + 3];
    const float* Wq   = (const float*)d_in[base + 4];
    const float* Wk   = (const float*)d_in[base + 5];
    const float* Wv   = (const float*)d_in[base + 6];
    const float* Wek  = (const float*)d_in[base + 7];
    const float* Wev  = (const float*)d_in[base + 8];
    const float* Wo   = (const float*)d_in[base + 9];
    const float* Weu  = (const float*)d_in[base + 10];
    const float* QW1  = (const float*)d_in[base + 11];
    const float* Qb1  = (const float*)d_in[base + 12];
    const float* QW2  = (const float*)d_in[base + 13];
    const float* Qb2  = (const float*)d_in[base + 14];
    const int* src = ei;
    const int* dst = ei + EE;
    float* out = (float*)d_out;

    float *qf, *ga, *cn, *ce, *elut;
    __half *feat0, *feat1, *e0, *e1, *kvh, *PQh, *ekv, *aggh, *pack;
    int *code, *cnt, *rowptr, *cursor, *csr, *psrc, *pdst, *pcode;
    cudaGetSymbolAddress((void**)&feat0, g_feat0);
    cudaGetSymbolAddress((void**)&feat1, g_feat1);
    cudaGetSymbolAddress((void**)&e0, g_e0);
    cudaGetSymbolAddress((void**)&e1, g_e1);
    cudaGetSymbolAddress((void**)&qf, g_qf);
    cudaGetSymbolAddress((void**)&kvh, g_kvh);
    cudaGetSymbolAddress((void**)&PQh, g_PQh);
    cudaGetSymbolAddress((void**)&ekv, g_ekv);
    cudaGetSymbolAddress((void**)&aggh, g_aggh);
    cudaGetSymbolAddress((void**)&ga, g_ga);
    cudaGetSymbolAddress((void**)&cn, g_cn);
    cudaGetSymbolAddress((void**)&ce, g_ce);
    cudaGetSymbolAddress((void**)&code, g_code);
    cudaGetSymbolAddress((void**)&elut, g_elut);
    cudaGetSymbolAddress((void**)&cnt, g_cnt);
    cudaGetSymbolAddress((void**)&rowptr, g_rowptr);
    cudaGetSymbolAddress((void**)&cursor, g_cursor);
    cudaGetSymbolAddress((void**)&csr, g_csr);
    cudaGetSymbolAddress((void**)&psrc, g_psrc);
    cudaGetSymbolAddress((void**)&pdst, g_pdst);
    cudaGetSymbolAddress((void**)&pcode, g_pcode);
    cudaGetSymbolAddress((void**)&pack, g_pack);

    const int SMT1 = 34816 + 69632;        // NB=1 (104448)
    const int SMT2 = 34816 + 2 * 69632;    // NB>=2 (174080)
    cudaFuncSetAttribute(mma_gemm<0>, cudaFuncAttributeMaxDynamicSharedMemorySize, SMT2);
    cudaFuncSetAttribute(mma_gemm<1>, cudaFuncAttributeMaxDynamicSharedMemorySize, SMT1);
    cudaFuncSetAttribute(mma_gemm<2>, cudaFuncAttributeMaxDynamicSharedMemorySize, SMT2);

    const int TPB = 256;
    const int gN32 = (NN * 32 + TPB - 1) / TPB;
    const int gE32 = (EE * 32 + TPB - 1) / TPB;
    const int gE   = (EE + TPB - 1) / TPB;
    const int GN = (NN + 127) / 128;
    const int GE = (EE + 127) / 128;

    // prologue: weights, embeddings, CSR build + permuted edge arrays
    k_packall<<<72, 256>>>(Wq, Wk, Wv, Wek, Wev, Wo, Weu, pack);
    k_node_embed<<<gN32, TPB>>>(x, emb, feat0);
    k_lut_e<<<1024, 128>>>(femb, pemb, bemb, elut);
    k_code<<<gE, TPB>>>(flow, pos, blk, src, dst, code);
    cudaMemsetAsync(cnt, 0, NN * sizeof(int));
    k_count<<<gE, TPB>>>(dst, cnt);
    k_scan<<<1, 1024>>>(cnt, rowptr, cursor);
    k_scatter<<<gE, TPB>>>(dst, cursor, csr);
    k_permute<<<gE, TPB>>>(csr, src, dst, code, psrc, pdst, pcode);
    k_expand_e<<<gE32, TPB>>>(pcode, elut, e0);   // e0 fp16, CSR order

    __half* fc = feat0; __half* fn = feat1;
    __half* ec = e0;    __half* en = e1;

    for (int l = 0; l < LL; l++) {
        const __half* pb = pack + (size_t)l * 9 * 32768;

        // node pass: q (fp32, 2-term), k,v (->kvh), P,Q (->PQh) from fc
        {
            Outs o{}; o.C[0] = qf;
            mma_gemm<0><<<GN, 512, SMT2>>>(fc, pb, o, kvh, PQh, nullptr, nullptr,
                                           nullptr, nullptr, NN);
        }
        // edge pass (1-term): ek,ev (->ekv, CSR order) + en, reading ec ONCE
        {
            Outs o{};
            mma_gemm<2><<<GE, 512, SMT2>>>(ec, pb + (size_t)5 * 32768, o, ekv, en,
                                           nullptr, PQh, psrc, pdst, EE);
        }

        // fused attention (sequential ekv, L2-resident kv gathers)
        k_attn<<<gN32, TPB>>>(qf, kvh, ekv, psrc, rowptr, aggh);

        // feat_new = relu(fc + aggh@Wo)   (Wo at mt=8, 2-term)
        {
            Outs o{};
            mma_gemm<1><<<GN, 512, SMT1>>>(aggh, pb + (size_t)8 * 32768, o, fn, nullptr,
                                           fc, nullptr, nullptr, nullptr, NN);
        }

        __half* tf = fc; fc = fn; fn = tf;
        __half* te = ec; ec = en; en = te;
    }

    cudaMemsetAsync(ga, 0, (size_t)GG * 256 * sizeof(float));
    cudaMemsetAsync(cn, 0, GG * sizeof(float));
    cudaMemsetAsync(ce, 0, GG * sizeof(float));
    k_gnode<<<gN32, TPB>>>(fc, ntype, batch, ga, cn);
    k_gedge<<<gE32, TPB>>>(ec, psrc, batch, ga, ce);
    k_head<<<GG, 128>>>(ga, cn, ce, QW1, Qb1, QW2, Qb2, out);
}